// round 2
// baseline (speedup 1.0000x reference)
#include <cuda_runtime.h>
#include <math.h>

// ---------------- problem constants ----------------
constexpr int BB = 4;
constexpr int SS = 4096;
constexpr int DD = 768;
constexpr int PP = 683;
constexpr int NBYTE = 260;
constexpr int HASHMASK = 65535;     // HASH_VOCAB = 65536 (power of two)
constexpr int BS  = BB * SS;        // 16384 rows
constexpr int BSD = BS * DD;        // 12,582,912
constexpr int BPD = BB * PP * DD;   // 2,098,176
constexpr int CC  = 32;             // scan chunks
constexpr int LL  = SS / CC;        // 128
constexpr int CBD = CC * BB * DD;   // 98,304

// ---------------- static scratch (no runtime allocation allowed) ----------------
// layout: x | xn | hg(2*BSD) | h | y | patch | carry(2*CBD) | hinit(CBD) | cum | pid
constexpr size_t SCRATCH_FLOATS =
    (size_t)6 * BSD + BPD + (size_t)3 * CBD + (size_t)BB * PP + (size_t)BS;
__device__ float g_scratch[SCRATCH_FLOATS];

// ---------------- embedding: tok_emb[id] + hash_emb[rolling 4-gram hash] ----------------
__global__ void k_embed(const int* __restrict__ ids, const float* __restrict__ tok,
                        const float* __restrict__ hsh, float* __restrict__ out) {
    int bs = blockIdx.x;            // b*S + s
    int s  = bs & (SS - 1);
    int t0 = ids[bs];
    int acc = t0, p = 31;
#pragma unroll
    for (int j = 1; j < 4; j++) {
        if (s >= j) acc += ids[bs - j] * p;
        p *= 31;
    }
    int hid = acc & HASHMASK;
    const float* tr = tok + (size_t)t0 * DD;
    const float* hr = hsh + (size_t)hid * DD;
    float* orow = out + (size_t)bs * DD;
    for (int d = threadIdx.x; d < DD; d += blockDim.x)
        orow[d] = tr[d] + hr[d];
}

// ---------------- RMSNorm: out = x * rsqrt(mean(x^2)+eps) * w ----------------
__global__ void k_rmsnorm(const float* __restrict__ x, const float* __restrict__ w,
                          float* __restrict__ out) {
    int row = blockIdx.x;
    const float* xr = x + (size_t)row * DD;
    float ss = 0.f;
    for (int d = threadIdx.x; d < DD; d += 256) {
        float v = xr[d];
        ss += v * v;
    }
    __shared__ float red[8];
#pragma unroll
    for (int o = 16; o > 0; o >>= 1) ss += __shfl_xor_sync(~0u, ss, o);
    if ((threadIdx.x & 31) == 0) red[threadIdx.x >> 5] = ss;
    __syncthreads();
    if (threadIdx.x == 0) {
        float v = 0.f;
#pragma unroll
        for (int i = 0; i < 8; i++) v += red[i];
        red[0] = rsqrtf(v / DD + 1e-6f);
    }
    __syncthreads();
    float r = red[0];
    float* orow = out + (size_t)row * DD;
    for (int d = threadIdx.x; d < 256 * ((DD + 255) / 256); d += 256)
        if (d < DD) orow[d] = xr[d] * r * w[d];
}

// ---------------- SGEMM: C[M,N] = A[M,K] @ Bw[K,N] (+ Res[M,N]) ----------------
// classic 128x128x8 tile, 256 threads, 8x8 per thread. M%128==0, K%8==0; N guarded.
template <bool RES>
__global__ void __launch_bounds__(256, 2)
k_sgemm(const float* __restrict__ A, const float* __restrict__ Bw,
        const float* __restrict__ Res, float* __restrict__ C,
        int M, int N, int K) {
    constexpr int BM = 128, BN = 128, BK = 8;
    __shared__ float As[BK][BM];
    __shared__ float Bs[BK][BN];
    int tid = threadIdx.x;
    int m0 = blockIdx.y * BM, n0 = blockIdx.x * BN;
    int aRow = tid >> 1, aCol = (tid & 1) * 4;
    int bRow = tid >> 5, bCol = (tid & 31) * 4;
    int tx = tid & 15, ty = tid >> 4;

    float acc[8][8];
#pragma unroll
    for (int i = 0; i < 8; i++)
#pragma unroll
        for (int j = 0; j < 8; j++) acc[i][j] = 0.f;

    for (int k0 = 0; k0 < K; k0 += BK) {
        float4 va = *(const float4*)(A + (size_t)(m0 + aRow) * K + k0 + aCol);
        As[aCol + 0][aRow] = va.x;
        As[aCol + 1][aRow] = va.y;
        As[aCol + 2][aRow] = va.z;
        As[aCol + 3][aRow] = va.w;

        int gcol = n0 + bCol;
        const float* bp = Bw + (size_t)(k0 + bRow) * N + gcol;
        float4 vb;
        if (gcol + 3 < N) {
            vb = *(const float4*)bp;
        } else {
            vb.x = (gcol + 0 < N) ? bp[0] : 0.f;
            vb.y = (gcol + 1 < N) ? bp[1] : 0.f;
            vb.z = (gcol + 2 < N) ? bp[2] : 0.f;
            vb.w = 0.f;
        }
        *(float4*)&Bs[bRow][bCol] = vb;
        __syncthreads();

#pragma unroll
        for (int k = 0; k < BK; k++) {
            float4 a0 = *(const float4*)&As[k][ty * 8];
            float4 a1 = *(const float4*)&As[k][ty * 8 + 4];
            float4 b0 = *(const float4*)&Bs[k][tx * 8];
            float4 b1 = *(const float4*)&Bs[k][tx * 8 + 4];
            float ar[8] = {a0.x, a0.y, a0.z, a0.w, a1.x, a1.y, a1.z, a1.w};
            float br[8] = {b0.x, b0.y, b0.z, b0.w, b1.x, b1.y, b1.z, b1.w};
#pragma unroll
            for (int i = 0; i < 8; i++)
#pragma unroll
                for (int j = 0; j < 8; j++) acc[i][j] = fmaf(ar[i], br[j], acc[i][j]);
        }
        __syncthreads();
    }

#pragma unroll
    for (int i = 0; i < 8; i++) {
        int row = m0 + ty * 8 + i;
#pragma unroll
        for (int j = 0; j < 8; j++) {
            int col = n0 + tx * 8 + j;
            if (col < N) {
                float v = acc[i][j];
                if (RES) v += Res[(size_t)row * N + col];
                C[(size_t)row * N + col] = v;
            }
        }
    }
}

// ---------------- minGRU scan (linear space) ----------------
// h_t = a_t * h_{t-1} + b_t,  a = sigmoid(-gate), b = sigmoid(gate) * g(hidden)
__device__ __forceinline__ void mingru_coef(float hidden, float gate, float& a, float& bv) {
    float e   = __expf(-fabsf(gate));      // in (0,1], never inf
    float inv = 1.f / (1.f + e);
    float sneg = e * inv;                   // sigmoid(-|gate|)
    float spos = inv;                       // sigmoid(+|gate|)
    float z = (gate >= 0.f) ? spos : sneg;  // sigmoid(gate)
    a       = (gate >= 0.f) ? sneg : spos;  // sigmoid(-gate)
    float g;
    if (hidden >= 0.f) g = hidden + 0.5f;
    else {
        float eh = __expf(hidden);
        g = eh / (1.f + eh);
    }
    bv = z * g;
}

// pass 1: per-chunk affine reduction (A, B): h_end = A*h_start + B
__global__ void k_scan_red(const float* __restrict__ hg, float2* __restrict__ carry) {
    int idx = blockIdx.x * 256 + threadIdx.x;  // CC*BB*DD threads
    int d = idx % DD;
    int bc = idx / DD;
    int b = bc % BB;
    int c = bc / BB;
    const float* base = hg + (size_t)(b * SS + c * LL) * (2 * DD) + d;
    float A = 1.f, Bv = 0.f;
#pragma unroll 4
    for (int t = 0; t < LL; t++) {
        float hid = __ldg(base), gt = __ldg(base + DD);
        base += 2 * DD;
        float a, bv;
        mingru_coef(hid, gt, a, bv);
        A *= a;
        Bv = fmaf(a, Bv, bv);
    }
    carry[idx] = make_float2(A, Bv);
}

// pass 2: sequential scan over the 32 chunk carries per channel
__global__ void k_scan_carry(const float2* __restrict__ carry, float* __restrict__ hinit) {
    int ch = blockIdx.x * 256 + threadIdx.x;  // BB*DD threads
    int d = ch % DD;
    int b = ch / DD;
    float h = 0.f;
#pragma unroll
    for (int c = 0; c < CC; c++) {
        int i = (c * BB + b) * DD + d;
        hinit[i] = h;
        float2 ab = carry[i];
        h = fmaf(ab.x, h, ab.y);
    }
}

// pass 3: re-scan each chunk from its prefix, write h
__global__ void k_scan_apply(const float* __restrict__ hg, const float* __restrict__ hinit,
                             float* __restrict__ hout) {
    int idx = blockIdx.x * 256 + threadIdx.x;
    int d = idx % DD;
    int bc = idx / DD;
    int b = bc % BB;
    int c = bc / BB;
    const float* base = hg + (size_t)(b * SS + c * LL) * (2 * DD) + d;
    float* out = hout + (size_t)(b * SS + c * LL) * DD + d;
    float h = hinit[idx];
#pragma unroll 4
    for (int t = 0; t < LL; t++) {
        float hid = __ldg(base), gt = __ldg(base + DD);
        base += 2 * DD;
        float a, bv;
        mingru_coef(hid, gt, a, bv);
        h = fmaf(a, h, bv);
        out[0] = h;
        out += DD;
    }
}

// ---------------- patch bookkeeping ----------------
__global__ void k_cum(const int* __restrict__ lens, int* __restrict__ cum) {
    int b = blockIdx.x;
    if (threadIdx.x == 0) {
        int s = 0;
        for (int p = 0; p < PP; p++) {
            s += lens[b * PP + p];
            cum[b * PP + p] = s;
        }
    }
}

__global__ void k_pid(const int* __restrict__ cum, int* __restrict__ pid) {
    int i = blockIdx.x * 256 + threadIdx.x;
    if (i >= BS) return;
    int b = i / SS;
    int pos = i % SS;
    const int* c = cum + b * PP;
    int lo = 0, hi = PP;
    while (lo < hi) {
        int mid = (lo + hi) >> 1;
        if (c[mid] <= pos) lo = mid + 1;
        else hi = mid;
    }
    pid[i] = lo;
}

// segment max over contiguous patch ranges
__global__ void k_segmax(const float* __restrict__ y, const int* __restrict__ cum,
                         float* __restrict__ patch) {
    int bp = blockIdx.x;
    int b = bp / PP, p = bp % PP;
    int start = p ? cum[b * PP + p - 1] : 0;
    int end = cum[b * PP + p];
    const float* yb = y + (size_t)b * SS * DD;
    float* orow = patch + (size_t)bp * DD;
    for (int d = threadIdx.x; d < DD; d += 256) {
        float m = -3.402823466e38f;
        for (int s = start; s < end; s++)
            m = fmaxf(m, yb[(size_t)s * DD + d]);
        orow[d] = m;
    }
}

// y2 = y + patch[patch_id]
__global__ void k_gadd(const float* __restrict__ y, const float* __restrict__ patch,
                       const int* __restrict__ pid, float* __restrict__ out) {
    int i = blockIdx.x * 256 + threadIdx.x;  // BSD threads exactly
    int d = i % DD;
    int bs = i / DD;
    int b = bs / SS;
    int p = pid[bs];
    out[i] = y[i] + patch[(size_t)(b * PP + p) * DD + d];
}

// ---------------- launch ----------------
extern "C" void kernel_launch(void* const* d_in, const int* in_sizes, int n_in,
                              void* d_out, int out_size) {
    const int*   ids      = (const int*)d_in[0];
    const int*   lens     = (const int*)d_in[1];
    const float* tok      = (const float*)d_in[2];
    const float* hsh      = (const float*)d_in[3];
    const float* enc_nw   = (const float*)d_in[4];
    const float* enc_whg  = (const float*)d_in[5];
    const float* enc_wout = (const float*)d_in[6];
    const float* dec_nw   = (const float*)d_in[7];
    const float* dec_whg  = (const float*)d_in[8];
    const float* dec_wout = (const float*)d_in[9];
    const float* fin_nw   = (const float*)d_in[10];
    const float* oproj    = (const float*)d_in[11];
    float*       out      = (float*)d_out;

    float* base = nullptr;
    cudaGetSymbolAddress((void**)&base, g_scratch);
    float*  x     = base;
    float*  xn    = x + (size_t)BSD;
    float*  hg    = xn + (size_t)BSD;
    float*  h     = hg + (size_t)2 * BSD;
    float*  y     = h + (size_t)BSD;
    float*  patch = y + (size_t)BSD;
    float2* carry = (float2*)(patch + (size_t)BPD);
    float*  hinit = patch + (size_t)BPD + (size_t)2 * CBD;
    int*    cum   = (int*)(hinit + (size_t)CBD);
    int*    pid   = cum + BB * PP;

    dim3 g_hg((2 * DD) / 128, BS / 128);   // 12 x 128
    dim3 g_sq(DD / 128, BS / 128);         // 6 x 128
    dim3 g_lg((NBYTE + 127) / 128, BS / 128);

    // patch bookkeeping (independent of the rest until segmax)
    k_cum<<<BB, 32>>>(lens, cum);
    k_pid<<<(BS + 255) / 256, 256>>>(cum, pid);

    // embeddings
    k_embed<<<BS, 256>>>(ids, tok, hsh, x);

    // ---- encoder minGRU block ----
    k_rmsnorm<<<BS, 256>>>(x, enc_nw, xn);
    k_sgemm<false><<<g_hg, 256>>>(xn, enc_whg, nullptr, hg, BS, 2 * DD, DD);
    k_scan_red<<<CBD / 256, 256>>>(hg, carry);
    k_scan_carry<<<(BB * DD) / 256, 256>>>(carry, hinit);
    k_scan_apply<<<CBD / 256, 256>>>(hg, hinit, h);
    k_sgemm<true><<<g_sq, 256>>>(h, enc_wout, x, y, BS, DD, DD);

    // ---- patch pooling + decoder input ----
    k_segmax<<<BB * PP, 256>>>(y, cum, patch);
    k_gadd<<<BSD / 256, 256>>>(y, patch, pid, x);

    // ---- decoder minGRU block ----
    k_rmsnorm<<<BS, 256>>>(x, dec_nw, xn);
    k_sgemm<false><<<g_hg, 256>>>(xn, dec_whg, nullptr, hg, BS, 2 * DD, DD);
    k_scan_red<<<CBD / 256, 256>>>(hg, carry);
    k_scan_carry<<<(BB * DD) / 256, 256>>>(carry, hinit);
    k_scan_apply<<<CBD / 256, 256>>>(hg, hinit, h);
    k_sgemm<true><<<g_sq, 256>>>(h, dec_wout, x, y, BS, DD, DD);

    // ---- final norm + logits ----
    k_rmsnorm<<<BS, 256>>>(y, fin_nw, xn);
    k_sgemm<false><<<g_lg, 256>>>(xn, oproj, nullptr, out, BS, NBYTE, DD);
}

// round 4
// speedup vs baseline: 2.2194x; 2.2194x over previous
#include <cuda_runtime.h>
#include <cuda_bf16.h>
#include <math.h>
#include <stdint.h>

// ---------------- problem constants ----------------
constexpr int BB = 4;
constexpr int SS = 4096;
constexpr int DD = 768;
constexpr int PP = 683;
constexpr int NBYTE = 260;
constexpr int HASHMASK = 65535;     // HASH_VOCAB = 65536
constexpr int BS  = BB * SS;        // 16384 rows
constexpr int BSD = BS * DD;
constexpr int BPD = BB * PP * DD;
constexpr int CC  = 32;             // scan chunks
constexpr int LL  = SS / CC;        // 128
constexpr int CBD = CC * BB * DD;
constexpr int GK  = 768;            // GEMM K
constexpr int NLOGPAD = 384;        // logits N padded to 3*128

// ---------------- scratch layout (floats) ----------------
constexpr size_t OFF_X    = 0;
constexpr size_t OFF_Y    = OFF_X   + BSD;
constexpr size_t OFF_AB   = OFF_Y   + BSD;          // float2 [BS, DD]
constexpr size_t OFF_XH   = OFF_AB  + 2 * (size_t)BSD;
constexpr size_t OFF_XL   = OFF_XH  + BSD / 2;
constexpr size_t OFF_HH   = OFF_XL  + BSD / 2;
constexpr size_t OFF_HL   = OFF_HH  + BSD / 2;
constexpr size_t OFF_PAT  = OFF_HL  + BSD / 2;
constexpr size_t OFF_CAR  = OFF_PAT + BPD;          // float2 CBD
constexpr size_t OFF_HIN  = OFF_CAR + 2 * (size_t)CBD;
constexpr size_t OFF_CUM  = OFF_HIN + CBD;          // int
constexpr size_t OFF_PID  = OFF_CUM + BB * PP;      // int
constexpr size_t WHG_E    = 1536 * 768 / 2;         // bf16 elems / 2 = floats
constexpr size_t WOUT_E   = 768 * 768 / 2;
constexpr size_t WLOG_E   = (size_t)NLOGPAD * 768 / 2;
constexpr size_t OFF_WHGHE = OFF_PID + BS;
constexpr size_t OFF_WHGLE = OFF_WHGHE + WHG_E;
constexpr size_t OFF_WOUHE = OFF_WHGLE + WHG_E;
constexpr size_t OFF_WOULE = OFF_WOUHE + WOUT_E;
constexpr size_t OFF_WHGHD = OFF_WOULE + WOUT_E;
constexpr size_t OFF_WHGLD = OFF_WHGHD + WHG_E;
constexpr size_t OFF_WOUHD = OFF_WHGLD + WHG_E;
constexpr size_t OFF_WOULD = OFF_WOUHD + WOUT_E;
constexpr size_t OFF_WLGH  = OFF_WOULD + WOUT_E;
constexpr size_t OFF_WLGL  = OFF_WLGH + WLOG_E;
constexpr size_t SCRATCH_FLOATS = OFF_WLGL + WLOG_E + 64;
__device__ float g_scratch[SCRATCH_FLOATS];

// ---------------- PTX helpers (sm_100 baseline only) ----------------
__device__ __forceinline__ uint32_t s2u(const void* p) {
    uint32_t a;
    asm("{ .reg .u64 t; cvta.to.shared.u64 t, %1; cvt.u32.u64 %0, t; }" : "=r"(a) : "l"(p));
    return a;
}
__device__ __forceinline__ void cp16(uint32_t dst, const void* src) {
    asm volatile("cp.async.cg.shared.global [%0], [%1], 16;" :: "r"(dst), "l"(src));
}
__device__ __forceinline__ void cp_commit() { asm volatile("cp.async.commit_group;" ::: "memory"); }
template <int N>
__device__ __forceinline__ void cp_wait() { asm volatile("cp.async.wait_group %0;" :: "n"(N) : "memory"); }

__device__ __forceinline__ void ldsm_x4(uint32_t& r0, uint32_t& r1, uint32_t& r2, uint32_t& r3,
                                        uint32_t addr) {
    asm volatile("ldmatrix.sync.aligned.m8n8.x4.shared.b16 {%0,%1,%2,%3}, [%4];"
                 : "=r"(r0), "=r"(r1), "=r"(r2), "=r"(r3) : "r"(addr));
}
__device__ __forceinline__ void ldsm_x2(uint32_t& r0, uint32_t& r1, uint32_t addr) {
    asm volatile("ldmatrix.sync.aligned.m8n8.x2.shared.b16 {%0,%1}, [%2];"
                 : "=r"(r0), "=r"(r1) : "r"(addr));
}
__device__ __forceinline__ void mma16816(float* c, const uint32_t* a, const uint32_t* b) {
    asm volatile(
        "mma.sync.aligned.m16n8k16.row.col.f32.bf16.bf16.f32 "
        "{%0,%1,%2,%3}, {%4,%5,%6,%7}, {%8,%9}, {%0,%1,%2,%3};"
        : "+f"(c[0]), "+f"(c[1]), "+f"(c[2]), "+f"(c[3])
        : "r"(a[0]), "r"(a[1]), "r"(a[2]), "r"(a[3]), "r"(b[0]), "r"(b[1]));
}

__device__ __forceinline__ uint32_t sw128(uint32_t o) { return o ^ ((o >> 3) & 0x70); }

// ---------------- minGRU coefficients ----------------
__device__ __forceinline__ void mingru_coef(float hidden, float gate, float& a, float& bv) {
    float e    = __expf(-fabsf(gate));
    float inv  = 1.f / (1.f + e);
    float sneg = e * inv;
    float spos = inv;
    float z = (gate >= 0.f) ? spos : sneg;
    a       = (gate >= 0.f) ? sneg : spos;
    float g;
    if (hidden >= 0.f) g = hidden + 0.5f;
    else {
        float eh = __expf(hidden);
        g = eh / (1.f + eh);
    }
    bv = z * g;
}

__device__ __forceinline__ void split_bf16(float v, __nv_bfloat16& hi, __nv_bfloat16& lo) {
    hi = __float2bfloat16(v);
    lo = __float2bfloat16(v - __bfloat162float(hi));
}

// ================= HMMA split-bf16 GEMM =================
// C[128x128 tile] = Ah@Bh^T + Al@Bh^T + Ah@Bl^T over K=768 (A:[M,K] rm, B:[N,K] rm)
// EPI: 1 = minGRU (a,b) from interleaved (hid,gate) cols -> ab float2 [BS,768]
//      2 = += Res, store fp32 [BS,768]
//      3 = logits, store fp32 [BS,260] col-guarded
template <int EPI>
__global__ void __launch_bounds__(256, 1)
k_hgemm(const __nv_bfloat16* __restrict__ Ah, const __nv_bfloat16* __restrict__ Al,
        const __nv_bfloat16* __restrict__ Bh, const __nv_bfloat16* __restrict__ Bl,
        const float* __restrict__ Res, float* __restrict__ Cout, int Nld) {
    constexpr int KC = 64;              // bf16 per k-chunk (128 bytes)
    constexpr int NCHK = GK / KC;       // 12
    constexpr int NCH = 3 * NCHK;       // 36
    constexpr int NS = 3;
    constexpr int TILE = 128 * 128;     // bytes per matrix per stage
    constexpr int STAGE = 2 * TILE;

    extern __shared__ char smem[];
    uint32_t sb = s2u(smem);

    int tid = threadIdx.x;
    int lane = tid & 31, wid = tid >> 5;
    int wm = wid >> 2, wn = wid & 3;    // warp tile: rows wm*64, cols wn*32
    int m0 = blockIdx.y * 128, n0 = blockIdx.x * 128;

    const __nv_bfloat16* Asel[3] = {Ah, Al, Ah};
    const __nv_bfloat16* Bsel[3] = {Bh, Bh, Bl};

    auto load_stage = [&](int it) {
        int p = it / NCHK, kc = it % NCHK, s = it % NS;
        uint32_t abase = sb + s * STAGE;
        uint32_t bbase = abase + TILE;
        const __nv_bfloat16* Ap = Asel[p] + (size_t)m0 * GK + kc * KC;
        const __nv_bfloat16* Bp = Bsel[p] + (size_t)n0 * GK + kc * KC;
#pragma unroll
        for (int i = 0; i < 4; i++) {          // 128 rows * 8 chunks / 256 threads
            int idx = tid + i * 256;
            int r = idx >> 3, sg = idx & 7;
            cp16(abase + sw128(r * 128 + sg * 16), Ap + (size_t)r * GK + sg * 8);
        }
#pragma unroll
        for (int i = 0; i < 4; i++) {
            int idx = tid + i * 256;
            int r = idx >> 3, sg = idx & 7;
            cp16(bbase + sw128(r * 128 + sg * 16), Bp + (size_t)r * GK + sg * 8);
        }
    };

    float acc[4][4][4];
#pragma unroll
    for (int i = 0; i < 4; i++)
#pragma unroll
        for (int j = 0; j < 4; j++)
#pragma unroll
            for (int q = 0; q < 4; q++) acc[i][j][q] = 0.f;

    // precompute ldmatrix base offsets (lane-dependent, stage-independent)
    int aRow = (lane & 15);                  // within 16-row tile
    int aSel = (lane >> 4);                  // 16B half of 32B k16 group
    int bRow = (lane & 7);
    int bSel = ((lane >> 3) & 1);

    load_stage(0); cp_commit();
    load_stage(1); cp_commit();

    for (int it = 0; it < NCH; it++) {
        cp_wait<1>();
        __syncthreads();
        int nx = it + 2;
        if (nx < NCH) load_stage(nx);
        cp_commit();

        int s = it % NS;
        uint32_t abase = sb + s * STAGE;
        uint32_t bbase = abase + TILE;
#pragma unroll
        for (int kk = 0; kk < 4; kk++) {
            uint32_t af[4][4], bf[4][2];
#pragma unroll
            for (int i = 0; i < 4; i++) {
                int row = wm * 64 + i * 16 + aRow;
                int chunk = (kk * 2 + aSel) ^ (row & 7);
                ldsm_x4(af[i][0], af[i][1], af[i][2], af[i][3], abase + row * 128 + chunk * 16);
            }
#pragma unroll
            for (int j = 0; j < 4; j++) {
                int row = wn * 32 + j * 8 + bRow;
                int chunk = (kk * 2 + bSel) ^ (row & 7);
                ldsm_x2(bf[j][0], bf[j][1], bbase + row * 128 + chunk * 16);
            }
#pragma unroll
            for (int i = 0; i < 4; i++)
#pragma unroll
                for (int j = 0; j < 4; j++) mma16816(acc[i][j], af[i], bf[j]);
        }
    }

    // ---------------- epilogue ----------------
    int cRow = lane >> 2;            // 0..7
    int cCol = (lane & 3) * 2;       // even
#pragma unroll
    for (int i = 0; i < 4; i++) {
#pragma unroll
        for (int j = 0; j < 4; j++) {
            int r0 = m0 + wm * 64 + i * 16 + cRow;
            int r1 = r0 + 8;
            int col = n0 + wn * 32 + j * 8 + cCol;
            float c0 = acc[i][j][0], c1 = acc[i][j][1];
            float c2 = acc[i][j][2], c3 = acc[i][j][3];
            if (EPI == 1) {
                float2* ab = (float2*)Cout;
                int d = col >> 1;
                float a, bv;
                mingru_coef(c0, c1, a, bv);
                ab[(size_t)r0 * DD + d] = make_float2(a, bv);
                mingru_coef(c2, c3, a, bv);
                ab[(size_t)r1 * DD + d] = make_float2(a, bv);
            } else if (EPI == 2) {
                const float2* rr0 = (const float2*)(Res + (size_t)r0 * DD + col);
                const float2* rr1 = (const float2*)(Res + (size_t)r1 * DD + col);
                float2 v0 = rr0[0], v1 = rr1[0];
                *(float2*)(Cout + (size_t)r0 * DD + col) = make_float2(c0 + v0.x, c1 + v0.y);
                *(float2*)(Cout + (size_t)r1 * DD + col) = make_float2(c2 + v1.x, c3 + v1.y);
            } else {
                if (col < NBYTE) {
                    Cout[(size_t)r0 * NBYTE + col] = c0;
                    Cout[(size_t)r1 * NBYTE + col] = c2;
                }
                if (col + 1 < NBYTE) {
                    Cout[(size_t)r0 * NBYTE + col + 1] = c1;
                    Cout[(size_t)r1 * NBYTE + col + 1] = c3;
                }
            }
        }
    }
    (void)Nld;
}

// ---------------- weight prep: [K,N] fp32 -> transposed [Npad,K] bf16 hi/lo ----------------
// mode 0: identity column map; mode 1: interleave (even n -> col n/2, odd -> N/2 + n/2)
__global__ void k_wprep(const float* __restrict__ W, __nv_bfloat16* __restrict__ Wh,
                        __nv_bfloat16* __restrict__ Wl, int N, int mode, int nvalid) {
    __shared__ float tile[32][33];
    int n0 = blockIdx.x * 32, k0 = blockIdx.y * 32;
    int tx = threadIdx.x, ty = threadIdx.y;
    int n = n0 + tx;
    float v = 0.f;
    if (n < nvalid) {
        int src = (mode == 1) ? ((n & 1) ? (N >> 1) + (n >> 1) : (n >> 1)) : n;
        v = W[(size_t)(k0 + ty) * N + src];
    }
    tile[ty][tx] = v;
    __syncthreads();
    int on = n0 + ty, ok = k0 + tx;
    float w = tile[tx][ty];
    __nv_bfloat16 hi, lo;
    split_bf16(w, hi, lo);
    Wh[(size_t)on * GK + ok] = hi;
    Wl[(size_t)on * GK + ok] = lo;
}

// ---------------- embed + rmsnorm fused ----------------
__global__ void k_embed_rms(const int* __restrict__ ids, const float* __restrict__ tok,
                            const float* __restrict__ hsh, const float* __restrict__ nw,
                            float* __restrict__ x, __nv_bfloat16* __restrict__ xh,
                            __nv_bfloat16* __restrict__ xl) {
    int bs = blockIdx.x;
    int s = bs & (SS - 1);
    int t0 = ids[bs];
    int acc = t0, p = 31;
#pragma unroll
    for (int j = 1; j < 4; j++) {
        if (s >= j) acc += ids[bs - j] * p;
        p *= 31;
    }
    int hid = acc & HASHMASK;
    const float* tr = tok + (size_t)t0 * DD;
    const float* hr = hsh + (size_t)hid * DD;
    float vals[3];
    float ss = 0.f;
#pragma unroll
    for (int i = 0; i < 3; i++) {
        int d = threadIdx.x + i * 256;
        float v = tr[d] + hr[d];
        vals[i] = v;
        ss += v * v;
    }
    __shared__ float red[8];
#pragma unroll
    for (int o = 16; o > 0; o >>= 1) ss += __shfl_xor_sync(~0u, ss, o);
    if ((threadIdx.x & 31) == 0) red[threadIdx.x >> 5] = ss;
    __syncthreads();
    if (threadIdx.x == 0) {
        float v = 0.f;
#pragma unroll
        for (int i = 0; i < 8; i++) v += red[i];
        red[0] = rsqrtf(v / DD + 1e-6f);
    }
    __syncthreads();
    float r = red[0];
    size_t rb = (size_t)bs * DD;
#pragma unroll
    for (int i = 0; i < 3; i++) {
        int d = threadIdx.x + i * 256;
        x[rb + d] = vals[i];
        float v = vals[i] * r * nw[d];
        __nv_bfloat16 hi, lo;
        split_bf16(v, hi, lo);
        xh[rb + d] = hi;
        xl[rb + d] = lo;
    }
}

// ---------------- gadd + rmsnorm fused ----------------
__global__ void k_gadd_rms(const float* __restrict__ y, const float* __restrict__ patch,
                           const int* __restrict__ pid, const float* __restrict__ nw,
                           float* __restrict__ x, __nv_bfloat16* __restrict__ xh,
                           __nv_bfloat16* __restrict__ xl) {
    int bs = blockIdx.x;
    int b = bs / SS;
    const float* pr = patch + (size_t)(b * PP + pid[bs]) * DD;
    const float* yr = y + (size_t)bs * DD;
    float vals[3];
    float ss = 0.f;
#pragma unroll
    for (int i = 0; i < 3; i++) {
        int d = threadIdx.x + i * 256;
        float v = yr[d] + pr[d];
        vals[i] = v;
        ss += v * v;
    }
    __shared__ float red[8];
#pragma unroll
    for (int o = 16; o > 0; o >>= 1) ss += __shfl_xor_sync(~0u, ss, o);
    if ((threadIdx.x & 31) == 0) red[threadIdx.x >> 5] = ss;
    __syncthreads();
    if (threadIdx.x == 0) {
        float v = 0.f;
#pragma unroll
        for (int i = 0; i < 8; i++) v += red[i];
        red[0] = rsqrtf(v / DD + 1e-6f);
    }
    __syncthreads();
    float r = red[0];
    size_t rb = (size_t)bs * DD;
#pragma unroll
    for (int i = 0; i < 3; i++) {
        int d = threadIdx.x + i * 256;
        x[rb + d] = vals[i];
        float v = vals[i] * r * nw[d];
        __nv_bfloat16 hi, lo;
        split_bf16(v, hi, lo);
        xh[rb + d] = hi;
        xl[rb + d] = lo;
    }
}

// ---------------- final rmsnorm (bf16 hi/lo only) ----------------
__global__ void k_rms_b(const float* __restrict__ y, const float* __restrict__ nw,
                        __nv_bfloat16* __restrict__ xh, __nv_bfloat16* __restrict__ xl) {
    int bs = blockIdx.x;
    const float* yr = y + (size_t)bs * DD;
    float vals[3];
    float ss = 0.f;
#pragma unroll
    for (int i = 0; i < 3; i++) {
        int d = threadIdx.x + i * 256;
        float v = yr[d];
        vals[i] = v;
        ss += v * v;
    }
    __shared__ float red[8];
#pragma unroll
    for (int o = 16; o > 0; o >>= 1) ss += __shfl_xor_sync(~0u, ss, o);
    if ((threadIdx.x & 31) == 0) red[threadIdx.x >> 5] = ss;
    __syncthreads();
    if (threadIdx.x == 0) {
        float v = 0.f;
#pragma unroll
        for (int i = 0; i < 8; i++) v += red[i];
        red[0] = rsqrtf(v / DD + 1e-6f);
    }
    __syncthreads();
    float r = red[0];
    size_t rb = (size_t)bs * DD;
#pragma unroll
    for (int i = 0; i < 3; i++) {
        int d = threadIdx.x + i * 256;
        float v = vals[i] * r * nw[d];
        __nv_bfloat16 hi, lo;
        split_bf16(v, hi, lo);
        xh[rb + d] = hi;
        xl[rb + d] = lo;
    }
}

// ---------------- minGRU scan over precomputed (a,b) ----------------
__global__ void k_scan_red(const float2* __restrict__ ab, float2* __restrict__ carry) {
    int idx = blockIdx.x * 256 + threadIdx.x;
    int d = idx % DD;
    int bc = idx / DD;
    int b = bc % BB;
    int c = bc / BB;
    const float2* base = ab + (size_t)(b * SS + c * LL) * DD + d;
    float A = 1.f, Bv = 0.f;
#pragma unroll 4
    for (int t = 0; t < LL; t++) {
        float2 v = *base;
        base += DD;
        A *= v.x;
        Bv = fmaf(v.x, Bv, v.y);
    }
    carry[idx] = make_float2(A, Bv);
}

__global__ void k_scan_carry(const float2* __restrict__ carry, float* __restrict__ hinit) {
    int ch = blockIdx.x * 256 + threadIdx.x;
    int d = ch % DD;
    int b = ch / DD;
    float h = 0.f;
#pragma unroll
    for (int c = 0; c < CC; c++) {
        int i = (c * BB + b) * DD + d;
        hinit[i] = h;
        float2 abv = carry[i];
        h = fmaf(abv.x, h, abv.y);
    }
}

__global__ void k_scan_apply(const float2* __restrict__ ab, const float* __restrict__ hinit,
                             __nv_bfloat16* __restrict__ hh, __nv_bfloat16* __restrict__ hl) {
    int idx = blockIdx.x * 256 + threadIdx.x;
    int d = idx % DD;
    int bc = idx / DD;
    int b = bc % BB;
    int c = bc / BB;
    size_t off = (size_t)(b * SS + c * LL) * DD + d;
    const float2* base = ab + off;
    float h = hinit[idx];
#pragma unroll 4
    for (int t = 0; t < LL; t++) {
        float2 v = *base;
        base += DD;
        h = fmaf(v.x, h, v.y);
        __nv_bfloat16 hi, lo;
        split_bf16(h, hi, lo);
        hh[off] = hi;
        hl[off] = lo;
        off += DD;
    }
}

// ---------------- patch bookkeeping ----------------
__global__ void k_cum(const int* __restrict__ lens, int* __restrict__ cum) {
    int b = blockIdx.x;
    if (threadIdx.x == 0) {
        int s = 0;
        for (int p = 0; p < PP; p++) {
            s += lens[b * PP + p];
            cum[b * PP + p] = s;
        }
    }
}

__global__ void k_pid(const int* __restrict__ cum, int* __restrict__ pid) {
    int i = blockIdx.x * 256 + threadIdx.x;
    if (i >= BS) return;
    int b = i / SS;
    int pos = i % SS;
    const int* c = cum + b * PP;
    int lo = 0, hi = PP;
    while (lo < hi) {
        int mid = (lo + hi) >> 1;
        if (c[mid] <= pos) lo = mid + 1;
        else hi = mid;
    }
    pid[i] = lo;
}

__global__ void k_segmax(const float* __restrict__ y, const int* __restrict__ cum,
                         float* __restrict__ patch) {
    int bp = blockIdx.x;
    int b = bp / PP, p = bp % PP;
    int start = p ? cum[b * PP + p - 1] : 0;
    int end = cum[b * PP + p];
    const float* yb = y + (size_t)b * SS * DD;
    float* orow = patch + (size_t)bp * DD;
    for (int d = threadIdx.x; d < DD; d += 256) {
        float m = -3.402823466e38f;
        for (int s = start; s < end; s++)
            m = fmaxf(m, yb[(size_t)s * DD + d]);
        orow[d] = m;
    }
}

// ---------------- launch ----------------
extern "C" void kernel_launch(void* const* d_in, const int* in_sizes, int n_in,
                              void* d_out, int out_size) {
    const int*   ids      = (const int*)d_in[0];
    const int*   lens     = (const int*)d_in[1];
    const float* tok      = (const float*)d_in[2];
    const float* hsh      = (const float*)d_in[3];
    const float* enc_nw   = (const float*)d_in[4];
    const float* enc_whg  = (const float*)d_in[5];
    const float* enc_wout = (const float*)d_in[6];
    const float* dec_nw   = (const float*)d_in[7];
    const float* dec_whg  = (const float*)d_in[8];
    const float* dec_wout = (const float*)d_in[9];
    const float* fin_nw   = (const float*)d_in[10];
    const float* oproj    = (const float*)d_in[11];
    float*       out      = (float*)d_out;

    float* base = nullptr;
    cudaGetSymbolAddress((void**)&base, g_scratch);
    float*         x     = base + OFF_X;
    float*         y     = base + OFF_Y;
    float2*        ab    = (float2*)(base + OFF_AB);
    __nv_bfloat16* xh    = (__nv_bfloat16*)(base + OFF_XH);
    __nv_bfloat16* xl    = (__nv_bfloat16*)(base + OFF_XL);
    __nv_bfloat16* hh    = (__nv_bfloat16*)(base + OFF_HH);
    __nv_bfloat16* hl    = (__nv_bfloat16*)(base + OFF_HL);
    float*         patch = base + OFF_PAT;
    float2*        carry = (float2*)(base + OFF_CAR);
    float*         hinit = base + OFF_HIN;
    int*           cum   = (int*)(base + OFF_CUM);
    int*           pid   = (int*)(base + OFF_PID);
    __nv_bfloat16* wHGhe = (__nv_bfloat16*)(base + OFF_WHGHE);
    __nv_bfloat16* wHGle = (__nv_bfloat16*)(base + OFF_WHGLE);
    __nv_bfloat16* wOUhe = (__nv_bfloat16*)(base + OFF_WOUHE);
    __nv_bfloat16* wOUle = (__nv_bfloat16*)(base + OFF_WOULE);
    __nv_bfloat16* wHGhd = (__nv_bfloat16*)(base + OFF_WHGHD);
    __nv_bfloat16* wHGld = (__nv_bfloat16*)(base + OFF_WHGLD);
    __nv_bfloat16* wOUhd = (__nv_bfloat16*)(base + OFF_WOUHD);
    __nv_bfloat16* wOUld = (__nv_bfloat16*)(base + OFF_WOULD);
    __nv_bfloat16* wLGh  = (__nv_bfloat16*)(base + OFF_WLGH);
    __nv_bfloat16* wLGl  = (__nv_bfloat16*)(base + OFF_WLGL);

    constexpr int SMEM = 3 * 2 * 128 * 128;  // 98304 bytes
    cudaFuncSetAttribute(k_hgemm<1>, cudaFuncAttributeMaxDynamicSharedMemorySize, SMEM);
    cudaFuncSetAttribute(k_hgemm<2>, cudaFuncAttributeMaxDynamicSharedMemorySize, SMEM);
    cudaFuncSetAttribute(k_hgemm<3>, cudaFuncAttributeMaxDynamicSharedMemorySize, SMEM);

    // weight prep (independent)
    dim3 tb(32, 32);
    k_wprep<<<dim3(1536 / 32, GK / 32), tb>>>(enc_whg, wHGhe, wHGle, 1536, 1, 1536);
    k_wprep<<<dim3(768 / 32, GK / 32), tb>>>(enc_wout, wOUhe, wOUle, 768, 0, 768);
    k_wprep<<<dim3(1536 / 32, GK / 32), tb>>>(dec_whg, wHGhd, wHGld, 1536, 1, 1536);
    k_wprep<<<dim3(768 / 32, GK / 32), tb>>>(dec_wout, wOUhd, wOUld, 768, 0, 768);
    k_wprep<<<dim3(NLOGPAD / 32, GK / 32), tb>>>(oproj, wLGh, wLGl, NBYTE, 0, NBYTE);

    // patch bookkeeping
    k_cum<<<BB, 32>>>(lens, cum);
    k_pid<<<(BS + 255) / 256, 256>>>(cum, pid);

    // embeddings + encoder rmsnorm
    k_embed_rms<<<BS, 256>>>(ids, tok, hsh, enc_nw, x, xh, xl);

    // ---- encoder block ----
    k_hgemm<1><<<dim3(12, 128), 256, SMEM>>>(xh, xl, wHGhe, wHGle, nullptr, (float*)ab, 1536);
    k_scan_red<<<CBD / 256, 256>>>(ab, carry);
    k_scan_carry<<<(BB * DD) / 256, 256>>>(carry, hinit);
    k_scan_apply<<<CBD / 256, 256>>>(ab, hinit, hh, hl);
    k_hgemm<2><<<dim3(6, 128), 256, SMEM>>>(hh, hl, wOUhe, wOUle, x, y, 768);

    // ---- patch pooling + decoder input (+ decoder rmsnorm fused) ----
    k_segmax<<<BB * PP, 256>>>(y, cum, patch);
    k_gadd_rms<<<BS, 256>>>(y, patch, pid, dec_nw, x, xh, xl);

    // ---- decoder block ----
    k_hgemm<1><<<dim3(12, 128), 256, SMEM>>>(xh, xl, wHGhd, wHGld, nullptr, (float*)ab, 1536);
    k_scan_red<<<CBD / 256, 256>>>(ab, carry);
    k_scan_carry<<<(BB * DD) / 256, 256>>>(carry, hinit);
    k_scan_apply<<<CBD / 256, 256>>>(ab, hinit, hh, hl);
    k_hgemm<2><<<dim3(6, 128), 256, SMEM>>>(hh, hl, wOUhd, wOUld, x, y, 768);

    // ---- final norm + logits ----
    k_rms_b<<<BS, 256>>>(y, fin_nw, xh, xl);
    k_hgemm<3><<<dim3(3, 128), 256, SMEM>>>(xh, xl, wLGh, wLGl, nullptr, out, NLOGPAD);
}

// round 7
// speedup vs baseline: 2.6816x; 1.2082x over previous
#include <cuda_runtime.h>
#include <cuda_bf16.h>
#include <math.h>
#include <stdint.h>

// ---------------- problem constants ----------------
constexpr int BB = 4;
constexpr int SS = 4096;
constexpr int DD = 768;
constexpr int PP = 683;
constexpr int NBYTE = 260;
constexpr int HASHMASK = 65535;     // HASH_VOCAB = 65536
constexpr int BS  = BB * SS;        // 16384 rows
constexpr int BSD = BS * DD;
constexpr int BPD = BB * PP * DD;
constexpr int CC  = 32;             // scan chunks
constexpr int LL  = SS / CC;        // 128
constexpr int CBD = CC * BB * DD;
constexpr int GK  = 768;            // GEMM K
constexpr int NLOGPAD = 384;        // logits N padded to 3*128

// ---------------- scratch layout (floats) ----------------
constexpr size_t OFF_X    = 0;
constexpr size_t OFF_Y    = OFF_X   + BSD;
constexpr size_t OFF_AB   = OFF_Y   + BSD;          // float2 [BS, DD]
constexpr size_t OFF_XH   = OFF_AB  + 2 * (size_t)BSD;
constexpr size_t OFF_XL   = OFF_XH  + BSD / 2;
constexpr size_t OFF_HH   = OFF_XL  + BSD / 2;
constexpr size_t OFF_HL   = OFF_HH  + BSD / 2;
constexpr size_t OFF_PAT  = OFF_HL  + BSD / 2;
constexpr size_t OFF_CAR  = OFF_PAT + BPD;          // float2 CBD
constexpr size_t OFF_HIN  = OFF_CAR + 2 * (size_t)CBD;
constexpr size_t OFF_CUM  = OFF_HIN + CBD;          // int
constexpr size_t OFF_PID  = OFF_CUM + BB * PP;      // int
constexpr size_t WHG_E    = 1536 * 768 / 2;         // bf16 elems / 2 = floats
constexpr size_t WOUT_E   = 768 * 768 / 2;
constexpr size_t WLOG_E   = (size_t)NLOGPAD * 768 / 2;
constexpr size_t OFF_WHGHE = OFF_PID + BS;
constexpr size_t OFF_WHGLE = OFF_WHGHE + WHG_E;
constexpr size_t OFF_WOUHE = OFF_WHGLE + WHG_E;
constexpr size_t OFF_WOULE = OFF_WOUHE + WOUT_E;
constexpr size_t OFF_WHGHD = OFF_WOULE + WOUT_E;
constexpr size_t OFF_WHGLD = OFF_WHGHD + WHG_E;
constexpr size_t OFF_WOUHD = OFF_WHGLD + WHG_E;
constexpr size_t OFF_WOULD = OFF_WOUHD + WOUT_E;
constexpr size_t OFF_WLGH  = OFF_WOULD + WOUT_E;
constexpr size_t OFF_WLGL  = OFF_WLGH + WLOG_E;
constexpr size_t SCRATCH_FLOATS = OFF_WLGL + WLOG_E + 64;
__device__ float g_scratch[SCRATCH_FLOATS];

// ---------------- PTX helpers (sm_100 baseline only) ----------------
__device__ __forceinline__ uint32_t s2u(const void* p) {
    uint32_t a;
    asm("{ .reg .u64 t; cvta.to.shared.u64 t, %1; cvt.u32.u64 %0, t; }" : "=r"(a) : "l"(p));
    return a;
}
__device__ __forceinline__ void cp16(uint32_t dst, const void* src) {
    asm volatile("cp.async.cg.shared.global [%0], [%1], 16;" :: "r"(dst), "l"(src));
}
__device__ __forceinline__ void cp_commit() { asm volatile("cp.async.commit_group;" ::: "memory"); }
template <int N>
__device__ __forceinline__ void cp_wait() { asm volatile("cp.async.wait_group %0;" :: "n"(N) : "memory"); }

__device__ __forceinline__ void ldsm_x4(uint32_t& r0, uint32_t& r1, uint32_t& r2, uint32_t& r3,
                                        uint32_t addr) {
    asm volatile("ldmatrix.sync.aligned.m8n8.x4.shared.b16 {%0,%1,%2,%3}, [%4];"
                 : "=r"(r0), "=r"(r1), "=r"(r2), "=r"(r3) : "r"(addr));
}
__device__ __forceinline__ void ldsm_x2(uint32_t& r0, uint32_t& r1, uint32_t addr) {
    asm volatile("ldmatrix.sync.aligned.m8n8.x2.shared.b16 {%0,%1}, [%2];"
                 : "=r"(r0), "=r"(r1) : "r"(addr));
}
__device__ __forceinline__ void mma16816(float* c, const uint32_t* a, const uint32_t* b) {
    asm volatile(
        "mma.sync.aligned.m16n8k16.row.col.f32.bf16.bf16.f32 "
        "{%0,%1,%2,%3}, {%4,%5,%6,%7}, {%8,%9}, {%0,%1,%2,%3};"
        : "+f"(c[0]), "+f"(c[1]), "+f"(c[2]), "+f"(c[3])
        : "r"(a[0]), "r"(a[1]), "r"(a[2]), "r"(a[3]), "r"(b[0]), "r"(b[1]));
}

__device__ __forceinline__ uint32_t sw128(uint32_t o) { return o ^ ((o >> 3) & 0x70); }

// ---------------- minGRU coefficients ----------------
__device__ __forceinline__ void mingru_coef(float hidden, float gate, float& a, float& bv) {
    float e    = __expf(-fabsf(gate));
    float inv  = 1.f / (1.f + e);
    float sneg = e * inv;
    float spos = inv;
    float z = (gate >= 0.f) ? spos : sneg;
    a       = (gate >= 0.f) ? sneg : spos;
    float g;
    if (hidden >= 0.f) g = hidden + 0.5f;
    else {
        float eh = __expf(hidden);
        g = eh / (1.f + eh);
    }
    bv = z * g;
}

__device__ __forceinline__ void split_bf16(float v, __nv_bfloat16& hi, __nv_bfloat16& lo) {
    hi = __float2bfloat16(v);
    lo = __float2bfloat16(v - __bfloat162float(hi));
}

// ================= HMMA split-bf16 GEMM (combined-chunk pipeline) =================
// Per k-chunk: stage Ah,Al,Bh,Bl once; issue AhBh + AlBh + AhBl from it.
// 512 threads, 16 warps (4x4), warp tile 32x32 of the 128x128 CTA tile.
// EPI: 1 = minGRU (a,b) from interleaved (hid,gate) cols -> ab float2 [BS,768]
//      2 = += Res, store fp32 [BS,768]
//      3 = logits, store fp32 [BS,260] col-guarded
template <int EPI>
__global__ void __launch_bounds__(512, 1)
k_hgemm(const __nv_bfloat16* __restrict__ Ah, const __nv_bfloat16* __restrict__ Al,
        const __nv_bfloat16* __restrict__ Bh, const __nv_bfloat16* __restrict__ Bl,
        const float* __restrict__ Res, float* __restrict__ Cout) {
    constexpr int KC = 64;              // bf16 per k-chunk (128 bytes)
    constexpr int NCH = GK / KC;        // 12
    constexpr int MAT = 128 * 128;      // bytes per matrix tile
    constexpr int STAGE = 4 * MAT;      // Ah|Al|Bh|Bl

    extern __shared__ char smem[];
    uint32_t sb = s2u(smem);

    int tid = threadIdx.x;
    int lane = tid & 31, wid = tid >> 5;
    int wm = wid >> 2, wn = wid & 3;    // warp tile: rows wm*32, cols wn*32
    int m0 = blockIdx.y * 128, n0 = blockIdx.x * 128;

    auto load_stage = [&](int kc) {
        uint32_t st = sb + (kc & 1) * STAGE;
        const __nv_bfloat16* ah = Ah + (size_t)m0 * GK + kc * KC;
        const __nv_bfloat16* al = Al + (size_t)m0 * GK + kc * KC;
        const __nv_bfloat16* bh = Bh + (size_t)n0 * GK + kc * KC;
        const __nv_bfloat16* bl = Bl + (size_t)n0 * GK + kc * KC;
#pragma unroll
        for (int i = 0; i < 2; i++) {          // 128 rows * 8 segs / 512 threads
            int idx = tid + i * 512;
            int r = idx >> 3, sg = idx & 7;
            uint32_t so = sw128(r * 128 + sg * 16);
            size_t go = (size_t)r * GK + sg * 8;
            cp16(st + 0 * MAT + so, ah + go);
            cp16(st + 1 * MAT + so, al + go);
            cp16(st + 2 * MAT + so, bh + go);
            cp16(st + 3 * MAT + so, bl + go);
        }
    };

    float acc[2][4][4];
#pragma unroll
    for (int i = 0; i < 2; i++)
#pragma unroll
        for (int j = 0; j < 4; j++)
#pragma unroll
            for (int q = 0; q < 4; q++) acc[i][j][q] = 0.f;

    int aRow = (lane & 15);
    int aSel = (lane >> 4);
    int bRow = (lane & 7);
    int bSel = ((lane >> 3) & 1);

    load_stage(0); cp_commit();
    load_stage(1); cp_commit();

    for (int it = 0; it < NCH; it++) {
        cp_wait<1>();
        __syncthreads();
        uint32_t st = sb + (it & 1) * STAGE;
#pragma unroll
        for (int kk = 0; kk < 4; kk++) {
            uint32_t afh[2][4], afl[2][4], bfh[4][2], bfl[4][2];
#pragma unroll
            for (int i = 0; i < 2; i++) {
                int row = wm * 32 + i * 16 + aRow;
                int chunk = (kk * 2 + aSel) ^ (row & 7);
                uint32_t off = row * 128 + chunk * 16;
                ldsm_x4(afh[i][0], afh[i][1], afh[i][2], afh[i][3], st + 0 * MAT + off);
                ldsm_x4(afl[i][0], afl[i][1], afl[i][2], afl[i][3], st + 1 * MAT + off);
            }
#pragma unroll
            for (int j = 0; j < 4; j++) {
                int row = wn * 32 + j * 8 + bRow;
                int chunk = (kk * 2 + bSel) ^ (row & 7);
                uint32_t off = row * 128 + chunk * 16;
                ldsm_x2(bfh[j][0], bfh[j][1], st + 2 * MAT + off);
                ldsm_x2(bfl[j][0], bfl[j][1], st + 3 * MAT + off);
            }
#pragma unroll
            for (int i = 0; i < 2; i++)
#pragma unroll
                for (int j = 0; j < 4; j++) {
                    mma16816(acc[i][j], afh[i], bfh[j]);
                    mma16816(acc[i][j], afl[i], bfh[j]);
                    mma16816(acc[i][j], afh[i], bfl[j]);
                }
        }
        __syncthreads();
        if (it + 2 < NCH) load_stage(it + 2);
        cp_commit();
    }

    // ---------------- epilogue ----------------
    int cRow = lane >> 2;            // 0..7
    int cCol = (lane & 3) * 2;       // even
#pragma unroll
    for (int i = 0; i < 2; i++) {
#pragma unroll
        for (int j = 0; j < 4; j++) {
            int r0 = m0 + wm * 32 + i * 16 + cRow;
            int r1 = r0 + 8;
            int col = n0 + wn * 32 + j * 8 + cCol;
            float c0 = acc[i][j][0], c1 = acc[i][j][1];
            float c2 = acc[i][j][2], c3 = acc[i][j][3];
            if (EPI == 1) {
                float2* ab = (float2*)Cout;
                int d = col >> 1;
                float a, bv;
                mingru_coef(c0, c1, a, bv);
                ab[(size_t)r0 * DD + d] = make_float2(a, bv);
                mingru_coef(c2, c3, a, bv);
                ab[(size_t)r1 * DD + d] = make_float2(a, bv);
            } else if (EPI == 2) {
                const float2* rr0 = (const float2*)(Res + (size_t)r0 * DD + col);
                const float2* rr1 = (const float2*)(Res + (size_t)r1 * DD + col);
                float2 v0 = rr0[0], v1 = rr1[0];
                *(float2*)(Cout + (size_t)r0 * DD + col) = make_float2(c0 + v0.x, c1 + v0.y);
                *(float2*)(Cout + (size_t)r1 * DD + col) = make_float2(c2 + v1.x, c3 + v1.y);
            } else {
                if (col < NBYTE) {
                    Cout[(size_t)r0 * NBYTE + col] = c0;
                    Cout[(size_t)r1 * NBYTE + col] = c2;
                }
                if (col + 1 < NBYTE) {
                    Cout[(size_t)r0 * NBYTE + col + 1] = c1;
                    Cout[(size_t)r1 * NBYTE + col + 1] = c3;
                }
            }
        }
    }
}

// ---------------- weight prep: [K,N] fp32 -> transposed [Npad,K] bf16 hi/lo ----------------
__global__ void k_wprep(const float* __restrict__ W, __nv_bfloat16* __restrict__ Wh,
                        __nv_bfloat16* __restrict__ Wl, int N, int mode, int nvalid) {
    __shared__ float tile[32][33];
    int n0 = blockIdx.x * 32, k0 = blockIdx.y * 32;
    int tx = threadIdx.x, ty = threadIdx.y;
    int n = n0 + tx;
    float v = 0.f;
    if (n < nvalid) {
        int src = (mode == 1) ? ((n & 1) ? (N >> 1) + (n >> 1) : (n >> 1)) : n;
        v = W[(size_t)(k0 + ty) * N + src];
    }
    tile[ty][tx] = v;
    __syncthreads();
    int on = n0 + ty, ok = k0 + tx;
    float w = tile[tx][ty];
    __nv_bfloat16 hi, lo;
    split_bf16(w, hi, lo);
    Wh[(size_t)on * GK + ok] = hi;
    Wl[(size_t)on * GK + ok] = lo;
}

// ---------------- embed + rmsnorm fused ----------------
__global__ void k_embed_rms(const int* __restrict__ ids, const float* __restrict__ tok,
                            const float* __restrict__ hsh, const float* __restrict__ nw,
                            float* __restrict__ x, __nv_bfloat16* __restrict__ xh,
                            __nv_bfloat16* __restrict__ xl) {
    int bs = blockIdx.x;
    int s = bs & (SS - 1);
    int t0 = ids[bs];
    int acc = t0, p = 31;
#pragma unroll
    for (int j = 1; j < 4; j++) {
        if (s >= j) acc += ids[bs - j] * p;
        p *= 31;
    }
    int hid = acc & HASHMASK;
    const float* tr = tok + (size_t)t0 * DD;
    const float* hr = hsh + (size_t)hid * DD;
    float vals[3];
    float ss = 0.f;
#pragma unroll
    for (int i = 0; i < 3; i++) {
        int d = threadIdx.x + i * 256;
        float v = tr[d] + hr[d];
        vals[i] = v;
        ss += v * v;
    }
    __shared__ float red[8];
#pragma unroll
    for (int o = 16; o > 0; o >>= 1) ss += __shfl_xor_sync(~0u, ss, o);
    if ((threadIdx.x & 31) == 0) red[threadIdx.x >> 5] = ss;
    __syncthreads();
    if (threadIdx.x == 0) {
        float v = 0.f;
#pragma unroll
        for (int i = 0; i < 8; i++) v += red[i];
        red[0] = rsqrtf(v / DD + 1e-6f);
    }
    __syncthreads();
    float r = red[0];
    size_t rb = (size_t)bs * DD;
#pragma unroll
    for (int i = 0; i < 3; i++) {
        int d = threadIdx.x + i * 256;
        x[rb + d] = vals[i];
        float v = vals[i] * r * nw[d];
        __nv_bfloat16 hi, lo;
        split_bf16(v, hi, lo);
        xh[rb + d] = hi;
        xl[rb + d] = lo;
    }
}

// ---------------- gadd + rmsnorm fused ----------------
__global__ void k_gadd_rms(const float* __restrict__ y, const float* __restrict__ patch,
                           const int* __restrict__ pid, const float* __restrict__ nw,
                           float* __restrict__ x, __nv_bfloat16* __restrict__ xh,
                           __nv_bfloat16* __restrict__ xl) {
    int bs = blockIdx.x;
    int b = bs / SS;
    const float* pr = patch + (size_t)(b * PP + pid[bs]) * DD;
    const float* yr = y + (size_t)bs * DD;
    float vals[3];
    float ss = 0.f;
#pragma unroll
    for (int i = 0; i < 3; i++) {
        int d = threadIdx.x + i * 256;
        float v = yr[d] + pr[d];
        vals[i] = v;
        ss += v * v;
    }
    __shared__ float red[8];
#pragma unroll
    for (int o = 16; o > 0; o >>= 1) ss += __shfl_xor_sync(~0u, ss, o);
    if ((threadIdx.x & 31) == 0) red[threadIdx.x >> 5] = ss;
    __syncthreads();
    if (threadIdx.x == 0) {
        float v = 0.f;
#pragma unroll
        for (int i = 0; i < 8; i++) v += red[i];
        red[0] = rsqrtf(v / DD + 1e-6f);
    }
    __syncthreads();
    float r = red[0];
    size_t rb = (size_t)bs * DD;
#pragma unroll
    for (int i = 0; i < 3; i++) {
        int d = threadIdx.x + i * 256;
        x[rb + d] = vals[i];
        float v = vals[i] * r * nw[d];
        __nv_bfloat16 hi, lo;
        split_bf16(v, hi, lo);
        xh[rb + d] = hi;
        xl[rb + d] = lo;
    }
}

// ---------------- final rmsnorm (bf16 hi/lo only) ----------------
__global__ void k_rms_b(const float* __restrict__ y, const float* __restrict__ nw,
                        __nv_bfloat16* __restrict__ xh, __nv_bfloat16* __restrict__ xl) {
    int bs = blockIdx.x;
    const float* yr = y + (size_t)bs * DD;
    float vals[3];
    float ss = 0.f;
#pragma unroll
    for (int i = 0; i < 3; i++) {
        int d = threadIdx.x + i * 256;
        float v = yr[d];
        vals[i] = v;
        ss += v * v;
    }
    __shared__ float red[8];
#pragma unroll
    for (int o = 16; o > 0; o >>= 1) ss += __shfl_xor_sync(~0u, ss, o);
    if ((threadIdx.x & 31) == 0) red[threadIdx.x >> 5] = ss;
    __syncthreads();
    if (threadIdx.x == 0) {
        float v = 0.f;
#pragma unroll
        for (int i = 0; i < 8; i++) v += red[i];
        red[0] = rsqrtf(v / DD + 1e-6f);
    }
    __syncthreads();
    float r = red[0];
    size_t rb = (size_t)bs * DD;
#pragma unroll
    for (int i = 0; i < 3; i++) {
        int d = threadIdx.x + i * 256;
        float v = vals[i] * r * nw[d];
        __nv_bfloat16 hi, lo;
        split_bf16(v, hi, lo);
        xh[rb + d] = hi;
        xl[rb + d] = lo;
    }
}

// ---------------- minGRU scan over precomputed (a,b) ----------------
__global__ void k_scan_red(const float2* __restrict__ ab, float2* __restrict__ carry) {
    int idx = blockIdx.x * 256 + threadIdx.x;
    int d = idx % DD;
    int bc = idx / DD;
    int b = bc % BB;
    int c = bc / BB;
    const float2* base = ab + (size_t)(b * SS + c * LL) * DD + d;
    float A = 1.f, Bv = 0.f;
#pragma unroll 4
    for (int t = 0; t < LL; t++) {
        float2 v = *base;
        base += DD;
        A *= v.x;
        Bv = fmaf(v.x, Bv, v.y);
    }
    carry[idx] = make_float2(A, Bv);
}

__global__ void k_scan_carry(const float2* __restrict__ carry, float* __restrict__ hinit) {
    int ch = blockIdx.x * 256 + threadIdx.x;
    int d = ch % DD;
    int b = ch / DD;
    float h = 0.f;
#pragma unroll
    for (int c = 0; c < CC; c++) {
        int i = (c * BB + b) * DD + d;
        hinit[i] = h;
        float2 abv = carry[i];
        h = fmaf(abv.x, h, abv.y);
    }
}

__global__ void k_scan_apply(const float2* __restrict__ ab, const float* __restrict__ hinit,
                             __nv_bfloat16* __restrict__ hh, __nv_bfloat16* __restrict__ hl) {
    int idx = blockIdx.x * 256 + threadIdx.x;
    int d = idx % DD;
    int bc = idx / DD;
    int b = bc % BB;
    int c = bc / BB;
    size_t off = (size_t)(b * SS + c * LL) * DD + d;
    const float2* base = ab + off;
    float h = hinit[idx];
#pragma unroll 4
    for (int t = 0; t < LL; t++) {
        float2 v = *base;
        base += DD;
        h = fmaf(v.x, h, v.y);
        __nv_bfloat16 hi, lo;
        split_bf16(h, hi, lo);
        hh[off] = hi;
        hl[off] = lo;
        off += DD;
    }
}

// ---------------- patch bookkeeping ----------------
__global__ void k_cum(const int* __restrict__ lens, int* __restrict__ cum) {
    int b = blockIdx.x;
    if (threadIdx.x == 0) {
        int s = 0;
        for (int p = 0; p < PP; p++) {
            s += lens[b * PP + p];
            cum[b * PP + p] = s;
        }
    }
}

__global__ void k_pid(const int* __restrict__ cum, int* __restrict__ pid) {
    int i = blockIdx.x * 256 + threadIdx.x;
    if (i >= BS) return;
    int b = i / SS;
    int pos = i % SS;
    const int* c = cum + b * PP;
    int lo = 0, hi = PP;
    while (lo < hi) {
        int mid = (lo + hi) >> 1;
        if (c[mid] <= pos) lo = mid + 1;
        else hi = mid;
    }
    pid[i] = lo;
}

__global__ void k_segmax(const float* __restrict__ y, const int* __restrict__ cum,
                         float* __restrict__ patch) {
    int bp = blockIdx.x;
    int b = bp / PP, p = bp % PP;
    int start = p ? cum[b * PP + p - 1] : 0;
    int end = cum[b * PP + p];
    const float* yb = y + (size_t)b * SS * DD;
    float* orow = patch + (size_t)bp * DD;
    for (int d = threadIdx.x; d < DD; d += 256) {
        float m = -3.402823466e38f;
        for (int s = start; s < end; s++)
            m = fmaxf(m, yb[(size_t)s * DD + d]);
        orow[d] = m;
    }
}

// ---------------- launch ----------------
extern "C" void kernel_launch(void* const* d_in, const int* in_sizes, int n_in,
                              void* d_out, int out_size) {
    const int*   ids      = (const int*)d_in[0];
    const int*   lens     = (const int*)d_in[1];
    const float* tok      = (const float*)d_in[2];
    const float* hsh      = (const float*)d_in[3];
    const float* enc_nw   = (const float*)d_in[4];
    const float* enc_whg  = (const float*)d_in[5];
    const float* enc_wout = (const float*)d_in[6];
    const float* dec_nw   = (const float*)d_in[7];
    const float* dec_whg  = (const float*)d_in[8];
    const float* dec_wout = (const float*)d_in[9];
    const float* fin_nw   = (const float*)d_in[10];
    const float* oproj    = (const float*)d_in[11];
    float*       out      = (float*)d_out;

    float* base = nullptr;
    cudaGetSymbolAddress((void**)&base, g_scratch);
    float*         x     = base + OFF_X;
    float*         y     = base + OFF_Y;
    float2*        ab    = (float2*)(base + OFF_AB);
    __nv_bfloat16* xh    = (__nv_bfloat16*)(base + OFF_XH);
    __nv_bfloat16* xl    = (__nv_bfloat16*)(base + OFF_XL);
    __nv_bfloat16* hh    = (__nv_bfloat16*)(base + OFF_HH);
    __nv_bfloat16* hl    = (__nv_bfloat16*)(base + OFF_HL);
    float*         patch = base + OFF_PAT;
    float2*        carry = (float2*)(base + OFF_CAR);
    float*         hinit = base + OFF_HIN;
    int*           cum   = (int*)(base + OFF_CUM);
    int*           pid   = (int*)(base + OFF_PID);
    __nv_bfloat16* wHGhe = (__nv_bfloat16*)(base + OFF_WHGHE);
    __nv_bfloat16* wHGle = (__nv_bfloat16*)(base + OFF_WHGLE);
    __nv_bfloat16* wOUhe = (__nv_bfloat16*)(base + OFF_WOUHE);
    __nv_bfloat16* wOUle = (__nv_bfloat16*)(base + OFF_WOULE);
    __nv_bfloat16* wHGhd = (__nv_bfloat16*)(base + OFF_WHGHD);
    __nv_bfloat16* wHGld = (__nv_bfloat16*)(base + OFF_WHGLD);
    __nv_bfloat16* wOUhd = (__nv_bfloat16*)(base + OFF_WOUHD);
    __nv_bfloat16* wOUld = (__nv_bfloat16*)(base + OFF_WOULD);
    __nv_bfloat16* wLGh  = (__nv_bfloat16*)(base + OFF_WLGH);
    __nv_bfloat16* wLGl  = (__nv_bfloat16*)(base + OFF_WLGL);

    constexpr int SMEM = 2 * 4 * 128 * 128;  // 131072 bytes
    cudaFuncSetAttribute(k_hgemm<1>, cudaFuncAttributeMaxDynamicSharedMemorySize, SMEM);
    cudaFuncSetAttribute(k_hgemm<2>, cudaFuncAttributeMaxDynamicSharedMemorySize, SMEM);
    cudaFuncSetAttribute(k_hgemm<3>, cudaFuncAttributeMaxDynamicSharedMemorySize, SMEM);

    // weight prep (independent)
    dim3 tb(32, 32);
    k_wprep<<<dim3(1536 / 32, GK / 32), tb>>>(enc_whg, wHGhe, wHGle, 1536, 1, 1536);
    k_wprep<<<dim3(768 / 32, GK / 32), tb>>>(enc_wout, wOUhe, wOUle, 768, 0, 768);
    k_wprep<<<dim3(1536 / 32, GK / 32), tb>>>(dec_whg, wHGhd, wHGld, 1536, 1, 1536);
    k_wprep<<<dim3(768 / 32, GK / 32), tb>>>(dec_wout, wOUhd, wOUld, 768, 0, 768);
    k_wprep<<<dim3(NLOGPAD / 32, GK / 32), tb>>>(oproj, wLGh, wLGl, NBYTE, 0, NBYTE);

    // patch bookkeeping
    k_cum<<<BB, 32>>>(lens, cum);
    k_pid<<<(BS + 255) / 256, 256>>>(cum, pid);

    // embeddings + encoder rmsnorm
    k_embed_rms<<<BS, 256>>>(ids, tok, hsh, enc_nw, x, xh, xl);

    // ---- encoder block ----
    k_hgemm<1><<<dim3(12, 128), 512, SMEM>>>(xh, xl, wHGhe, wHGle, nullptr, (float*)ab);
    k_scan_red<<<CBD / 256, 256>>>(ab, carry);
    k_scan_carry<<<(BB * DD) / 256, 256>>>(carry, hinit);
    k_scan_apply<<<CBD / 256, 256>>>(ab, hinit, hh, hl);
    k_hgemm<2><<<dim3(6, 128), 512, SMEM>>>(hh, hl, wOUhe, wOUle, x, y);

    // ---- patch pooling + decoder input (+ decoder rmsnorm fused) ----
    k_segmax<<<BB * PP, 256>>>(y, cum, patch);
    k_gadd_rms<<<BS, 256>>>(y, patch, pid, dec_nw, x, xh, xl);

    // ---- decoder block ----
    k_hgemm<1><<<dim3(12, 128), 512, SMEM>>>(xh, xl, wHGhd, wHGld, nullptr, (float*)ab);
    k_scan_red<<<CBD / 256, 256>>>(ab, carry);
    k_scan_carry<<<(BB * DD) / 256, 256>>>(carry, hinit);
    k_scan_apply<<<CBD / 256, 256>>>(ab, hinit, hh, hl);
    k_hgemm<2><<<dim3(6, 128), 512, SMEM>>>(hh, hl, wOUhd, wOUld, x, y);

    // ---- final norm + logits ----
    k_rms_b<<<BS, 256>>>(y, fin_nw, xh, xl);
    k_hgemm<3><<<dim3(3, 128), 512, SMEM>>>(xh, xl, wLGh, wLGl, nullptr, out);
}

// round 10
// speedup vs baseline: 2.7555x; 1.0275x over previous
#include <cuda_runtime.h>
#include <cuda_bf16.h>
#include <math.h>
#include <stdint.h>

// ---------------- problem constants ----------------
constexpr int BB = 4;
constexpr int SS = 4096;
constexpr int DD = 768;
constexpr int PP = 683;
constexpr int NBYTE = 260;
constexpr int HASHMASK = 65535;     // HASH_VOCAB = 65536
constexpr int BS  = BB * SS;        // 16384 rows
constexpr int BSD = BS * DD;
constexpr int BPD = BB * PP * DD;
constexpr int CC  = 32;             // scan chunks
constexpr int LL  = SS / CC;        // 128
constexpr int CBD = CC * BB * DD;
constexpr int GK  = 768;            // GEMM K
constexpr int NLOGPAD = 384;        // logits N padded to 3*128

// ---------------- scratch layout (floats) ----------------
constexpr size_t OFF_X    = 0;
constexpr size_t OFF_Y    = OFF_X   + BSD;
constexpr size_t OFF_AB   = OFF_Y   + BSD;          // float2 [BS, DD]
constexpr size_t OFF_XH   = OFF_AB  + 2 * (size_t)BSD;
constexpr size_t OFF_XL   = OFF_XH  + BSD / 2;
constexpr size_t OFF_HH   = OFF_XL  + BSD / 2;
constexpr size_t OFF_HL   = OFF_HH  + BSD / 2;
constexpr size_t OFF_PAT  = OFF_HL  + BSD / 2;
constexpr size_t OFF_CAR  = OFF_PAT + BPD;          // float2 CBD
constexpr size_t OFF_HIN  = OFF_CAR + 2 * (size_t)CBD;
constexpr size_t OFF_CUM  = OFF_HIN + CBD;          // int
constexpr size_t OFF_PID  = OFF_CUM + BB * PP;      // int
constexpr size_t WHG_E    = 1536 * 768 / 2;         // bf16 elems / 2 = floats
constexpr size_t WOUT_E   = 768 * 768 / 2;
constexpr size_t WLOG_E   = (size_t)NLOGPAD * 768 / 2;
constexpr size_t OFF_WHGHE = OFF_PID + BS;
constexpr size_t OFF_WHGLE = OFF_WHGHE + WHG_E;
constexpr size_t OFF_WOUHE = OFF_WHGLE + WHG_E;
constexpr size_t OFF_WOULE = OFF_WOUHE + WOUT_E;
constexpr size_t OFF_WHGHD = OFF_WOULE + WOUT_E;
constexpr size_t OFF_WHGLD = OFF_WHGHD + WHG_E;
constexpr size_t OFF_WOUHD = OFF_WHGLD + WHG_E;
constexpr size_t OFF_WOULD = OFF_WOUHD + WOUT_E;
constexpr size_t OFF_WLGH  = OFF_WOULD + WOUT_E;
constexpr size_t OFF_WLGL  = OFF_WLGH + WLOG_E;
constexpr size_t SCRATCH_FLOATS = OFF_WLGL + WLOG_E + 64;
__device__ float g_scratch[SCRATCH_FLOATS];

// ---------------- PTX helpers (sm_100 baseline only) ----------------
__device__ __forceinline__ uint32_t s2u(const void* p) {
    uint32_t a;
    asm("{ .reg .u64 t; cvta.to.shared.u64 t, %1; cvt.u32.u64 %0, t; }" : "=r"(a) : "l"(p));
    return a;
}
__device__ __forceinline__ void cp16(uint32_t dst, const void* src) {
    asm volatile("cp.async.cg.shared.global [%0], [%1], 16;" :: "r"(dst), "l"(src));
}
__device__ __forceinline__ void cp_commit() { asm volatile("cp.async.commit_group;" ::: "memory"); }
template <int N>
__device__ __forceinline__ void cp_wait() { asm volatile("cp.async.wait_group %0;" :: "n"(N) : "memory"); }

__device__ __forceinline__ void ldsm_x4(uint32_t& r0, uint32_t& r1, uint32_t& r2, uint32_t& r3,
                                        uint32_t addr) {
    asm volatile("ldmatrix.sync.aligned.m8n8.x4.shared.b16 {%0,%1,%2,%3}, [%4];"
                 : "=r"(r0), "=r"(r1), "=r"(r2), "=r"(r3) : "r"(addr));
}
__device__ __forceinline__ void mma16816(float* c, const uint32_t* a, const uint32_t* b) {
    asm volatile(
        "mma.sync.aligned.m16n8k16.row.col.f32.bf16.bf16.f32 "
        "{%0,%1,%2,%3}, {%4,%5,%6,%7}, {%8,%9}, {%0,%1,%2,%3};"
        : "+f"(c[0]), "+f"(c[1]), "+f"(c[2]), "+f"(c[3])
        : "r"(a[0]), "r"(a[1]), "r"(a[2]), "r"(a[3]), "r"(b[0]), "r"(b[1]));
}

__device__ __forceinline__ uint32_t sw128(uint32_t o) { return o ^ ((o >> 3) & 0x70); }

// ---------------- minGRU coefficients ----------------
__device__ __forceinline__ void mingru_coef(float hidden, float gate, float& a, float& bv) {
    float e    = __expf(-fabsf(gate));
    float inv  = 1.f / (1.f + e);
    float sneg = e * inv;
    float spos = inv;
    float z = (gate >= 0.f) ? spos : sneg;
    a       = (gate >= 0.f) ? sneg : spos;
    float g;
    if (hidden >= 0.f) g = hidden + 0.5f;
    else {
        float eh = __expf(hidden);
        g = eh / (1.f + eh);
    }
    bv = z * g;
}

__device__ __forceinline__ void split_bf16(float v, __nv_bfloat16& hi, __nv_bfloat16& lo) {
    hi = __float2bfloat16(v);
    lo = __float2bfloat16(v - __bfloat162float(hi));
}

// ================= HMMA split-bf16 GEMM (3-stage combined-chunk pipeline) =================
// Per k-chunk: stage Ah,Al,Bh,Bl once; issue AhBh + AlBh + AhBl from it.
// 512 threads, 16 warps (4x4), warp tile 32x32 of the 128x128 CTA tile.
// 3 smem stages, ONE syncthreads per iteration; loads issue before compute.
// EPI: 1 = minGRU (a,b) from interleaved (hid,gate) cols -> ab float2 [BS,768]
//      2 = += Res, store fp32 [BS,768]
//      3 = logits, store fp32 [BS,260] col-guarded
template <int EPI>
__global__ void __launch_bounds__(512, 1)
k_hgemm(const __nv_bfloat16* __restrict__ Ah, const __nv_bfloat16* __restrict__ Al,
        const __nv_bfloat16* __restrict__ Bh, const __nv_bfloat16* __restrict__ Bl,
        const float* __restrict__ Res, float* __restrict__ Cout) {
    constexpr int KC = 64;              // bf16 per k-chunk (128 bytes)
    constexpr int NCH = GK / KC;        // 12
    constexpr int MAT = 128 * 128;      // bytes per matrix tile
    constexpr int STAGE = 4 * MAT;      // Ah|Al|Bh|Bl

    extern __shared__ char smem[];
    uint32_t sb = s2u(smem);

    int tid = threadIdx.x;
    int lane = tid & 31, wid = tid >> 5;
    int wm = wid >> 2, wn = wid & 3;    // warp tile: rows wm*32, cols wn*32
    int m0 = blockIdx.y * 128, n0 = blockIdx.x * 128;

    auto load_stage = [&](int kc) {
        uint32_t st = sb + (kc % 3) * STAGE;
        const __nv_bfloat16* ah = Ah + (size_t)m0 * GK + kc * KC;
        const __nv_bfloat16* al = Al + (size_t)m0 * GK + kc * KC;
        const __nv_bfloat16* bh = Bh + (size_t)n0 * GK + kc * KC;
        const __nv_bfloat16* bl = Bl + (size_t)n0 * GK + kc * KC;
#pragma unroll
        for (int i = 0; i < 2; i++) {          // 128 rows * 8 segs / 512 threads
            int idx = tid + i * 512;
            int r = idx >> 3, sg = idx & 7;
            uint32_t so = sw128(r * 128 + sg * 16);
            size_t go = (size_t)r * GK + sg * 8;
            cp16(st + 0 * MAT + so, ah + go);
            cp16(st + 1 * MAT + so, al + go);
            cp16(st + 2 * MAT + so, bh + go);
            cp16(st + 3 * MAT + so, bl + go);
        }
    };

    float acc[2][4][4];
#pragma unroll
    for (int i = 0; i < 2; i++)
#pragma unroll
        for (int j = 0; j < 4; j++)
#pragma unroll
            for (int q = 0; q < 4; q++) acc[i][j][q] = 0.f;

    int aRow = (lane & 15);
    int aSel = (lane >> 4);
    int bTile = (lane >> 4);            // which j-tile within a pair
    int bSel = ((lane >> 3) & 1);       // k16-half
    int bRow = (lane & 7);

    load_stage(0); cp_commit();
    load_stage(1); cp_commit();

    for (int it = 0; it < NCH; it++) {
        cp_wait<1>();
        __syncthreads();
        if (it + 2 < NCH) load_stage(it + 2);
        cp_commit();

        uint32_t st = sb + (it % 3) * STAGE;
#pragma unroll
        for (int kk = 0; kk < 4; kk++) {
            uint32_t afh[2][4], afl[2][4], bfh[4][2], bfl[4][2];
#pragma unroll
            for (int i = 0; i < 2; i++) {
                int row = wm * 32 + i * 16 + aRow;
                int chunk = (kk * 2 + aSel) ^ (row & 7);
                uint32_t off = row * 128 + chunk * 16;
                ldsm_x4(afh[i][0], afh[i][1], afh[i][2], afh[i][3], st + 0 * MAT + off);
                ldsm_x4(afl[i][0], afl[i][1], afl[i][2], afl[i][3], st + 1 * MAT + off);
            }
#pragma unroll
            for (int jp = 0; jp < 2; jp++) {
                int row = wn * 32 + jp * 16 + bTile * 8 + bRow;
                int chunk = (kk * 2 + bSel) ^ (row & 7);
                uint32_t off = row * 128 + chunk * 16;
                ldsm_x4(bfh[jp * 2][0], bfh[jp * 2][1], bfh[jp * 2 + 1][0], bfh[jp * 2 + 1][1],
                        st + 2 * MAT + off);
                ldsm_x4(bfl[jp * 2][0], bfl[jp * 2][1], bfl[jp * 2 + 1][0], bfl[jp * 2 + 1][1],
                        st + 3 * MAT + off);
            }
#pragma unroll
            for (int i = 0; i < 2; i++)
#pragma unroll
                for (int j = 0; j < 4; j++) {
                    mma16816(acc[i][j], afh[i], bfh[j]);
                    mma16816(acc[i][j], afl[i], bfh[j]);
                    mma16816(acc[i][j], afh[i], bfl[j]);
                }
        }
    }

    // ---------------- epilogue ----------------
    int cRow = lane >> 2;            // 0..7
    int cCol = (lane & 3) * 2;       // even
#pragma unroll
    for (int i = 0; i < 2; i++) {
#pragma unroll
        for (int j = 0; j < 4; j++) {
            int r0 = m0 + wm * 32 + i * 16 + cRow;
            int r1 = r0 + 8;
            int col = n0 + wn * 32 + j * 8 + cCol;
            float c0 = acc[i][j][0], c1 = acc[i][j][1];
            float c2 = acc[i][j][2], c3 = acc[i][j][3];
            if (EPI == 1) {
                float2* ab = (float2*)Cout;
                int d = col >> 1;
                float a, bv;
                mingru_coef(c0, c1, a, bv);
                ab[(size_t)r0 * DD + d] = make_float2(a, bv);
                mingru_coef(c2, c3, a, bv);
                ab[(size_t)r1 * DD + d] = make_float2(a, bv);
            } else if (EPI == 2) {
                const float2* rr0 = (const float2*)(Res + (size_t)r0 * DD + col);
                const float2* rr1 = (const float2*)(Res + (size_t)r1 * DD + col);
                float2 v0 = rr0[0], v1 = rr1[0];
                *(float2*)(Cout + (size_t)r0 * DD + col) = make_float2(c0 + v0.x, c1 + v0.y);
                *(float2*)(Cout + (size_t)r1 * DD + col) = make_float2(c2 + v1.x, c3 + v1.y);
            } else {
                if (col < NBYTE) {
                    Cout[(size_t)r0 * NBYTE + col] = c0;
                    Cout[(size_t)r1 * NBYTE + col] = c2;
                }
                if (col + 1 < NBYTE) {
                    Cout[(size_t)r0 * NBYTE + col + 1] = c1;
                    Cout[(size_t)r1 * NBYTE + col + 1] = c3;
                }
            }
        }
    }
}

// ---------------- weight prep: [K,N] fp32 -> transposed [Npad,K] bf16 hi/lo ----------------
__global__ void k_wprep(const float* __restrict__ W, __nv_bfloat16* __restrict__ Wh,
                        __nv_bfloat16* __restrict__ Wl, int N, int mode, int nvalid) {
    __shared__ float tile[32][33];
    int n0 = blockIdx.x * 32, k0 = blockIdx.y * 32;
    int tx = threadIdx.x, ty = threadIdx.y;
    int n = n0 + tx;
    float v = 0.f;
    if (n < nvalid) {
        int src = (mode == 1) ? ((n & 1) ? (N >> 1) + (n >> 1) : (n >> 1)) : n;
        v = W[(size_t)(k0 + ty) * N + src];
    }
    tile[ty][tx] = v;
    __syncthreads();
    int on = n0 + ty, ok = k0 + tx;
    float w = tile[tx][ty];
    __nv_bfloat16 hi, lo;
    split_bf16(w, hi, lo);
    Wh[(size_t)on * GK + ok] = hi;
    Wl[(size_t)on * GK + ok] = lo;
}

// ---------------- embed + rmsnorm fused ----------------
__global__ void k_embed_rms(const int* __restrict__ ids, const float* __restrict__ tok,
                            const float* __restrict__ hsh, const float* __restrict__ nw,
                            float* __restrict__ x, __nv_bfloat16* __restrict__ xh,
                            __nv_bfloat16* __restrict__ xl) {
    int bs = blockIdx.x;
    int s = bs & (SS - 1);
    int t0 = ids[bs];
    int acc = t0, p = 31;
#pragma unroll
    for (int j = 1; j < 4; j++) {
        if (s >= j) acc += ids[bs - j] * p;
        p *= 31;
    }
    int hid = acc & HASHMASK;
    const float* tr = tok + (size_t)t0 * DD;
    const float* hr = hsh + (size_t)hid * DD;
    float vals[3];
    float ss = 0.f;
#pragma unroll
    for (int i = 0; i < 3; i++) {
        int d = threadIdx.x + i * 256;
        float v = tr[d] + hr[d];
        vals[i] = v;
        ss += v * v;
    }
    __shared__ float red[8];
#pragma unroll
    for (int o = 16; o > 0; o >>= 1) ss += __shfl_xor_sync(~0u, ss, o);
    if ((threadIdx.x & 31) == 0) red[threadIdx.x >> 5] = ss;
    __syncthreads();
    if (threadIdx.x == 0) {
        float v = 0.f;
#pragma unroll
        for (int i = 0; i < 8; i++) v += red[i];
        red[0] = rsqrtf(v / DD + 1e-6f);
    }
    __syncthreads();
    float r = red[0];
    size_t rb = (size_t)bs * DD;
#pragma unroll
    for (int i = 0; i < 3; i++) {
        int d = threadIdx.x + i * 256;
        x[rb + d] = vals[i];
        float v = vals[i] * r * nw[d];
        __nv_bfloat16 hi, lo;
        split_bf16(v, hi, lo);
        xh[rb + d] = hi;
        xl[rb + d] = lo;
    }
}

// ---------------- gadd + rmsnorm fused ----------------
__global__ void k_gadd_rms(const float* __restrict__ y, const float* __restrict__ patch,
                           const int* __restrict__ pid, const float* __restrict__ nw,
                           float* __restrict__ x, __nv_bfloat16* __restrict__ xh,
                           __nv_bfloat16* __restrict__ xl) {
    int bs = blockIdx.x;
    int b = bs / SS;
    const float* pr = patch + (size_t)(b * PP + pid[bs]) * DD;
    const float* yr = y + (size_t)bs * DD;
    float vals[3];
    float ss = 0.f;
#pragma unroll
    for (int i = 0; i < 3; i++) {
        int d = threadIdx.x + i * 256;
        float v = yr[d] + pr[d];
        vals[i] = v;
        ss += v * v;
    }
    __shared__ float red[8];
#pragma unroll
    for (int o = 16; o > 0; o >>= 1) ss += __shfl_xor_sync(~0u, ss, o);
    if ((threadIdx.x & 31) == 0) red[threadIdx.x >> 5] = ss;
    __syncthreads();
    if (threadIdx.x == 0) {
        float v = 0.f;
#pragma unroll
        for (int i = 0; i < 8; i++) v += red[i];
        red[0] = rsqrtf(v / DD + 1e-6f);
    }
    __syncthreads();
    float r = red[0];
    size_t rb = (size_t)bs * DD;
#pragma unroll
    for (int i = 0; i < 3; i++) {
        int d = threadIdx.x + i * 256;
        x[rb + d] = vals[i];
        float v = vals[i] * r * nw[d];
        __nv_bfloat16 hi, lo;
        split_bf16(v, hi, lo);
        xh[rb + d] = hi;
        xl[rb + d] = lo;
    }
}

// ---------------- final rmsnorm (bf16 hi/lo only) ----------------
__global__ void k_rms_b(const float* __restrict__ y, const float* __restrict__ nw,
                        __nv_bfloat16* __restrict__ xh, __nv_bfloat16* __restrict__ xl) {
    int bs = blockIdx.x;
    const float* yr = y + (size_t)bs * DD;
    float vals[3];
    float ss = 0.f;
#pragma unroll
    for (int i = 0; i < 3; i++) {
        int d = threadIdx.x + i * 256;
        float v = yr[d];
        vals[i] = v;
        ss += v * v;
    }
    __shared__ float red[8];
#pragma unroll
    for (int o = 16; o > 0; o >>= 1) ss += __shfl_xor_sync(~0u, ss, o);
    if ((threadIdx.x & 31) == 0) red[threadIdx.x >> 5] = ss;
    __syncthreads();
    if (threadIdx.x == 0) {
        float v = 0.f;
#pragma unroll
        for (int i = 0; i < 8; i++) v += red[i];
        red[0] = rsqrtf(v / DD + 1e-6f);
    }
    __syncthreads();
    float r = red[0];
    size_t rb = (size_t)bs * DD;
#pragma unroll
    for (int i = 0; i < 3; i++) {
        int d = threadIdx.x + i * 256;
        float v = vals[i] * r * nw[d];
        __nv_bfloat16 hi, lo;
        split_bf16(v, hi, lo);
        xh[rb + d] = hi;
        xl[rb + d] = lo;
    }
}

// ---------------- minGRU scan over precomputed (a,b) ----------------
__global__ void k_scan_red(const float2* __restrict__ ab, float2* __restrict__ carry) {
    int idx = blockIdx.x * 256 + threadIdx.x;
    int d = idx % DD;
    int bc = idx / DD;
    int b = bc % BB;
    int c = bc / BB;
    const float2* base = ab + (size_t)(b * SS + c * LL) * DD + d;
    float A = 1.f, Bv = 0.f;
#pragma unroll 4
    for (int t = 0; t < LL; t++) {
        float2 v = *base;
        base += DD;
        A *= v.x;
        Bv = fmaf(v.x, Bv, v.y);
    }
    carry[idx] = make_float2(A, Bv);
}

__global__ void k_scan_carry(const float2* __restrict__ carry, float* __restrict__ hinit) {
    int ch = blockIdx.x * 256 + threadIdx.x;
    int d = ch % DD;
    int b = ch / DD;
    float h = 0.f;
#pragma unroll
    for (int c = 0; c < CC; c++) {
        int i = (c * BB + b) * DD + d;
        hinit[i] = h;
        float2 abv = carry[i];
        h = fmaf(abv.x, h, abv.y);
    }
}

__global__ void k_scan_apply(const float2* __restrict__ ab, const float* __restrict__ hinit,
                             __nv_bfloat16* __restrict__ hh, __nv_bfloat16* __restrict__ hl) {
    int idx = blockIdx.x * 256 + threadIdx.x;
    int d = idx % DD;
    int bc = idx / DD;
    int b = bc % BB;
    int c = bc / BB;
    size_t off = (size_t)(b * SS + c * LL) * DD + d;
    const float2* base = ab + off;
    float h = hinit[idx];
#pragma unroll 4
    for (int t = 0; t < LL; t++) {
        float2 v = *base;
        base += DD;
        h = fmaf(v.x, h, v.y);
        __nv_bfloat16 hi, lo;
        split_bf16(h, hi, lo);
        hh[off] = hi;
        hl[off] = lo;
        off += DD;
    }
}

// ---------------- patch bookkeeping ----------------
__global__ void k_cum(const int* __restrict__ lens, int* __restrict__ cum) {
    int b = blockIdx.x;
    if (threadIdx.x == 0) {
        int s = 0;
        for (int p = 0; p < PP; p++) {
            s += lens[b * PP + p];
            cum[b * PP + p] = s;
        }
    }
}

__global__ void k_pid(const int* __restrict__ cum, int* __restrict__ pid) {
    int i = blockIdx.x * 256 + threadIdx.x;
    if (i >= BS) return;
    int b = i / SS;
    int pos = i % SS;
    const int* c = cum + b * PP;
    int lo = 0, hi = PP;
    while (lo < hi) {
        int mid = (lo + hi) >> 1;
        if (c[mid] <= pos) lo = mid + 1;
        else hi = mid;
    }
    pid[i] = lo;
}

__global__ void k_segmax(const float* __restrict__ y, const int* __restrict__ cum,
                         float* __restrict__ patch) {
    int bp = blockIdx.x;
    int b = bp / PP, p = bp % PP;
    int start = p ? cum[b * PP + p - 1] : 0;
    int end = cum[b * PP + p];
    const float* yb = y + (size_t)b * SS * DD;
    float* orow = patch + (size_t)bp * DD;
    for (int d = threadIdx.x; d < DD; d += 256) {
        float m = -3.402823466e38f;
        for (int s = start; s < end; s++)
            m = fmaxf(m, yb[(size_t)s * DD + d]);
        orow[d] = m;
    }
}

// ---------------- launch ----------------
extern "C" void kernel_launch(void* const* d_in, const int* in_sizes, int n_in,
                              void* d_out, int out_size) {
    const int*   ids      = (const int*)d_in[0];
    const int*   lens     = (const int*)d_in[1];
    const float* tok      = (const float*)d_in[2];
    const float* hsh      = (const float*)d_in[3];
    const float* enc_nw   = (const float*)d_in[4];
    const float* enc_whg  = (const float*)d_in[5];
    const float* enc_wout = (const float*)d_in[6];
    const float* dec_nw   = (const float*)d_in[7];
    const float* dec_whg  = (const float*)d_in[8];
    const float* dec_wout = (const float*)d_in[9];
    const float* fin_nw   = (const float*)d_in[10];
    const float* oproj    = (const float*)d_in[11];
    float*       out      = (float*)d_out;

    float* base = nullptr;
    cudaGetSymbolAddress((void**)&base, g_scratch);
    float*         x     = base + OFF_X;
    float*         y     = base + OFF_Y;
    float2*        ab    = (float2*)(base + OFF_AB);
    __nv_bfloat16* xh    = (__nv_bfloat16*)(base + OFF_XH);
    __nv_bfloat16* xl    = (__nv_bfloat16*)(base + OFF_XL);
    __nv_bfloat16* hh    = (__nv_bfloat16*)(base + OFF_HH);
    __nv_bfloat16* hl    = (__nv_bfloat16*)(base + OFF_HL);
    float*         patch = base + OFF_PAT;
    float2*        carry = (float2*)(base + OFF_CAR);
    float*         hinit = base + OFF_HIN;
    int*           cum   = (int*)(base + OFF_CUM);
    int*           pid   = (int*)(base + OFF_PID);
    __nv_bfloat16* wHGhe = (__nv_bfloat16*)(base + OFF_WHGHE);
    __nv_bfloat16* wHGle = (__nv_bfloat16*)(base + OFF_WHGLE);
    __nv_bfloat16* wOUhe = (__nv_bfloat16*)(base + OFF_WOUHE);
    __nv_bfloat16* wOUle = (__nv_bfloat16*)(base + OFF_WOULE);
    __nv_bfloat16* wHGhd = (__nv_bfloat16*)(base + OFF_WHGHD);
    __nv_bfloat16* wHGld = (__nv_bfloat16*)(base + OFF_WHGLD);
    __nv_bfloat16* wOUhd = (__nv_bfloat16*)(base + OFF_WOUHD);
    __nv_bfloat16* wOUld = (__nv_bfloat16*)(base + OFF_WOULD);
    __nv_bfloat16* wLGh  = (__nv_bfloat16*)(base + OFF_WLGH);
    __nv_bfloat16* wLGl  = (__nv_bfloat16*)(base + OFF_WLGL);

    constexpr int SMEM = 3 * 4 * 128 * 128;  // 196608 bytes (3 stages)
    cudaFuncSetAttribute(k_hgemm<1>, cudaFuncAttributeMaxDynamicSharedMemorySize, SMEM);
    cudaFuncSetAttribute(k_hgemm<2>, cudaFuncAttributeMaxDynamicSharedMemorySize, SMEM);
    cudaFuncSetAttribute(k_hgemm<3>, cudaFuncAttributeMaxDynamicSharedMemorySize, SMEM);

    dim3 tb(32, 32);
    // launches 0..4 (so launch #5 = first GEMM for ncu -s 5 -c 1)
    k_cum<<<BB, 32>>>(lens, cum);
    k_pid<<<(BS + 255) / 256, 256>>>(cum, pid);
    k_embed_rms<<<BS, 256>>>(ids, tok, hsh, enc_nw, x, xh, xl);
    k_wprep<<<dim3(1536 / 32, GK / 32), tb>>>(enc_whg, wHGhe, wHGle, 1536, 1, 1536);
    k_wprep<<<dim3(768 / 32, GK / 32), tb>>>(enc_wout, wOUhe, wOUle, 768, 0, 768);

    // ---- encoder block ----  (launch #5 = k_hgemm<1>)
    k_hgemm<1><<<dim3(12, 128), 512, SMEM>>>(xh, xl, wHGhe, wHGle, nullptr, (float*)ab);
    k_scan_red<<<CBD / 256, 256>>>(ab, carry);
    k_scan_carry<<<(BB * DD) / 256, 256>>>(carry, hinit);
    k_scan_apply<<<CBD / 256, 256>>>(ab, hinit, hh, hl);
    k_hgemm<2><<<dim3(6, 128), 512, SMEM>>>(hh, hl, wOUhe, wOUle, x, y);

    // remaining weight preps (needed later)
    k_wprep<<<dim3(1536 / 32, GK / 32), tb>>>(dec_whg, wHGhd, wHGld, 1536, 1, 1536);
    k_wprep<<<dim3(768 / 32, GK / 32), tb>>>(dec_wout, wOUhd, wOUld, 768, 0, 768);
    k_wprep<<<dim3(NLOGPAD / 32, GK / 32), tb>>>(oproj, wLGh, wLGl, NBYTE, 0, NBYTE);

    // ---- patch pooling + decoder input (+ decoder rmsnorm fused) ----
    k_segmax<<<BB * PP, 256>>>(y, cum, patch);
    k_gadd_rms<<<BS, 256>>>(y, patch, pid, dec_nw, x, xh, xl);

    // ---- decoder block ----
    k_hgemm<1><<<dim3(12, 128), 512, SMEM>>>(xh, xl, wHGhd, wHGld, nullptr, (float*)ab);
    k_scan_red<<<CBD / 256, 256>>>(ab, carry);
    k_scan_carry<<<(BB * DD) / 256, 256>>>(carry, hinit);
    k_scan_apply<<<CBD / 256, 256>>>(ab, hinit, hh, hl);
    k_hgemm<2><<<dim3(6, 128), 512, SMEM>>>(hh, hl, wOUhd, wOUld, x, y);

    // ---- final norm + logits ----
    k_rms_b<<<BS, 256>>>(y, fin_nw, xh, xl);
    k_hgemm<3><<<dim3(3, 128), 512, SMEM>>>(xh, xl, wLGh, wLGl, nullptr, out);
}

// round 11
// speedup vs baseline: 3.0462x; 1.1055x over previous
#include <cuda_runtime.h>
#include <cuda_bf16.h>
#include <math.h>
#include <stdint.h>

// ---------------- problem constants ----------------
constexpr int BB = 4;
constexpr int SS = 4096;
constexpr int DD = 768;
constexpr int PP = 683;
constexpr int NBYTE = 260;
constexpr int HASHMASK = 65535;     // HASH_VOCAB = 65536
constexpr int BS  = BB * SS;        // 16384 rows
constexpr int BSD = BS * DD;
constexpr int BPD = BB * PP * DD;
constexpr int CC  = 32;             // scan chunks
constexpr int LL  = SS / CC;        // 128
constexpr int CBD = CC * BB * DD;
constexpr int GK  = 768;            // GEMM K
constexpr int NLOGPAD = 384;        // logits N padded

// ---------------- scratch layout (floats) ----------------
constexpr size_t OFF_X    = 0;
constexpr size_t OFF_Y    = OFF_X   + BSD;
constexpr size_t OFF_AB   = OFF_Y   + BSD;          // float2 [BS, DD]
constexpr size_t OFF_XH   = OFF_AB  + 2 * (size_t)BSD;
constexpr size_t OFF_XL   = OFF_XH  + BSD / 2;
constexpr size_t OFF_HH   = OFF_XL  + BSD / 2;
constexpr size_t OFF_HL   = OFF_HH  + BSD / 2;
constexpr size_t OFF_PAT  = OFF_HL  + BSD / 2;
constexpr size_t OFF_CAR  = OFF_PAT + BPD;          // float2 CBD
constexpr size_t OFF_HIN  = OFF_CAR + 2 * (size_t)CBD;
constexpr size_t OFF_CUM  = OFF_HIN + CBD;          // int
constexpr size_t OFF_PID  = OFF_CUM + BB * PP;      // int
constexpr size_t WHG_E    = 1536 * 768 / 2;         // bf16 elems / 2 = floats
constexpr size_t WOUT_E   = 768 * 768 / 2;
constexpr size_t WLOG_E   = (size_t)NLOGPAD * 768 / 2;
constexpr size_t OFF_WHGHE = OFF_PID + BS;
constexpr size_t OFF_WHGLE = OFF_WHGHE + WHG_E;
constexpr size_t OFF_WOUHE = OFF_WHGLE + WHG_E;
constexpr size_t OFF_WOULE = OFF_WOUHE + WOUT_E;
constexpr size_t OFF_WHGHD = OFF_WOULE + WOUT_E;
constexpr size_t OFF_WHGLD = OFF_WHGHD + WHG_E;
constexpr size_t OFF_WOUHD = OFF_WHGLD + WHG_E;
constexpr size_t OFF_WOULD = OFF_WOUHD + WOUT_E;
constexpr size_t OFF_WLGH  = OFF_WOULD + WOUT_E;
constexpr size_t OFF_WLGL  = OFF_WLGH + WLOG_E;
constexpr size_t SCRATCH_FLOATS = OFF_WLGL + WLOG_E + 64;
__device__ float g_scratch[SCRATCH_FLOATS];

// ---------------- PTX helpers (sm_100 baseline only) ----------------
__device__ __forceinline__ uint32_t s2u(const void* p) {
    uint32_t a;
    asm("{ .reg .u64 t; cvta.to.shared.u64 t, %1; cvt.u32.u64 %0, t; }" : "=r"(a) : "l"(p));
    return a;
}
__device__ __forceinline__ void cp16(uint32_t dst, const void* src) {
    asm volatile("cp.async.cg.shared.global [%0], [%1], 16;" :: "r"(dst), "l"(src));
}
__device__ __forceinline__ void cp_commit() { asm volatile("cp.async.commit_group;" ::: "memory"); }
template <int N>
__device__ __forceinline__ void cp_wait() { asm volatile("cp.async.wait_group %0;" :: "n"(N) : "memory"); }

__device__ __forceinline__ void ldsm_x4(uint32_t& r0, uint32_t& r1, uint32_t& r2, uint32_t& r3,
                                        uint32_t addr) {
    asm volatile("ldmatrix.sync.aligned.m8n8.x4.shared.b16 {%0,%1,%2,%3}, [%4];"
                 : "=r"(r0), "=r"(r1), "=r"(r2), "=r"(r3) : "r"(addr));
}
__device__ __forceinline__ void mma16816(float* c, const uint32_t* a, const uint32_t* b) {
    asm volatile(
        "mma.sync.aligned.m16n8k16.row.col.f32.bf16.bf16.f32 "
        "{%0,%1,%2,%3}, {%4,%5,%6,%7}, {%8,%9}, {%0,%1,%2,%3};"
        : "+f"(c[0]), "+f"(c[1]), "+f"(c[2]), "+f"(c[3])
        : "r"(a[0]), "r"(a[1]), "r"(a[2]), "r"(a[3]), "r"(b[0]), "r"(b[1]));
}

__device__ __forceinline__ uint32_t sw128(uint32_t o) { return o ^ ((o >> 3) & 0x70); }

// ---------------- minGRU coefficients ----------------
__device__ __forceinline__ void mingru_coef(float hidden, float gate, float& a, float& bv) {
    float e    = __expf(-fabsf(gate));
    float inv  = 1.f / (1.f + e);
    float sneg = e * inv;
    float spos = inv;
    float z = (gate >= 0.f) ? spos : sneg;
    a       = (gate >= 0.f) ? sneg : spos;
    float g;
    if (hidden >= 0.f) g = hidden + 0.5f;
    else {
        float eh = __expf(hidden);
        g = eh / (1.f + eh);
    }
    bv = z * g;
}

__device__ __forceinline__ void split_bf16(float v, __nv_bfloat16& hi, __nv_bfloat16& lo) {
    hi = __float2bfloat16(v);
    lo = __float2bfloat16(v - __bfloat162float(hi));
}

// ================= HMMA split-bf16 GEMM (128x64 tile, 2 CTAs/SM) =================
// Per k-chunk: stage Ah,Al,Bh,Bl once; issue AhBh + AlBh + AhBl from it.
// 256 threads, 8 warps (4x2), warp tile 32x32 of the 128x64 CTA tile.
// 2 smem stages (48KB each -> 96KB/CTA -> 2 CTAs/SM for cross-CTA overlap
// of prologue/epilogue/barriers).
// EPI: 1 = minGRU (a,b) from interleaved (hid,gate) cols -> ab float2 [BS,768]
//      2 = += Res, store fp32 [BS,768]
//      3 = logits, store fp32 [BS,260] col-guarded
template <int EPI>
__global__ void __launch_bounds__(256, 2)
k_hgemm(const __nv_bfloat16* __restrict__ Ah, const __nv_bfloat16* __restrict__ Al,
        const __nv_bfloat16* __restrict__ Bh, const __nv_bfloat16* __restrict__ Bl,
        const float* __restrict__ Res, float* __restrict__ Cout) {
    constexpr int KC = 64;               // bf16 per k-chunk (128 bytes)
    constexpr int NCH = GK / KC;         // 12
    constexpr int MAT_A = 128 * 128;     // 16 KB
    constexpr int MAT_B = 64 * 128;      // 8 KB
    constexpr int OFF_AH = 0;
    constexpr int OFF_AL = MAT_A;
    constexpr int OFF_BH = 2 * MAT_A;
    constexpr int OFF_BL = 2 * MAT_A + MAT_B;
    constexpr int STAGE  = 2 * MAT_A + 2 * MAT_B;   // 49152

    extern __shared__ char smem[];
    uint32_t sb = s2u(smem);

    int tid = threadIdx.x;
    int lane = tid & 31, wid = tid >> 5;
    int wm = wid >> 1, wn = wid & 1;     // warp tile: rows wm*32, cols wn*32
    int m0 = blockIdx.y * 128, n0 = blockIdx.x * 64;

    auto load_stage = [&](int kc) {
        uint32_t st = sb + (kc & 1) * STAGE;
        const __nv_bfloat16* ah = Ah + (size_t)m0 * GK + kc * KC;
        const __nv_bfloat16* al = Al + (size_t)m0 * GK + kc * KC;
        const __nv_bfloat16* bh = Bh + (size_t)n0 * GK + kc * KC;
        const __nv_bfloat16* bl = Bl + (size_t)n0 * GK + kc * KC;
#pragma unroll
        for (int i = 0; i < 4; i++) {          // A: 128 rows * 8 segs / 256 thr
            int idx = tid + i * 256;
            int r = idx >> 3, sg = idx & 7;
            uint32_t so = sw128(r * 128 + sg * 16);
            size_t go = (size_t)r * GK + sg * 8;
            cp16(st + OFF_AH + so, ah + go);
            cp16(st + OFF_AL + so, al + go);
        }
#pragma unroll
        for (int i = 0; i < 2; i++) {          // B: 64 rows * 8 segs / 256 thr
            int idx = tid + i * 256;
            int r = idx >> 3, sg = idx & 7;
            uint32_t so = sw128(r * 128 + sg * 16);
            size_t go = (size_t)r * GK + sg * 8;
            cp16(st + OFF_BH + so, bh + go);
            cp16(st + OFF_BL + so, bl + go);
        }
    };

    float acc[2][4][4];
#pragma unroll
    for (int i = 0; i < 2; i++)
#pragma unroll
        for (int j = 0; j < 4; j++)
#pragma unroll
            for (int q = 0; q < 4; q++) acc[i][j][q] = 0.f;

    int aRow = (lane & 15);
    int aSel = (lane >> 4);
    int bTile = (lane >> 4);            // which j-tile within a pair
    int bSel = ((lane >> 3) & 1);       // k16-half
    int bRow = (lane & 7);

    load_stage(0); cp_commit();
    load_stage(1); cp_commit();

    for (int it = 0; it < NCH; it++) {
        cp_wait<1>();
        __syncthreads();

        uint32_t st = sb + (it & 1) * STAGE;
#pragma unroll
        for (int kk = 0; kk < 4; kk++) {
            uint32_t afh[2][4], afl[2][4], bfh[4][2], bfl[4][2];
#pragma unroll
            for (int i = 0; i < 2; i++) {
                int row = wm * 32 + i * 16 + aRow;
                int chunk = (kk * 2 + aSel) ^ (row & 7);
                uint32_t off = row * 128 + chunk * 16;
                ldsm_x4(afh[i][0], afh[i][1], afh[i][2], afh[i][3], st + OFF_AH + off);
                ldsm_x4(afl[i][0], afl[i][1], afl[i][2], afl[i][3], st + OFF_AL + off);
            }
#pragma unroll
            for (int jp = 0; jp < 2; jp++) {
                int row = wn * 32 + jp * 16 + bTile * 8 + bRow;
                int chunk = (kk * 2 + bSel) ^ (row & 7);
                uint32_t off = row * 128 + chunk * 16;
                ldsm_x4(bfh[jp * 2][0], bfh[jp * 2][1], bfh[jp * 2 + 1][0], bfh[jp * 2 + 1][1],
                        st + OFF_BH + off);
                ldsm_x4(bfl[jp * 2][0], bfl[jp * 2][1], bfl[jp * 2 + 1][0], bfl[jp * 2 + 1][1],
                        st + OFF_BL + off);
            }
#pragma unroll
            for (int i = 0; i < 2; i++)
#pragma unroll
                for (int j = 0; j < 4; j++) {
                    mma16816(acc[i][j], afh[i], bfh[j]);
                    mma16816(acc[i][j], afl[i], bfh[j]);
                    mma16816(acc[i][j], afh[i], bfl[j]);
                }
        }
        __syncthreads();
        if (it + 2 < NCH) load_stage(it + 2);
        cp_commit();
    }

    // ---------------- epilogue ----------------
    int cRow = lane >> 2;            // 0..7
    int cCol = (lane & 3) * 2;       // even
#pragma unroll
    for (int i = 0; i < 2; i++) {
#pragma unroll
        for (int j = 0; j < 4; j++) {
            int r0 = m0 + wm * 32 + i * 16 + cRow;
            int r1 = r0 + 8;
            int col = n0 + wn * 32 + j * 8 + cCol;
            float c0 = acc[i][j][0], c1 = acc[i][j][1];
            float c2 = acc[i][j][2], c3 = acc[i][j][3];
            if (EPI == 1) {
                float2* ab = (float2*)Cout;
                int d = col >> 1;
                float a, bv;
                mingru_coef(c0, c1, a, bv);
                ab[(size_t)r0 * DD + d] = make_float2(a, bv);
                mingru_coef(c2, c3, a, bv);
                ab[(size_t)r1 * DD + d] = make_float2(a, bv);
            } else if (EPI == 2) {
                const float2* rr0 = (const float2*)(Res + (size_t)r0 * DD + col);
                const float2* rr1 = (const float2*)(Res + (size_t)r1 * DD + col);
                float2 v0 = rr0[0], v1 = rr1[0];
                *(float2*)(Cout + (size_t)r0 * DD + col) = make_float2(c0 + v0.x, c1 + v0.y);
                *(float2*)(Cout + (size_t)r1 * DD + col) = make_float2(c2 + v1.x, c3 + v1.y);
            } else {
                if (col < NBYTE) {
                    Cout[(size_t)r0 * NBYTE + col] = c0;
                    Cout[(size_t)r1 * NBYTE + col] = c2;
                }
                if (col + 1 < NBYTE) {
                    Cout[(size_t)r0 * NBYTE + col + 1] = c1;
                    Cout[(size_t)r1 * NBYTE + col + 1] = c3;
                }
            }
        }
    }
}

// ---------------- weight prep: [K,N] fp32 -> transposed [Npad,K] bf16 hi/lo ----------------
__global__ void k_wprep(const float* __restrict__ W, __nv_bfloat16* __restrict__ Wh,
                        __nv_bfloat16* __restrict__ Wl, int N, int mode, int nvalid) {
    __shared__ float tile[32][33];
    int n0 = blockIdx.x * 32, k0 = blockIdx.y * 32;
    int tx = threadIdx.x, ty = threadIdx.y;
    int n = n0 + tx;
    float v = 0.f;
    if (n < nvalid) {
        int src = (mode == 1) ? ((n & 1) ? (N >> 1) + (n >> 1) : (n >> 1)) : n;
        v = W[(size_t)(k0 + ty) * N + src];
    }
    tile[ty][tx] = v;
    __syncthreads();
    int on = n0 + ty, ok = k0 + tx;
    float w = tile[tx][ty];
    __nv_bfloat16 hi, lo;
    split_bf16(w, hi, lo);
    Wh[(size_t)on * GK + ok] = hi;
    Wl[(size_t)on * GK + ok] = lo;
}

// ---------------- embed + rmsnorm fused ----------------
__global__ void k_embed_rms(const int* __restrict__ ids, const float* __restrict__ tok,
                            const float* __restrict__ hsh, const float* __restrict__ nw,
                            float* __restrict__ x, __nv_bfloat16* __restrict__ xh,
                            __nv_bfloat16* __restrict__ xl) {
    int bs = blockIdx.x;
    int s = bs & (SS - 1);
    int t0 = ids[bs];
    int acc = t0, p = 31;
#pragma unroll
    for (int j = 1; j < 4; j++) {
        if (s >= j) acc += ids[bs - j] * p;
        p *= 31;
    }
    int hid = acc & HASHMASK;
    const float* tr = tok + (size_t)t0 * DD;
    const float* hr = hsh + (size_t)hid * DD;
    float vals[3];
    float ss = 0.f;
#pragma unroll
    for (int i = 0; i < 3; i++) {
        int d = threadIdx.x + i * 256;
        float v = tr[d] + hr[d];
        vals[i] = v;
        ss += v * v;
    }
    __shared__ float red[8];
#pragma unroll
    for (int o = 16; o > 0; o >>= 1) ss += __shfl_xor_sync(~0u, ss, o);
    if ((threadIdx.x & 31) == 0) red[threadIdx.x >> 5] = ss;
    __syncthreads();
    if (threadIdx.x == 0) {
        float v = 0.f;
#pragma unroll
        for (int i = 0; i < 8; i++) v += red[i];
        red[0] = rsqrtf(v / DD + 1e-6f);
    }
    __syncthreads();
    float r = red[0];
    size_t rb = (size_t)bs * DD;
#pragma unroll
    for (int i = 0; i < 3; i++) {
        int d = threadIdx.x + i * 256;
        x[rb + d] = vals[i];
        float v = vals[i] * r * nw[d];
        __nv_bfloat16 hi, lo;
        split_bf16(v, hi, lo);
        xh[rb + d] = hi;
        xl[rb + d] = lo;
    }
}

// ---------------- gadd + rmsnorm fused ----------------
__global__ void k_gadd_rms(const float* __restrict__ y, const float* __restrict__ patch,
                           const int* __restrict__ pid, const float* __restrict__ nw,
                           float* __restrict__ x, __nv_bfloat16* __restrict__ xh,
                           __nv_bfloat16* __restrict__ xl) {
    int bs = blockIdx.x;
    int b = bs / SS;
    const float* pr = patch + (size_t)(b * PP + pid[bs]) * DD;
    const float* yr = y + (size_t)bs * DD;
    float vals[3];
    float ss = 0.f;
#pragma unroll
    for (int i = 0; i < 3; i++) {
        int d = threadIdx.x + i * 256;
        float v = yr[d] + pr[d];
        vals[i] = v;
        ss += v * v;
    }
    __shared__ float red[8];
#pragma unroll
    for (int o = 16; o > 0; o >>= 1) ss += __shfl_xor_sync(~0u, ss, o);
    if ((threadIdx.x & 31) == 0) red[threadIdx.x >> 5] = ss;
    __syncthreads();
    if (threadIdx.x == 0) {
        float v = 0.f;
#pragma unroll
        for (int i = 0; i < 8; i++) v += red[i];
        red[0] = rsqrtf(v / DD + 1e-6f);
    }
    __syncthreads();
    float r = red[0];
    size_t rb = (size_t)bs * DD;
#pragma unroll
    for (int i = 0; i < 3; i++) {
        int d = threadIdx.x + i * 256;
        x[rb + d] = vals[i];
        float v = vals[i] * r * nw[d];
        __nv_bfloat16 hi, lo;
        split_bf16(v, hi, lo);
        xh[rb + d] = hi;
        xl[rb + d] = lo;
    }
}

// ---------------- final rmsnorm (bf16 hi/lo only) ----------------
__global__ void k_rms_b(const float* __restrict__ y, const float* __restrict__ nw,
                        __nv_bfloat16* __restrict__ xh, __nv_bfloat16* __restrict__ xl) {
    int bs = blockIdx.x;
    const float* yr = y + (size_t)bs * DD;
    float vals[3];
    float ss = 0.f;
#pragma unroll
    for (int i = 0; i < 3; i++) {
        int d = threadIdx.x + i * 256;
        float v = yr[d];
        vals[i] = v;
        ss += v * v;
    }
    __shared__ float red[8];
#pragma unroll
    for (int o = 16; o > 0; o >>= 1) ss += __shfl_xor_sync(~0u, ss, o);
    if ((threadIdx.x & 31) == 0) red[threadIdx.x >> 5] = ss;
    __syncthreads();
    if (threadIdx.x == 0) {
        float v = 0.f;
#pragma unroll
        for (int i = 0; i < 8; i++) v += red[i];
        red[0] = rsqrtf(v / DD + 1e-6f);
    }
    __syncthreads();
    float r = red[0];
    size_t rb = (size_t)bs * DD;
#pragma unroll
    for (int i = 0; i < 3; i++) {
        int d = threadIdx.x + i * 256;
        float v = vals[i] * r * nw[d];
        __nv_bfloat16 hi, lo;
        split_bf16(v, hi, lo);
        xh[rb + d] = hi;
        xl[rb + d] = lo;
    }
}

// ---------------- minGRU scan over precomputed (a,b) ----------------
__global__ void k_scan_red(const float2* __restrict__ ab, float2* __restrict__ carry) {
    int idx = blockIdx.x * 256 + threadIdx.x;
    int d = idx % DD;
    int bc = idx / DD;
    int b = bc % BB;
    int c = bc / BB;
    const float2* base = ab + (size_t)(b * SS + c * LL) * DD + d;
    float A = 1.f, Bv = 0.f;
#pragma unroll 4
    for (int t = 0; t < LL; t++) {
        float2 v = *base;
        base += DD;
        A *= v.x;
        Bv = fmaf(v.x, Bv, v.y);
    }
    carry[idx] = make_float2(A, Bv);
}

__global__ void k_scan_carry(const float2* __restrict__ carry, float* __restrict__ hinit) {
    int ch = blockIdx.x * 256 + threadIdx.x;
    int d = ch % DD;
    int b = ch / DD;
    float h = 0.f;
#pragma unroll
    for (int c = 0; c < CC; c++) {
        int i = (c * BB + b) * DD + d;
        hinit[i] = h;
        float2 abv = carry[i];
        h = fmaf(abv.x, h, abv.y);
    }
}

__global__ void k_scan_apply(const float2* __restrict__ ab, const float* __restrict__ hinit,
                             __nv_bfloat16* __restrict__ hh, __nv_bfloat16* __restrict__ hl) {
    int idx = blockIdx.x * 256 + threadIdx.x;
    int d = idx % DD;
    int bc = idx / DD;
    int b = bc % BB;
    int c = bc / BB;
    size_t off = (size_t)(b * SS + c * LL) * DD + d;
    const float2* base = ab + off;
    float h = hinit[idx];
#pragma unroll 4
    for (int t = 0; t < LL; t++) {
        float2 v = *base;
        base += DD;
        h = fmaf(v.x, h, v.y);
        __nv_bfloat16 hi, lo;
        split_bf16(h, hi, lo);
        hh[off] = hi;
        hl[off] = lo;
        off += DD;
    }
}

// ---------------- patch bookkeeping ----------------
__global__ void k_cum(const int* __restrict__ lens, int* __restrict__ cum) {
    int b = blockIdx.x;
    if (threadIdx.x == 0) {
        int s = 0;
        for (int p = 0; p < PP; p++) {
            s += lens[b * PP + p];
            cum[b * PP + p] = s;
        }
    }
}

__global__ void k_pid(const int* __restrict__ cum, int* __restrict__ pid) {
    int i = blockIdx.x * 256 + threadIdx.x;
    if (i >= BS) return;
    int b = i / SS;
    int pos = i % SS;
    const int* c = cum + b * PP;
    int lo = 0, hi = PP;
    while (lo < hi) {
        int mid = (lo + hi) >> 1;
        if (c[mid] <= pos) lo = mid + 1;
        else hi = mid;
    }
    pid[i] = lo;
}

__global__ void k_segmax(const float* __restrict__ y, const int* __restrict__ cum,
                         float* __restrict__ patch) {
    int bp = blockIdx.x;
    int b = bp / PP, p = bp % PP;
    int start = p ? cum[b * PP + p - 1] : 0;
    int end = cum[b * PP + p];
    const float* yb = y + (size_t)b * SS * DD;
    float* orow = patch + (size_t)bp * DD;
    for (int d = threadIdx.x; d < DD; d += 256) {
        float m = -3.402823466e38f;
        for (int s = start; s < end; s++)
            m = fmaxf(m, yb[(size_t)s * DD + d]);
        orow[d] = m;
    }
}

// ---------------- launch ----------------
extern "C" void kernel_launch(void* const* d_in, const int* in_sizes, int n_in,
                              void* d_out, int out_size) {
    const int*   ids      = (const int*)d_in[0];
    const int*   lens     = (const int*)d_in[1];
    const float* tok      = (const float*)d_in[2];
    const float* hsh      = (const float*)d_in[3];
    const float* enc_nw   = (const float*)d_in[4];
    const float* enc_whg  = (const float*)d_in[5];
    const float* enc_wout = (const float*)d_in[6];
    const float* dec_nw   = (const float*)d_in[7];
    const float* dec_whg  = (const float*)d_in[8];
    const float* dec_wout = (const float*)d_in[9];
    const float* fin_nw   = (const float*)d_in[10];
    const float* oproj    = (const float*)d_in[11];
    float*       out      = (float*)d_out;

    float* base = nullptr;
    cudaGetSymbolAddress((void**)&base, g_scratch);
    float*         x     = base + OFF_X;
    float*         y     = base + OFF_Y;
    float2*        ab    = (float2*)(base + OFF_AB);
    __nv_bfloat16* xh    = (__nv_bfloat16*)(base + OFF_XH);
    __nv_bfloat16* xl    = (__nv_bfloat16*)(base + OFF_XL);
    __nv_bfloat16* hh    = (__nv_bfloat16*)(base + OFF_HH);
    __nv_bfloat16* hl    = (__nv_bfloat16*)(base + OFF_HL);
    float*         patch = base + OFF_PAT;
    float2*        carry = (float2*)(base + OFF_CAR);
    float*         hinit = base + OFF_HIN;
    int*           cum   = (int*)(base + OFF_CUM);
    int*           pid   = (int*)(base + OFF_PID);
    __nv_bfloat16* wHGhe = (__nv_bfloat16*)(base + OFF_WHGHE);
    __nv_bfloat16* wHGle = (__nv_bfloat16*)(base + OFF_WHGLE);
    __nv_bfloat16* wOUhe = (__nv_bfloat16*)(base + OFF_WOUHE);
    __nv_bfloat16* wOUle = (__nv_bfloat16*)(base + OFF_WOULE);
    __nv_bfloat16* wHGhd = (__nv_bfloat16*)(base + OFF_WHGHD);
    __nv_bfloat16* wHGld = (__nv_bfloat16*)(base + OFF_WHGLD);
    __nv_bfloat16* wOUhd = (__nv_bfloat16*)(base + OFF_WOUHD);
    __nv_bfloat16* wOUld = (__nv_bfloat16*)(base + OFF_WOULD);
    __nv_bfloat16* wLGh  = (__nv_bfloat16*)(base + OFF_WLGH);
    __nv_bfloat16* wLGl  = (__nv_bfloat16*)(base + OFF_WLGL);

    constexpr int SMEM = 2 * (2 * 128 * 128 + 2 * 64 * 128);  // 98304 bytes
    cudaFuncSetAttribute(k_hgemm<1>, cudaFuncAttributeMaxDynamicSharedMemorySize, SMEM);
    cudaFuncSetAttribute(k_hgemm<2>, cudaFuncAttributeMaxDynamicSharedMemorySize, SMEM);
    cudaFuncSetAttribute(k_hgemm<3>, cudaFuncAttributeMaxDynamicSharedMemorySize, SMEM);

    dim3 tb(32, 32);
    // launches 0..4 (so launch #5 = first GEMM for ncu)
    k_cum<<<BB, 32>>>(lens, cum);
    k_pid<<<(BS + 255) / 256, 256>>>(cum, pid);
    k_embed_rms<<<BS, 256>>>(ids, tok, hsh, enc_nw, x, xh, xl);
    k_wprep<<<dim3(1536 / 32, GK / 32), tb>>>(enc_whg, wHGhe, wHGle, 1536, 1, 1536);
    k_wprep<<<dim3(768 / 32, GK / 32), tb>>>(enc_wout, wOUhe, wOUle, 768, 0, 768);

    // ---- encoder block ----  (launch #5 = k_hgemm<1>)
    k_hgemm<1><<<dim3(24, 128), 256, SMEM>>>(xh, xl, wHGhe, wHGle, nullptr, (float*)ab);
    k_scan_red<<<CBD / 256, 256>>>(ab, carry);
    k_scan_carry<<<(BB * DD) / 256, 256>>>(carry, hinit);
    k_scan_apply<<<CBD / 256, 256>>>(ab, hinit, hh, hl);
    k_hgemm<2><<<dim3(12, 128), 256, SMEM>>>(hh, hl, wOUhe, wOUle, x, y);

    // remaining weight preps (needed later)
    k_wprep<<<dim3(1536 / 32, GK / 32), tb>>>(dec_whg, wHGhd, wHGld, 1536, 1, 1536);
    k_wprep<<<dim3(768 / 32, GK / 32), tb>>>(dec_wout, wOUhd, wOUld, 768, 0, 768);
    k_wprep<<<dim3(NLOGPAD / 32, GK / 32), tb>>>(oproj, wLGh, wLGl, NBYTE, 0, NBYTE);

    // ---- patch pooling + decoder input (+ decoder rmsnorm fused) ----
    k_segmax<<<BB * PP, 256>>>(y, cum, patch);
    k_gadd_rms<<<BS, 256>>>(y, patch, pid, dec_nw, x, xh, xl);

    // ---- decoder block ----
    k_hgemm<1><<<dim3(24, 128), 256, SMEM>>>(xh, xl, wHGhd, wHGld, nullptr, (float*)ab);
    k_scan_red<<<CBD / 256, 256>>>(ab, carry);
    k_scan_carry<<<(BB * DD) / 256, 256>>>(carry, hinit);
    k_scan_apply<<<CBD / 256, 256>>>(ab, hinit, hh, hl);
    k_hgemm<2><<<dim3(12, 128), 256, SMEM>>>(hh, hl, wOUhd, wOUld, x, y);

    // ---- final norm + logits ----
    k_rms_b<<<BS, 256>>>(y, fin_nw, xh, xl);
    k_hgemm<3><<<dim3(6, 128), 256, SMEM>>>(xh, xl, wLGh, wLGl, nullptr, out);
}

// round 12
// speedup vs baseline: 3.0823x; 1.0119x over previous
#include <cuda_runtime.h>
#include <cuda_bf16.h>
#include <math.h>
#include <stdint.h>

// ---------------- problem constants ----------------
constexpr int BB = 4;
constexpr int SS = 4096;
constexpr int DD = 768;
constexpr int PP = 683;
constexpr int NBYTE = 260;
constexpr int HASHMASK = 65535;     // HASH_VOCAB = 65536
constexpr int BS  = BB * SS;        // 16384 rows
constexpr int BSD = BS * DD;
constexpr int BPD = BB * PP * DD;
constexpr int CC  = 32;             // scan chunks
constexpr int LL  = SS / CC;        // 128
constexpr int CBD = CC * BB * DD;
constexpr int GK  = 768;            // GEMM K
constexpr int NLOGPAD = 384;        // logits N padded

// ---------------- scratch layout (floats) ----------------
constexpr size_t OFF_X    = 0;
constexpr size_t OFF_Y    = OFF_X   + BSD;
constexpr size_t OFF_AB   = OFF_Y   + BSD;          // float2 [BS, DD]
constexpr size_t OFF_XH   = OFF_AB  + 2 * (size_t)BSD;
constexpr size_t OFF_XL   = OFF_XH  + BSD / 2;
constexpr size_t OFF_HH   = OFF_XL  + BSD / 2;
constexpr size_t OFF_HL   = OFF_HH  + BSD / 2;
constexpr size_t OFF_PAT  = OFF_HL  + BSD / 2;
constexpr size_t OFF_CAR  = OFF_PAT + BPD;          // float2 CBD
constexpr size_t OFF_HIN  = OFF_CAR + 2 * (size_t)CBD;
constexpr size_t OFF_CUM  = OFF_HIN + CBD;          // int
constexpr size_t OFF_PID  = OFF_CUM + BB * PP;      // int
constexpr size_t WHG_E    = 1536 * 768 / 2;         // bf16 elems / 2 = floats
constexpr size_t WOUT_E   = 768 * 768 / 2;
constexpr size_t WLOG_E   = (size_t)NLOGPAD * 768 / 2;
constexpr size_t OFF_WHGHE = OFF_PID + BS;
constexpr size_t OFF_WHGLE = OFF_WHGHE + WHG_E;
constexpr size_t OFF_WOUHE = OFF_WHGLE + WHG_E;
constexpr size_t OFF_WOULE = OFF_WOUHE + WOUT_E;
constexpr size_t OFF_WHGHD = OFF_WOULE + WOUT_E;
constexpr size_t OFF_WHGLD = OFF_WHGHD + WHG_E;
constexpr size_t OFF_WOUHD = OFF_WHGLD + WHG_E;
constexpr size_t OFF_WOULD = OFF_WOUHD + WOUT_E;
constexpr size_t OFF_WLGH  = OFF_WOULD + WOUT_E;
constexpr size_t OFF_WLGL  = OFF_WLGH + WLOG_E;
constexpr size_t SCRATCH_FLOATS = OFF_WLGL + WLOG_E + 64;
__device__ float g_scratch[SCRATCH_FLOATS];

// ---------------- PTX helpers (sm_100 baseline only) ----------------
__device__ __forceinline__ uint32_t s2u(const void* p) {
    uint32_t a;
    asm("{ .reg .u64 t; cvta.to.shared.u64 t, %1; cvt.u32.u64 %0, t; }" : "=r"(a) : "l"(p));
    return a;
}
__device__ __forceinline__ void cp16(uint32_t dst, const void* src) {
    asm volatile("cp.async.cg.shared.global [%0], [%1], 16;" :: "r"(dst), "l"(src));
}
__device__ __forceinline__ void cp_commit() { asm volatile("cp.async.commit_group;" ::: "memory"); }
template <int N>
__device__ __forceinline__ void cp_wait() { asm volatile("cp.async.wait_group %0;" :: "n"(N) : "memory"); }

__device__ __forceinline__ void ldsm_x4(uint32_t& r0, uint32_t& r1, uint32_t& r2, uint32_t& r3,
                                        uint32_t addr) {
    asm volatile("ldmatrix.sync.aligned.m8n8.x4.shared.b16 {%0,%1,%2,%3}, [%4];"
                 : "=r"(r0), "=r"(r1), "=r"(r2), "=r"(r3) : "r"(addr));
}
__device__ __forceinline__ void mma16816(float* c, const uint32_t* a, const uint32_t* b) {
    asm volatile(
        "mma.sync.aligned.m16n8k16.row.col.f32.bf16.bf16.f32 "
        "{%0,%1,%2,%3}, {%4,%5,%6,%7}, {%8,%9}, {%0,%1,%2,%3};"
        : "+f"(c[0]), "+f"(c[1]), "+f"(c[2]), "+f"(c[3])
        : "r"(a[0]), "r"(a[1]), "r"(a[2]), "r"(a[3]), "r"(b[0]), "r"(b[1]));
}

__device__ __forceinline__ uint32_t sw128(uint32_t o) { return o ^ ((o >> 3) & 0x70); }

__device__ __forceinline__ void split_bf16(float v, __nv_bfloat16& hi, __nv_bfloat16& lo) {
    hi = __float2bfloat16(v);
    lo = __float2bfloat16(v - __bfloat162float(hi));
}

// ---------------- batched minGRU coefficients (4 elements, 1 shared rcp) ----------------
// a_k = sigmoid(-g_k); b_k = sigmoid(g_k) * gtilde(h_k)
// gtilde(h) = h+0.5 (h>=0) | sigmoid(h) (h<0)
// Uses one rcp over the product of all (up to 8) denominators; clamp +-10 keeps
// the product <= ~5.5e34 (< fp32 max) and changes sigma only beyond |x|>10
// (abs err < 5e-5, never hit for unit-variance pre-activations).
__device__ __forceinline__ void mingru4(const float* hid4, const float* gt4,
                                        float* aout, float* bout) {
    float u[4], x[4], dd[4], e[4];
#pragma unroll
    for (int k = 0; k < 4; k++) {
        float g = fminf(fmaxf(gt4[k], -10.f), 10.f);
        u[k] = __expf(-g);
        x[k] = 1.f + u[k];
        float hm = fmaxf(fminf(hid4[k], 0.f), -10.f);
        e[k] = __expf(hm);
        dd[k] = (hid4[k] < 0.f) ? (1.f + e[k]) : 1.f;
    }
    float A0 = x[0] * dd[0], A1 = x[1] * dd[1];
    float A2 = x[2] * dd[2], A3 = x[3] * dd[3];
    float P01 = A0 * A1, P23 = A2 * A3;
    float W = __frcp_rn(P01 * P23);
    float W01 = W * P23, W23 = W * P01;
    float iA[4];
    iA[0] = W01 * A1; iA[1] = W01 * A0;
    iA[2] = W23 * A3; iA[3] = W23 * A2;
#pragma unroll
    for (int k = 0; k < 4; k++) {
        float ix = iA[k] * dd[k];          // 1/(1+u) = sigmoid(g)
        aout[k] = u[k] * ix;               // sigmoid(-g)
        float gt_;
        if (hid4[k] >= 0.f) gt_ = hid4[k] + 0.5f;
        else                gt_ = e[k] * (iA[k] * x[k]);  // e/(1+e)
        bout[k] = ix * gt_;
    }
}

// ================= HMMA split-bf16 GEMM (128x64 tile, 2 CTAs/SM) =================
// Per k-chunk: stage Ah,Al,Bh,Bl once; issue AhBh + AlBh + AhBl from it.
// 256 threads, 8 warps (4x2), warp tile 32x32 of the 128x64 CTA tile.
// EPI: 1 = minGRU (a,b) from interleaved (hid,gate) cols -> ab float2 [BS,768]
//      2 = += Res, store fp32 [BS,768]
//      3 = logits, store fp32 [BS,260] col-guarded
template <int EPI>
__global__ void __launch_bounds__(256, 2)
k_hgemm(const __nv_bfloat16* __restrict__ Ah, const __nv_bfloat16* __restrict__ Al,
        const __nv_bfloat16* __restrict__ Bh, const __nv_bfloat16* __restrict__ Bl,
        const float* __restrict__ Res, float* __restrict__ Cout) {
    constexpr int KC = 64;               // bf16 per k-chunk (128 bytes)
    constexpr int NCH = GK / KC;         // 12
    constexpr int MAT_A = 128 * 128;     // 16 KB
    constexpr int MAT_B = 64 * 128;      // 8 KB
    constexpr int OFF_AH = 0;
    constexpr int OFF_AL = MAT_A;
    constexpr int OFF_BH = 2 * MAT_A;
    constexpr int OFF_BL = 2 * MAT_A + MAT_B;
    constexpr int STAGE  = 2 * MAT_A + 2 * MAT_B;   // 49152

    extern __shared__ char smem[];
    uint32_t sb = s2u(smem);

    int tid = threadIdx.x;
    int lane = tid & 31, wid = tid >> 5;
    int wm = wid >> 1, wn = wid & 1;     // warp tile: rows wm*32, cols wn*32
    int m0 = blockIdx.y * 128, n0 = blockIdx.x * 64;

    auto load_stage = [&](int kc) {
        uint32_t st = sb + (kc & 1) * STAGE;
        const __nv_bfloat16* ah = Ah + (size_t)m0 * GK + kc * KC;
        const __nv_bfloat16* al = Al + (size_t)m0 * GK + kc * KC;
        const __nv_bfloat16* bh = Bh + (size_t)n0 * GK + kc * KC;
        const __nv_bfloat16* bl = Bl + (size_t)n0 * GK + kc * KC;
#pragma unroll
        for (int i = 0; i < 4; i++) {          // A: 128 rows * 8 segs / 256 thr
            int idx = tid + i * 256;
            int r = idx >> 3, sg = idx & 7;
            uint32_t so = sw128(r * 128 + sg * 16);
            size_t go = (size_t)r * GK + sg * 8;
            cp16(st + OFF_AH + so, ah + go);
            cp16(st + OFF_AL + so, al + go);
        }
#pragma unroll
        for (int i = 0; i < 2; i++) {          // B: 64 rows * 8 segs / 256 thr
            int idx = tid + i * 256;
            int r = idx >> 3, sg = idx & 7;
            uint32_t so = sw128(r * 128 + sg * 16);
            size_t go = (size_t)r * GK + sg * 8;
            cp16(st + OFF_BH + so, bh + go);
            cp16(st + OFF_BL + so, bl + go);
        }
    };

    float acc[2][4][4];
#pragma unroll
    for (int i = 0; i < 2; i++)
#pragma unroll
        for (int j = 0; j < 4; j++)
#pragma unroll
            for (int q = 0; q < 4; q++) acc[i][j][q] = 0.f;

    int aRow = (lane & 15);
    int aSel = (lane >> 4);
    int bTile = (lane >> 4);            // which j-tile within a pair
    int bSel = ((lane >> 3) & 1);       // k16-half
    int bRow = (lane & 7);

    load_stage(0); cp_commit();
    load_stage(1); cp_commit();

    for (int it = 0; it < NCH; it++) {
        cp_wait<1>();
        __syncthreads();

        uint32_t st = sb + (it & 1) * STAGE;
#pragma unroll
        for (int kk = 0; kk < 4; kk++) {
            uint32_t afh[2][4], afl[2][4], bfh[4][2], bfl[4][2];
#pragma unroll
            for (int i = 0; i < 2; i++) {
                int row = wm * 32 + i * 16 + aRow;
                int chunk = (kk * 2 + aSel) ^ (row & 7);
                uint32_t off = row * 128 + chunk * 16;
                ldsm_x4(afh[i][0], afh[i][1], afh[i][2], afh[i][3], st + OFF_AH + off);
                ldsm_x4(afl[i][0], afl[i][1], afl[i][2], afl[i][3], st + OFF_AL + off);
            }
#pragma unroll
            for (int jp = 0; jp < 2; jp++) {
                int row = wn * 32 + jp * 16 + bTile * 8 + bRow;
                int chunk = (kk * 2 + bSel) ^ (row & 7);
                uint32_t off = row * 128 + chunk * 16;
                ldsm_x4(bfh[jp * 2][0], bfh[jp * 2][1], bfh[jp * 2 + 1][0], bfh[jp * 2 + 1][1],
                        st + OFF_BH + off);
                ldsm_x4(bfl[jp * 2][0], bfl[jp * 2][1], bfl[jp * 2 + 1][0], bfl[jp * 2 + 1][1],
                        st + OFF_BL + off);
            }
#pragma unroll
            for (int i = 0; i < 2; i++)
#pragma unroll
                for (int j = 0; j < 4; j++) {
                    mma16816(acc[i][j], afh[i], bfh[j]);
                    mma16816(acc[i][j], afl[i], bfh[j]);
                    mma16816(acc[i][j], afh[i], bfl[j]);
                }
        }
        __syncthreads();
        if (it + 2 < NCH) load_stage(it + 2);
        cp_commit();
    }

    // ---------------- epilogue ----------------
    int cRow = lane >> 2;            // 0..7
    int cCol = (lane & 3) * 2;       // even
    if (EPI == 1) {
        float2* ab = (float2*)Cout;
#pragma unroll
        for (int j = 0; j < 4; j++) {
            int col = n0 + wn * 32 + j * 8 + cCol;
            int d = col >> 1;
            float hid4[4], gt4[4];
            int rows[4];
#pragma unroll
            for (int i = 0; i < 2; i++) {
                int r0 = m0 + wm * 32 + i * 16 + cRow;
                rows[i * 2]     = r0;
                rows[i * 2 + 1] = r0 + 8;
                hid4[i * 2]     = acc[i][j][0];
                gt4[i * 2]      = acc[i][j][1];
                hid4[i * 2 + 1] = acc[i][j][2];
                gt4[i * 2 + 1]  = acc[i][j][3];
            }
            float av[4], bv[4];
            mingru4(hid4, gt4, av, bv);
#pragma unroll
            for (int k = 0; k < 4; k++)
                ab[(size_t)rows[k] * DD + d] = make_float2(av[k], bv[k]);
        }
    } else {
#pragma unroll
        for (int i = 0; i < 2; i++) {
#pragma unroll
            for (int j = 0; j < 4; j++) {
                int r0 = m0 + wm * 32 + i * 16 + cRow;
                int r1 = r0 + 8;
                int col = n0 + wn * 32 + j * 8 + cCol;
                float c0 = acc[i][j][0], c1 = acc[i][j][1];
                float c2 = acc[i][j][2], c3 = acc[i][j][3];
                if (EPI == 2) {
                    const float2* rr0 = (const float2*)(Res + (size_t)r0 * DD + col);
                    const float2* rr1 = (const float2*)(Res + (size_t)r1 * DD + col);
                    float2 v0 = rr0[0], v1 = rr1[0];
                    *(float2*)(Cout + (size_t)r0 * DD + col) = make_float2(c0 + v0.x, c1 + v0.y);
                    *(float2*)(Cout + (size_t)r1 * DD + col) = make_float2(c2 + v1.x, c3 + v1.y);
                } else {
                    if (col < NBYTE) {
                        Cout[(size_t)r0 * NBYTE + col] = c0;
                        Cout[(size_t)r1 * NBYTE + col] = c2;
                    }
                    if (col + 1 < NBYTE) {
                        Cout[(size_t)r0 * NBYTE + col + 1] = c1;
                        Cout[(size_t)r1 * NBYTE + col + 1] = c3;
                    }
                }
            }
        }
    }
}

// ---------------- weight prep: [K,N] fp32 -> transposed [Npad,K] bf16 hi/lo ----------------
__global__ void k_wprep(const float* __restrict__ W, __nv_bfloat16* __restrict__ Wh,
                        __nv_bfloat16* __restrict__ Wl, int N, int mode, int nvalid) {
    __shared__ float tile[32][33];
    int n0 = blockIdx.x * 32, k0 = blockIdx.y * 32;
    int tx = threadIdx.x, ty = threadIdx.y;
    int n = n0 + tx;
    float v = 0.f;
    if (n < nvalid) {
        int src = (mode == 1) ? ((n & 1) ? (N >> 1) + (n >> 1) : (n >> 1)) : n;
        v = W[(size_t)(k0 + ty) * N + src];
    }
    tile[ty][tx] = v;
    __syncthreads();
    int on = n0 + ty, ok = k0 + tx;
    float w = tile[tx][ty];
    __nv_bfloat16 hi, lo;
    split_bf16(w, hi, lo);
    Wh[(size_t)on * GK + ok] = hi;
    Wl[(size_t)on * GK + ok] = lo;
}

// ---------------- embed + rmsnorm fused ----------------
__global__ void k_embed_rms(const int* __restrict__ ids, const float* __restrict__ tok,
                            const float* __restrict__ hsh, const float* __restrict__ nw,
                            float* __restrict__ x, __nv_bfloat16* __restrict__ xh,
                            __nv_bfloat16* __restrict__ xl) {
    int bs = blockIdx.x;
    int s = bs & (SS - 1);
    int t0 = ids[bs];
    int acc = t0, p = 31;
#pragma unroll
    for (int j = 1; j < 4; j++) {
        if (s >= j) acc += ids[bs - j] * p;
        p *= 31;
    }
    int hid = acc & HASHMASK;
    const float* tr = tok + (size_t)t0 * DD;
    const float* hr = hsh + (size_t)hid * DD;
    float vals[3];
    float ss = 0.f;
#pragma unroll
    for (int i = 0; i < 3; i++) {
        int d = threadIdx.x + i * 256;
        float v = tr[d] + hr[d];
        vals[i] = v;
        ss += v * v;
    }
    __shared__ float red[8];
#pragma unroll
    for (int o = 16; o > 0; o >>= 1) ss += __shfl_xor_sync(~0u, ss, o);
    if ((threadIdx.x & 31) == 0) red[threadIdx.x >> 5] = ss;
    __syncthreads();
    if (threadIdx.x == 0) {
        float v = 0.f;
#pragma unroll
        for (int i = 0; i < 8; i++) v += red[i];
        red[0] = rsqrtf(v / DD + 1e-6f);
    }
    __syncthreads();
    float r = red[0];
    size_t rb = (size_t)bs * DD;
#pragma unroll
    for (int i = 0; i < 3; i++) {
        int d = threadIdx.x + i * 256;
        x[rb + d] = vals[i];
        float v = vals[i] * r * nw[d];
        __nv_bfloat16 hi, lo;
        split_bf16(v, hi, lo);
        xh[rb + d] = hi;
        xl[rb + d] = lo;
    }
}

// ---------------- gadd + rmsnorm fused ----------------
__global__ void k_gadd_rms(const float* __restrict__ y, const float* __restrict__ patch,
                           const int* __restrict__ pid, const float* __restrict__ nw,
                           float* __restrict__ x, __nv_bfloat16* __restrict__ xh,
                           __nv_bfloat16* __restrict__ xl) {
    int bs = blockIdx.x;
    int b = bs / SS;
    const float* pr = patch + (size_t)(b * PP + pid[bs]) * DD;
    const float* yr = y + (size_t)bs * DD;
    float vals[3];
    float ss = 0.f;
#pragma unroll
    for (int i = 0; i < 3; i++) {
        int d = threadIdx.x + i * 256;
        float v = yr[d] + pr[d];
        vals[i] = v;
        ss += v * v;
    }
    __shared__ float red[8];
#pragma unroll
    for (int o = 16; o > 0; o >>= 1) ss += __shfl_xor_sync(~0u, ss, o);
    if ((threadIdx.x & 31) == 0) red[threadIdx.x >> 5] = ss;
    __syncthreads();
    if (threadIdx.x == 0) {
        float v = 0.f;
#pragma unroll
        for (int i = 0; i < 8; i++) v += red[i];
        red[0] = rsqrtf(v / DD + 1e-6f);
    }
    __syncthreads();
    float r = red[0];
    size_t rb = (size_t)bs * DD;
#pragma unroll
    for (int i = 0; i < 3; i++) {
        int d = threadIdx.x + i * 256;
        x[rb + d] = vals[i];
        float v = vals[i] * r * nw[d];
        __nv_bfloat16 hi, lo;
        split_bf16(v, hi, lo);
        xh[rb + d] = hi;
        xl[rb + d] = lo;
    }
}

// ---------------- final rmsnorm (bf16 hi/lo only) ----------------
__global__ void k_rms_b(const float* __restrict__ y, const float* __restrict__ nw,
                        __nv_bfloat16* __restrict__ xh, __nv_bfloat16* __restrict__ xl) {
    int bs = blockIdx.x;
    const float* yr = y + (size_t)bs * DD;
    float vals[3];
    float ss = 0.f;
#pragma unroll
    for (int i = 0; i < 3; i++) {
        int d = threadIdx.x + i * 256;
        float v = yr[d];
        vals[i] = v;
        ss += v * v;
    }
    __shared__ float red[8];
#pragma unroll
    for (int o = 16; o > 0; o >>= 1) ss += __shfl_xor_sync(~0u, ss, o);
    if ((threadIdx.x & 31) == 0) red[threadIdx.x >> 5] = ss;
    __syncthreads();
    if (threadIdx.x == 0) {
        float v = 0.f;
#pragma unroll
        for (int i = 0; i < 8; i++) v += red[i];
        red[0] = rsqrtf(v / DD + 1e-6f);
    }
    __syncthreads();
    float r = red[0];
    size_t rb = (size_t)bs * DD;
#pragma unroll
    for (int i = 0; i < 3; i++) {
        int d = threadIdx.x + i * 256;
        float v = vals[i] * r * nw[d];
        __nv_bfloat16 hi, lo;
        split_bf16(v, hi, lo);
        xh[rb + d] = hi;
        xl[rb + d] = lo;
    }
}

// ---------------- minGRU scan over precomputed (a,b) ----------------
__global__ void k_scan_red(const float2* __restrict__ ab, float2* __restrict__ carry) {
    int idx = blockIdx.x * 256 + threadIdx.x;
    int d = idx % DD;
    int bc = idx / DD;
    int b = bc % BB;
    int c = bc / BB;
    const float2* base = ab + (size_t)(b * SS + c * LL) * DD + d;
    float A = 1.f, Bv = 0.f;
#pragma unroll 4
    for (int t = 0; t < LL; t++) {
        float2 v = *base;
        base += DD;
        A *= v.x;
        Bv = fmaf(v.x, Bv, v.y);
    }
    carry[idx] = make_float2(A, Bv);
}

__global__ void k_scan_carry(const float2* __restrict__ carry, float* __restrict__ hinit) {
    int ch = blockIdx.x * 256 + threadIdx.x;
    int d = ch % DD;
    int b = ch / DD;
    float h = 0.f;
#pragma unroll
    for (int c = 0; c < CC; c++) {
        int i = (c * BB + b) * DD + d;
        hinit[i] = h;
        float2 abv = carry[i];
        h = fmaf(abv.x, h, abv.y);
    }
}

__global__ void k_scan_apply(const float2* __restrict__ ab, const float* __restrict__ hinit,
                             __nv_bfloat16* __restrict__ hh, __nv_bfloat16* __restrict__ hl) {
    int idx = blockIdx.x * 256 + threadIdx.x;
    int d = idx % DD;
    int bc = idx / DD;
    int b = bc % BB;
    int c = bc / BB;
    size_t off = (size_t)(b * SS + c * LL) * DD + d;
    const float2* base = ab + off;
    float h = hinit[idx];
#pragma unroll 4
    for (int t = 0; t < LL; t++) {
        float2 v = *base;
        base += DD;
        h = fmaf(v.x, h, v.y);
        __nv_bfloat16 hi, lo;
        split_bf16(h, hi, lo);
        hh[off] = hi;
        hl[off] = lo;
        off += DD;
    }
}

// ---------------- patch bookkeeping ----------------
__global__ void k_cum(const int* __restrict__ lens, int* __restrict__ cum) {
    int b = blockIdx.x;
    if (threadIdx.x == 0) {
        int s = 0;
        for (int p = 0; p < PP; p++) {
            s += lens[b * PP + p];
            cum[b * PP + p] = s;
        }
    }
}

__global__ void k_pid(const int* __restrict__ cum, int* __restrict__ pid) {
    int i = blockIdx.x * 256 + threadIdx.x;
    if (i >= BS) return;
    int b = i / SS;
    int pos = i % SS;
    const int* c = cum + b * PP;
    int lo = 0, hi = PP;
    while (lo < hi) {
        int mid = (lo + hi) >> 1;
        if (c[mid] <= pos) lo = mid + 1;
        else hi = mid;
    }
    pid[i] = lo;
}

__global__ void k_segmax(const float* __restrict__ y, const int* __restrict__ cum,
                         float* __restrict__ patch) {
    int bp = blockIdx.x;
    int b = bp / PP, p = bp % PP;
    int start = p ? cum[b * PP + p - 1] : 0;
    int end = cum[b * PP + p];
    const float* yb = y + (size_t)b * SS * DD;
    float* orow = patch + (size_t)bp * DD;
    for (int d = threadIdx.x; d < DD; d += 256) {
        float m = -3.402823466e38f;
        for (int s = start; s < end; s++)
            m = fmaxf(m, yb[(size_t)s * DD + d]);
        orow[d] = m;
    }
}

// ---------------- launch ----------------
extern "C" void kernel_launch(void* const* d_in, const int* in_sizes, int n_in,
                              void* d_out, int out_size) {
    const int*   ids      = (const int*)d_in[0];
    const int*   lens     = (const int*)d_in[1];
    const float* tok      = (const float*)d_in[2];
    const float* hsh      = (const float*)d_in[3];
    const float* enc_nw   = (const float*)d_in[4];
    const float* enc_whg  = (const float*)d_in[5];
    const float* enc_wout = (const float*)d_in[6];
    const float* dec_nw   = (const float*)d_in[7];
    const float* dec_whg  = (const float*)d_in[8];
    const float* dec_wout = (const float*)d_in[9];
    const float* fin_nw   = (const float*)d_in[10];
    const float* oproj    = (const float*)d_in[11];
    float*       out      = (float*)d_out;

    float* base = nullptr;
    cudaGetSymbolAddress((void**)&base, g_scratch);
    float*         x     = base + OFF_X;
    float*         y     = base + OFF_Y;
    float2*        ab    = (float2*)(base + OFF_AB);
    __nv_bfloat16* xh    = (__nv_bfloat16*)(base + OFF_XH);
    __nv_bfloat16* xl    = (__nv_bfloat16*)(base + OFF_XL);
    __nv_bfloat16* hh    = (__nv_bfloat16*)(base + OFF_HH);
    __nv_bfloat16* hl    = (__nv_bfloat16*)(base + OFF_HL);
    float*         patch = base + OFF_PAT;
    float2*        carry = (float2*)(base + OFF_CAR);
    float*         hinit = base + OFF_HIN;
    int*           cum   = (int*)(base + OFF_CUM);
    int*           pid   = (int*)(base + OFF_PID);
    __nv_bfloat16* wHGhe = (__nv_bfloat16*)(base + OFF_WHGHE);
    __nv_bfloat16* wHGle = (__nv_bfloat16*)(base + OFF_WHGLE);
    __nv_bfloat16* wOUhe = (__nv_bfloat16*)(base + OFF_WOUHE);
    __nv_bfloat16* wOUle = (__nv_bfloat16*)(base + OFF_WOULE);
    __nv_bfloat16* wHGhd = (__nv_bfloat16*)(base + OFF_WHGHD);
    __nv_bfloat16* wHGld = (__nv_bfloat16*)(base + OFF_WHGLD);
    __nv_bfloat16* wOUhd = (__nv_bfloat16*)(base + OFF_WOUHD);
    __nv_bfloat16* wOUld = (__nv_bfloat16*)(base + OFF_WOULD);
    __nv_bfloat16* wLGh  = (__nv_bfloat16*)(base + OFF_WLGH);
    __nv_bfloat16* wLGl  = (__nv_bfloat16*)(base + OFF_WLGL);

    constexpr int SMEM = 2 * (2 * 128 * 128 + 2 * 64 * 128);  // 98304 bytes
    cudaFuncSetAttribute(k_hgemm<1>, cudaFuncAttributeMaxDynamicSharedMemorySize, SMEM);
    cudaFuncSetAttribute(k_hgemm<2>, cudaFuncAttributeMaxDynamicSharedMemorySize, SMEM);
    cudaFuncSetAttribute(k_hgemm<3>, cudaFuncAttributeMaxDynamicSharedMemorySize, SMEM);

    dim3 tb(32, 32);
    // launches 0..4 (so launch #5 = first GEMM for ncu)
    k_cum<<<BB, 32>>>(lens, cum);
    k_pid<<<(BS + 255) / 256, 256>>>(cum, pid);
    k_embed_rms<<<BS, 256>>>(ids, tok, hsh, enc_nw, x, xh, xl);
    k_wprep<<<dim3(1536 / 32, GK / 32), tb>>>(enc_whg, wHGhe, wHGle, 1536, 1, 1536);
    k_wprep<<<dim3(768 / 32, GK / 32), tb>>>(enc_wout, wOUhe, wOUle, 768, 0, 768);

    // ---- encoder block ----  (launch #5 = k_hgemm<1>)
    k_hgemm<1><<<dim3(24, 128), 256, SMEM>>>(xh, xl, wHGhe, wHGle, nullptr, (float*)ab);
    k_scan_red<<<CBD / 256, 256>>>(ab, carry);
    k_scan_carry<<<(BB * DD) / 256, 256>>>(carry, hinit);
    k_scan_apply<<<CBD / 256, 256>>>(ab, hinit, hh, hl);
    k_hgemm<2><<<dim3(12, 128), 256, SMEM>>>(hh, hl, wOUhe, wOUle, x, y);

    // remaining weight preps (needed later)
    k_wprep<<<dim3(1536 / 32, GK / 32), tb>>>(dec_whg, wHGhd, wHGld, 1536, 1, 1536);
    k_wprep<<<dim3(768 / 32, GK / 32), tb>>>(dec_wout, wOUhd, wOUld, 768, 0, 768);
    k_wprep<<<dim3(NLOGPAD / 32, GK / 32), tb>>>(oproj, wLGh, wLGl, NBYTE, 0, NBYTE);

    // ---- patch pooling + decoder input (+ decoder rmsnorm fused) ----
    k_segmax<<<BB * PP, 256>>>(y, cum, patch);
    k_gadd_rms<<<BS, 256>>>(y, patch, pid, dec_nw, x, xh, xl);

    // ---- decoder block ----
    k_hgemm<1><<<dim3(24, 128), 256, SMEM>>>(xh, xl, wHGhd, wHGld, nullptr, (float*)ab);
    k_scan_red<<<CBD / 256, 256>>>(ab, carry);
    k_scan_carry<<<(BB * DD) / 256, 256>>>(carry, hinit);
    k_scan_apply<<<CBD / 256, 256>>>(ab, hinit, hh, hl);
    k_hgemm<2><<<dim3(12, 128), 256, SMEM>>>(hh, hl, wOUhd, wOUld, x, y);

    // ---- final norm + logits ----
    k_rms_b<<<BS, 256>>>(y, fin_nw, xh, xl);
    k_hgemm<3><<<dim3(6, 128), 256, SMEM>>>(xh, xl, wLGh, wLGl, nullptr, out);
}

// round 14
// speedup vs baseline: 3.1134x; 1.0101x over previous
#include <cuda_runtime.h>
#include <cuda_bf16.h>
#include <math.h>
#include <stdint.h>

// ---------------- problem constants ----------------
constexpr int BB = 4;
constexpr int SS = 4096;
constexpr int DD = 768;
constexpr int PP = 683;
constexpr int NBYTE = 260;
constexpr int HASHMASK = 65535;     // HASH_VOCAB = 65536
constexpr int BS  = BB * SS;        // 16384 rows
constexpr int BSD = BS * DD;
constexpr int BPD = BB * PP * DD;
constexpr int CC  = 32;             // scan chunks
constexpr int LL  = SS / CC;        // 128
constexpr int CBD = CC * BB * DD;
constexpr int GK  = 768;            // GEMM K
constexpr int NLOGPAD = 384;        // logits weight rows padded

// ---------------- scratch layout (floats) ----------------
constexpr size_t OFF_X    = 0;
constexpr size_t OFF_Y    = OFF_X   + BSD;
constexpr size_t OFF_AB   = OFF_Y   + BSD;          // float2 [BS, DD]
constexpr size_t OFF_XH   = OFF_AB  + 2 * (size_t)BSD;
constexpr size_t OFF_XL   = OFF_XH  + BSD / 2;
constexpr size_t OFF_HH   = OFF_XL  + BSD / 2;
constexpr size_t OFF_HL   = OFF_HH  + BSD / 2;
constexpr size_t OFF_PAT  = OFF_HL  + BSD / 2;
constexpr size_t OFF_CAR  = OFF_PAT + BPD;          // float2 CBD
constexpr size_t OFF_HIN  = OFF_CAR + 2 * (size_t)CBD;
constexpr size_t OFF_CUM  = OFF_HIN + CBD;          // int
constexpr size_t OFF_PID  = OFF_CUM + BB * PP;      // int
constexpr size_t WHG_E    = 1536 * 768 / 2;         // bf16 elems / 2 = floats
constexpr size_t WOUT_E   = 768 * 768 / 2;
constexpr size_t WLOG_E   = (size_t)NLOGPAD * 768 / 2;
constexpr size_t OFF_WHGHE = OFF_PID + BS;
constexpr size_t OFF_WHGLE = OFF_WHGHE + WHG_E;
constexpr size_t OFF_WOUHE = OFF_WHGLE + WHG_E;
constexpr size_t OFF_WOULE = OFF_WOUHE + WOUT_E;
constexpr size_t OFF_WHGHD = OFF_WOULE + WOUT_E;
constexpr size_t OFF_WHGLD = OFF_WHGHD + WHG_E;
constexpr size_t OFF_WOUHD = OFF_WHGLD + WHG_E;
constexpr size_t OFF_WOULD = OFF_WOUHD + WOUT_E;
constexpr size_t OFF_WLGH  = OFF_WOULD + WOUT_E;
constexpr size_t OFF_WLGL  = OFF_WLGH + WLOG_E;
constexpr size_t SCRATCH_FLOATS = OFF_WLGL + WLOG_E + 64;
__device__ float g_scratch[SCRATCH_FLOATS];

// ---------------- PTX helpers (sm_100 baseline only) ----------------
__device__ __forceinline__ uint32_t s2u(const void* p) {
    uint32_t a;
    asm("{ .reg .u64 t; cvta.to.shared.u64 t, %1; cvt.u32.u64 %0, t; }" : "=r"(a) : "l"(p));
    return a;
}
__device__ __forceinline__ void cp16(uint32_t dst, const void* src) {
    asm volatile("cp.async.cg.shared.global [%0], [%1], 16;" :: "r"(dst), "l"(src));
}
__device__ __forceinline__ void cp_commit() { asm volatile("cp.async.commit_group;" ::: "memory"); }
template <int N>
__device__ __forceinline__ void cp_wait() { asm volatile("cp.async.wait_group %0;" :: "n"(N) : "memory"); }

__device__ __forceinline__ void ldsm_x4(uint32_t& r0, uint32_t& r1, uint32_t& r2, uint32_t& r3,
                                        uint32_t addr) {
    asm volatile("ldmatrix.sync.aligned.m8n8.x4.shared.b16 {%0,%1,%2,%3}, [%4];"
                 : "=r"(r0), "=r"(r1), "=r"(r2), "=r"(r3) : "r"(addr));
}
__device__ __forceinline__ void mma16816(float* c, const uint32_t* a, const uint32_t* b) {
    asm volatile(
        "mma.sync.aligned.m16n8k16.row.col.f32.bf16.bf16.f32 "
        "{%0,%1,%2,%3}, {%4,%5,%6,%7}, {%8,%9}, {%0,%1,%2,%3};"
        : "+f"(c[0]), "+f"(c[1]), "+f"(c[2]), "+f"(c[3])
        : "r"(a[0]), "r"(a[1]), "r"(a[2]), "r"(a[3]), "r"(b[0]), "r"(b[1]));
}

__device__ __forceinline__ uint32_t sw128(uint32_t o) { return o ^ ((o >> 3) & 0x70); }

__device__ __forceinline__ void split_bf16(float v, __nv_bfloat16& hi, __nv_bfloat16& lo) {
    hi = __float2bfloat16(v);
    lo = __float2bfloat16(v - __bfloat162float(hi));
}

// ---------------- batched minGRU coefficients (4 elements, 1 shared rcp) ----------------
__device__ __forceinline__ void mingru4(const float* hid4, const float* gt4,
                                        float* aout, float* bout) {
    float u[4], x[4], dd[4], e[4];
#pragma unroll
    for (int k = 0; k < 4; k++) {
        float g = fminf(fmaxf(gt4[k], -10.f), 10.f);
        u[k] = __expf(-g);
        x[k] = 1.f + u[k];
        float hm = fmaxf(fminf(hid4[k], 0.f), -10.f);
        e[k] = __expf(hm);
        dd[k] = (hid4[k] < 0.f) ? (1.f + e[k]) : 1.f;
    }
    float A0 = x[0] * dd[0], A1 = x[1] * dd[1];
    float A2 = x[2] * dd[2], A3 = x[3] * dd[3];
    float P01 = A0 * A1, P23 = A2 * A3;
    float W = __frcp_rn(P01 * P23);
    float W01 = W * P23, W23 = W * P01;
    float iA[4];
    iA[0] = W01 * A1; iA[1] = W01 * A0;
    iA[2] = W23 * A3; iA[3] = W23 * A2;
#pragma unroll
    for (int k = 0; k < 4; k++) {
        float ix = iA[k] * dd[k];          // sigmoid(g)
        aout[k] = u[k] * ix;               // sigmoid(-g)
        float gt_;
        if (hid4[k] >= 0.f) gt_ = hid4[k] + 0.5f;
        else                gt_ = e[k] * (iA[k] * x[k]);  // e/(1+e)
        bout[k] = ix * gt_;
    }
}

// ================= HMMA split-bf16 GEMM (128x64 tile, 2 CTAs/SM) =================
// Per k-chunk: stage Ah,Al,Bh,Bl once; issue AhBh + AlBh + AhBl (pass-major order:
// 8 independent accumulators between consecutive MMAs -> no RAW throttling).
// 256 threads, 8 warps (4x2), warp tile 32x32 of the 128x64 CTA tile.
// EPI: 1 = minGRU (a,b) from interleaved (hid,gate) cols -> ab float2 [BS,768]
//      2 = += Res, store fp32 [BS,768]
//      3 = logits, store fp32 [BS,260] col-guarded
template <int EPI>
__global__ void __launch_bounds__(256, 2)
k_hgemm(const __nv_bfloat16* __restrict__ Ah, const __nv_bfloat16* __restrict__ Al,
        const __nv_bfloat16* __restrict__ Bh, const __nv_bfloat16* __restrict__ Bl,
        const float* __restrict__ Res, float* __restrict__ Cout) {
    constexpr int KC = 64;               // bf16 per k-chunk (128 bytes)
    constexpr int NCH = GK / KC;         // 12
    constexpr int MAT_A = 128 * 128;     // 16 KB
    constexpr int MAT_B = 64 * 128;      // 8 KB
    constexpr int OFF_AH = 0;
    constexpr int OFF_AL = MAT_A;
    constexpr int OFF_BH = 2 * MAT_A;
    constexpr int OFF_BL = 2 * MAT_A + MAT_B;
    constexpr int STAGE  = 2 * MAT_A + 2 * MAT_B;   // 49152

    extern __shared__ char smem[];
    uint32_t sb = s2u(smem);

    int tid = threadIdx.x;
    int lane = tid & 31, wid = tid >> 5;
    int wm = wid >> 1, wn = wid & 1;     // warp tile: rows wm*32, cols wn*32
    int m0 = blockIdx.y * 128, n0 = blockIdx.x * 64;

    auto load_stage = [&](int kc) {
        uint32_t st = sb + (kc & 1) * STAGE;
        const __nv_bfloat16* ah = Ah + (size_t)m0 * GK + kc * KC;
        const __nv_bfloat16* al = Al + (size_t)m0 * GK + kc * KC;
        const __nv_bfloat16* bh = Bh + (size_t)n0 * GK + kc * KC;
        const __nv_bfloat16* bl = Bl + (size_t)n0 * GK + kc * KC;
#pragma unroll
        for (int i = 0; i < 4; i++) {          // A: 128 rows * 8 segs / 256 thr
            int idx = tid + i * 256;
            int r = idx >> 3, sg = idx & 7;
            uint32_t so = sw128(r * 128 + sg * 16);
            size_t go = (size_t)r * GK + sg * 8;
            cp16(st + OFF_AH + so, ah + go);
            cp16(st + OFF_AL + so, al + go);
        }
#pragma unroll
        for (int i = 0; i < 2; i++) {          // B: 64 rows * 8 segs / 256 thr
            int idx = tid + i * 256;
            int r = idx >> 3, sg = idx & 7;
            uint32_t so = sw128(r * 128 + sg * 16);
            size_t go = (size_t)r * GK + sg * 8;
            cp16(st + OFF_BH + so, bh + go);
            cp16(st + OFF_BL + so, bl + go);
        }
    };

    float acc[2][4][4];
#pragma unroll
    for (int i = 0; i < 2; i++)
#pragma unroll
        for (int j = 0; j < 4; j++)
#pragma unroll
            for (int q = 0; q < 4; q++) acc[i][j][q] = 0.f;

    int aRow = (lane & 15);
    int aSel = (lane >> 4);
    int bTile = (lane >> 4);            // which j-tile within a pair
    int bSel = ((lane >> 3) & 1);       // k16-half
    int bRow = (lane & 7);

    load_stage(0); cp_commit();
    load_stage(1); cp_commit();

    for (int it = 0; it < NCH; it++) {
        cp_wait<1>();
        __syncthreads();

        uint32_t st = sb + (it & 1) * STAGE;
#pragma unroll
        for (int kk = 0; kk < 4; kk++) {
            uint32_t afh[2][4], afl[2][4], bfh[4][2], bfl[4][2];
#pragma unroll
            for (int i = 0; i < 2; i++) {
                int row = wm * 32 + i * 16 + aRow;
                int chunk = (kk * 2 + aSel) ^ (row & 7);
                uint32_t off = row * 128 + chunk * 16;
                ldsm_x4(afh[i][0], afh[i][1], afh[i][2], afh[i][3], st + OFF_AH + off);
                ldsm_x4(afl[i][0], afl[i][1], afl[i][2], afl[i][3], st + OFF_AL + off);
            }
#pragma unroll
            for (int jp = 0; jp < 2; jp++) {
                int row = wn * 32 + jp * 16 + bTile * 8 + bRow;
                int chunk = (kk * 2 + bSel) ^ (row & 7);
                uint32_t off = row * 128 + chunk * 16;
                ldsm_x4(bfh[jp * 2][0], bfh[jp * 2][1], bfh[jp * 2 + 1][0], bfh[jp * 2 + 1][1],
                        st + OFF_BH + off);
                ldsm_x4(bfl[jp * 2][0], bfl[jp * 2][1], bfl[jp * 2 + 1][0], bfl[jp * 2 + 1][1],
                        st + OFF_BL + off);
            }
            // pass-major: consecutive MMAs hit different accumulators (8-deep ILP)
#pragma unroll
            for (int i = 0; i < 2; i++)
#pragma unroll
                for (int j = 0; j < 4; j++) mma16816(acc[i][j], afh[i], bfh[j]);
#pragma unroll
            for (int i = 0; i < 2; i++)
#pragma unroll
                for (int j = 0; j < 4; j++) mma16816(acc[i][j], afl[i], bfh[j]);
#pragma unroll
            for (int i = 0; i < 2; i++)
#pragma unroll
                for (int j = 0; j < 4; j++) mma16816(acc[i][j], afh[i], bfl[j]);
        }
        __syncthreads();
        if (it + 2 < NCH) load_stage(it + 2);
        cp_commit();
    }

    // ---------------- epilogue ----------------
    int cRow = lane >> 2;            // 0..7
    int cCol = (lane & 3) * 2;       // even
    if (EPI == 1) {
        float2* ab = (float2*)Cout;
#pragma unroll
        for (int j = 0; j < 4; j++) {
            int col = n0 + wn * 32 + j * 8 + cCol;
            int d = col >> 1;
            float hid4[4], gt4[4];
            int rows[4];
#pragma unroll
            for (int i = 0; i < 2; i++) {
                int r0 = m0 + wm * 32 + i * 16 + cRow;
                rows[i * 2]     = r0;
                rows[i * 2 + 1] = r0 + 8;
                hid4[i * 2]     = acc[i][j][0];
                gt4[i * 2]      = acc[i][j][1];
                hid4[i * 2 + 1] = acc[i][j][2];
                gt4[i * 2 + 1]  = acc[i][j][3];
            }
            float av[4], bv[4];
            mingru4(hid4, gt4, av, bv);
#pragma unroll
            for (int k = 0; k < 4; k++)
                ab[(size_t)rows[k] * DD + d] = make_float2(av[k], bv[k]);
        }
    } else {
#pragma unroll
        for (int i = 0; i < 2; i++) {
#pragma unroll
            for (int j = 0; j < 4; j++) {
                int r0 = m0 + wm * 32 + i * 16 + cRow;
                int r1 = r0 + 8;
                int col = n0 + wn * 32 + j * 8 + cCol;
                float c0 = acc[i][j][0], c1 = acc[i][j][1];
                float c2 = acc[i][j][2], c3 = acc[i][j][3];
                if (EPI == 2) {
                    const float2* rr0 = (const float2*)(Res + (size_t)r0 * DD + col);
                    const float2* rr1 = (const float2*)(Res + (size_t)r1 * DD + col);
                    float2 v0 = rr0[0], v1 = rr1[0];
                    *(float2*)(Cout + (size_t)r0 * DD + col) = make_float2(c0 + v0.x, c1 + v0.y);
                    *(float2*)(Cout + (size_t)r1 * DD + col) = make_float2(c2 + v1.x, c3 + v1.y);
                } else {
                    if (col < NBYTE) {
                        Cout[(size_t)r0 * NBYTE + col] = c0;
                        Cout[(size_t)r1 * NBYTE + col] = c2;
                    }
                    if (col + 1 < NBYTE) {
                        Cout[(size_t)r0 * NBYTE + col + 1] = c1;
                        Cout[(size_t)r1 * NBYTE + col + 1] = c3;
                    }
                }
            }
        }
    }
}

// ---------------- weight prep: [K,N] fp32 -> transposed [Npad,K] bf16 hi/lo ----------------
__global__ void k_wprep(const float* __restrict__ W, __nv_bfloat16* __restrict__ Wh,
                        __nv_bfloat16* __restrict__ Wl, int N, int mode, int nvalid) {
    __shared__ float tile[32][33];
    int n0 = blockIdx.x * 32, k0 = blockIdx.y * 32;
    int tx = threadIdx.x, ty = threadIdx.y;
    int n = n0 + tx;
    float v = 0.f;
    if (n < nvalid) {
        int src = (mode == 1) ? ((n & 1) ? (N >> 1) + (n >> 1) : (n >> 1)) : n;
        v = W[(size_t)(k0 + ty) * N + src];
    }
    tile[ty][tx] = v;
    __syncthreads();
    int on = n0 + ty, ok = k0 + tx;
    float w = tile[tx][ty];
    __nv_bfloat16 hi, lo;
    split_bf16(w, hi, lo);
    Wh[(size_t)on * GK + ok] = hi;
    Wl[(size_t)on * GK + ok] = lo;
}

// ---------------- embed + rmsnorm fused ----------------
__global__ void k_embed_rms(const int* __restrict__ ids, const float* __restrict__ tok,
                            const float* __restrict__ hsh, const float* __restrict__ nw,
                            float* __restrict__ x, __nv_bfloat16* __restrict__ xh,
                            __nv_bfloat16* __restrict__ xl) {
    int bs = blockIdx.x;
    int s = bs & (SS - 1);
    int t0 = ids[bs];
    int acc = t0, p = 31;
#pragma unroll
    for (int j = 1; j < 4; j++) {
        if (s >= j) acc += ids[bs - j] * p;
        p *= 31;
    }
    int hid = acc & HASHMASK;
    const float* tr = tok + (size_t)t0 * DD;
    const float* hr = hsh + (size_t)hid * DD;
    float vals[3];
    float ss = 0.f;
#pragma unroll
    for (int i = 0; i < 3; i++) {
        int d = threadIdx.x + i * 256;
        float v = tr[d] + hr[d];
        vals[i] = v;
        ss += v * v;
    }
    __shared__ float red[8];
#pragma unroll
    for (int o = 16; o > 0; o >>= 1) ss += __shfl_xor_sync(~0u, ss, o);
    if ((threadIdx.x & 31) == 0) red[threadIdx.x >> 5] = ss;
    __syncthreads();
    if (threadIdx.x == 0) {
        float v = 0.f;
#pragma unroll
        for (int i = 0; i < 8; i++) v += red[i];
        red[0] = rsqrtf(v / DD + 1e-6f);
    }
    __syncthreads();
    float r = red[0];
    size_t rb = (size_t)bs * DD;
#pragma unroll
    for (int i = 0; i < 3; i++) {
        int d = threadIdx.x + i * 256;
        x[rb + d] = vals[i];
        float v = vals[i] * r * nw[d];
        __nv_bfloat16 hi, lo;
        split_bf16(v, hi, lo);
        xh[rb + d] = hi;
        xl[rb + d] = lo;
    }
}

// ---------------- gadd + rmsnorm fused ----------------
__global__ void k_gadd_rms(const float* __restrict__ y, const float* __restrict__ patch,
                           const int* __restrict__ pid, const float* __restrict__ nw,
                           float* __restrict__ x, __nv_bfloat16* __restrict__ xh,
                           __nv_bfloat16* __restrict__ xl) {
    int bs = blockIdx.x;
    int b = bs / SS;
    const float* pr = patch + (size_t)(b * PP + pid[bs]) * DD;
    const float* yr = y + (size_t)bs * DD;
    float vals[3];
    float ss = 0.f;
#pragma unroll
    for (int i = 0; i < 3; i++) {
        int d = threadIdx.x + i * 256;
        float v = yr[d] + pr[d];
        vals[i] = v;
        ss += v * v;
    }
    __shared__ float red[8];
#pragma unroll
    for (int o = 16; o > 0; o >>= 1) ss += __shfl_xor_sync(~0u, ss, o);
    if ((threadIdx.x & 31) == 0) red[threadIdx.x >> 5] = ss;
    __syncthreads();
    if (threadIdx.x == 0) {
        float v = 0.f;
#pragma unroll
        for (int i = 0; i < 8; i++) v += red[i];
        red[0] = rsqrtf(v / DD + 1e-6f);
    }
    __syncthreads();
    float r = red[0];
    size_t rb = (size_t)bs * DD;
#pragma unroll
    for (int i = 0; i < 3; i++) {
        int d = threadIdx.x + i * 256;
        x[rb + d] = vals[i];
        float v = vals[i] * r * nw[d];
        __nv_bfloat16 hi, lo;
        split_bf16(v, hi, lo);
        xh[rb + d] = hi;
        xl[rb + d] = lo;
    }
}

// ---------------- final rmsnorm (bf16 hi/lo only) ----------------
__global__ void k_rms_b(const float* __restrict__ y, const float* __restrict__ nw,
                        __nv_bfloat16* __restrict__ xh, __nv_bfloat16* __restrict__ xl) {
    int bs = blockIdx.x;
    const float* yr = y + (size_t)bs * DD;
    float vals[3];
    float ss = 0.f;
#pragma unroll
    for (int i = 0; i < 3; i++) {
        int d = threadIdx.x + i * 256;
        float v = yr[d];
        vals[i] = v;
        ss += v * v;
    }
    __shared__ float red[8];
#pragma unroll
    for (int o = 16; o > 0; o >>= 1) ss += __shfl_xor_sync(~0u, ss, o);
    if ((threadIdx.x & 31) == 0) red[threadIdx.x >> 5] = ss;
    __syncthreads();
    if (threadIdx.x == 0) {
        float v = 0.f;
#pragma unroll
        for (int i = 0; i < 8; i++) v += red[i];
        red[0] = rsqrtf(v / DD + 1e-6f);
    }
    __syncthreads();
    float r = red[0];
    size_t rb = (size_t)bs * DD;
#pragma unroll
    for (int i = 0; i < 3; i++) {
        int d = threadIdx.x + i * 256;
        float v = vals[i] * r * nw[d];
        __nv_bfloat16 hi, lo;
        split_bf16(v, hi, lo);
        xh[rb + d] = hi;
        xl[rb + d] = lo;
    }
}

// ---------------- minGRU scan over precomputed (a,b) ----------------
__global__ void k_scan_red(const float2* __restrict__ ab, float2* __restrict__ carry) {
    int idx = blockIdx.x * 256 + threadIdx.x;
    int d = idx % DD;
    int bc = idx / DD;
    int b = bc % BB;
    int c = bc / BB;
    const float2* base = ab + (size_t)(b * SS + c * LL) * DD + d;
    float A = 1.f, Bv = 0.f;
#pragma unroll 4
    for (int t = 0; t < LL; t++) {
        float2 v = *base;
        base += DD;
        A *= v.x;
        Bv = fmaf(v.x, Bv, v.y);
    }
    carry[idx] = make_float2(A, Bv);
}

__global__ void k_scan_carry(const float2* __restrict__ carry, float* __restrict__ hinit) {
    int ch = blockIdx.x * 256 + threadIdx.x;
    int d = ch % DD;
    int b = ch / DD;
    float h = 0.f;
#pragma unroll
    for (int c = 0; c < CC; c++) {
        int i = (c * BB + b) * DD + d;
        hinit[i] = h;
        float2 abv = carry[i];
        h = fmaf(abv.x, h, abv.y);
    }
}

__global__ void k_scan_apply(const float2* __restrict__ ab, const float* __restrict__ hinit,
                             __nv_bfloat16* __restrict__ hh, __nv_bfloat16* __restrict__ hl) {
    int idx = blockIdx.x * 256 + threadIdx.x;
    int d = idx % DD;
    int bc = idx / DD;
    int b = bc % BB;
    int c = bc / BB;
    size_t off = (size_t)(b * SS + c * LL) * DD + d;
    const float2* base = ab + off;
    float h = hinit[idx];
#pragma unroll 4
    for (int t = 0; t < LL; t++) {
        float2 v = *base;
        base += DD;
        h = fmaf(v.x, h, v.y);
        __nv_bfloat16 hi, lo;
        split_bf16(h, hi, lo);
        hh[off] = hi;
        hl[off] = lo;
        off += DD;
    }
}

// ---------------- patch bookkeeping ----------------
__global__ void k_cum(const int* __restrict__ lens, int* __restrict__ cum) {
    int b = blockIdx.x;
    if (threadIdx.x == 0) {
        int s = 0;
        for (int p = 0; p < PP; p++) {
            s += lens[b * PP + p];
            cum[b * PP + p] = s;
        }
    }
}

__global__ void k_pid(const int* __restrict__ cum, int* __restrict__ pid) {
    int i = blockIdx.x * 256 + threadIdx.x;
    if (i >= BS) return;
    int b = i / SS;
    int pos = i % SS;
    const int* c = cum + b * PP;
    int lo = 0, hi = PP;
    while (lo < hi) {
        int mid = (lo + hi) >> 1;
        if (c[mid] <= pos) lo = mid + 1;
        else hi = mid;
    }
    pid[i] = lo;
}

__global__ void k_segmax(const float* __restrict__ y, const int* __restrict__ cum,
                         float* __restrict__ patch) {
    int bp = blockIdx.x;
    int b = bp / PP, p = bp % PP;
    int start = p ? cum[b * PP + p - 1] : 0;
    int end = cum[b * PP + p];
    const float* yb = y + (size_t)b * SS * DD;
    float* orow = patch + (size_t)bp * DD;
    for (int d = threadIdx.x; d < DD; d += 256) {
        float m = -3.402823466e38f;
        for (int s = start; s < end; s++)
            m = fmaxf(m, yb[(size_t)s * DD + d]);
        orow[d] = m;
    }
}

// ---------------- launch ----------------
extern "C" void kernel_launch(void* const* d_in, const int* in_sizes, int n_in,
                              void* d_out, int out_size) {
    const int*   ids      = (const int*)d_in[0];
    const int*   lens     = (const int*)d_in[1];
    const float* tok      = (const float*)d_in[2];
    const float* hsh      = (const float*)d_in[3];
    const float* enc_nw   = (const float*)d_in[4];
    const float* enc_whg  = (const float*)d_in[5];
    const float* enc_wout = (const float*)d_in[6];
    const float* dec_nw   = (const float*)d_in[7];
    const float* dec_whg  = (const float*)d_in[8];
    const float* dec_wout = (const float*)d_in[9];
    const float* fin_nw   = (const float*)d_in[10];
    const float* oproj    = (const float*)d_in[11];
    float*       out      = (float*)d_out;

    float* base = nullptr;
    cudaGetSymbolAddress((void**)&base, g_scratch);
    float*         x     = base + OFF_X;
    float*         y     = base + OFF_Y;
    float2*        ab    = (float2*)(base + OFF_AB);
    __nv_bfloat16* xh    = (__nv_bfloat16*)(base + OFF_XH);
    __nv_bfloat16* xl    = (__nv_bfloat16*)(base + OFF_XL);
    __nv_bfloat16* hh    = (__nv_bfloat16*)(base + OFF_HH);
    __nv_bfloat16* hl    = (__nv_bfloat16*)(base + OFF_HL);
    float*         patch = base + OFF_PAT;
    float2*        carry = (float2*)(base + OFF_CAR);
    float*         hinit = base + OFF_HIN;
    int*           cum   = (int*)(base + OFF_CUM);
    int*           pid   = (int*)(base + OFF_PID);
    __nv_bfloat16* wHGhe = (__nv_bfloat16*)(base + OFF_WHGHE);
    __nv_bfloat16* wHGle = (__nv_bfloat16*)(base + OFF_WHGLE);
    __nv_bfloat16* wOUhe = (__nv_bfloat16*)(base + OFF_WOUHE);
    __nv_bfloat16* wOUle = (__nv_bfloat16*)(base + OFF_WOULE);
    __nv_bfloat16* wHGhd = (__nv_bfloat16*)(base + OFF_WHGHD);
    __nv_bfloat16* wHGld = (__nv_bfloat16*)(base + OFF_WHGLD);
    __nv_bfloat16* wOUhd = (__nv_bfloat16*)(base + OFF_WOUHD);
    __nv_bfloat16* wOUld = (__nv_bfloat16*)(base + OFF_WOULD);
    __nv_bfloat16* wLGh  = (__nv_bfloat16*)(base + OFF_WLGH);
    __nv_bfloat16* wLGl  = (__nv_bfloat16*)(base + OFF_WLGL);

    constexpr int SMEM = 2 * (2 * 128 * 128 + 2 * 64 * 128);  // 98304 bytes
    cudaFuncSetAttribute(k_hgemm<1>, cudaFuncAttributeMaxDynamicSharedMemorySize, SMEM);
    cudaFuncSetAttribute(k_hgemm<2>, cudaFuncAttributeMaxDynamicSharedMemorySize, SMEM);
    cudaFuncSetAttribute(k_hgemm<3>, cudaFuncAttributeMaxDynamicSharedMemorySize, SMEM);

    dim3 tb(32, 32);
    k_cum<<<BB, 32>>>(lens, cum);
    k_pid<<<(BS + 255) / 256, 256>>>(cum, pid);
    k_embed_rms<<<BS, 256>>>(ids, tok, hsh, enc_nw, x, xh, xl);
    k_wprep<<<dim3(1536 / 32, GK / 32), tb>>>(enc_whg, wHGhe, wHGle, 1536, 1, 1536);
    k_wprep<<<dim3(768 / 32, GK / 32), tb>>>(enc_wout, wOUhe, wOUle, 768, 0, 768);

    // ---- encoder block ----
    k_hgemm<1><<<dim3(24, 128), 256, SMEM>>>(xh, xl, wHGhe, wHGle, nullptr, (float*)ab);
    k_scan_red<<<CBD / 256, 256>>>(ab, carry);
    k_scan_carry<<<(BB * DD) / 256, 256>>>(carry, hinit);
    k_scan_apply<<<CBD / 256, 256>>>(ab, hinit, hh, hl);
    k_hgemm<2><<<dim3(12, 128), 256, SMEM>>>(hh, hl, wOUhe, wOUle, x, y);

    // remaining weight preps
    k_wprep<<<dim3(1536 / 32, GK / 32), tb>>>(dec_whg, wHGhd, wHGld, 1536, 1, 1536);
    k_wprep<<<dim3(768 / 32, GK / 32), tb>>>(dec_wout, wOUhd, wOUld, 768, 0, 768);
    k_wprep<<<dim3(NLOGPAD / 32, GK / 32), tb>>>(oproj, wLGh, wLGl, NBYTE, 0, NBYTE);

    // ---- patch pooling + decoder input ----
    k_segmax<<<BB * PP, 256>>>(y, cum, patch);
    k_gadd_rms<<<BS, 256>>>(y, patch, pid, dec_nw, x, xh, xl);

    // ---- decoder block ----
    k_hgemm<1><<<dim3(24, 128), 256, SMEM>>>(xh, xl, wHGhd, wHGld, nullptr, (float*)ab);
    k_scan_red<<<CBD / 256, 256>>>(ab, carry);
    k_scan_carry<<<(BB * DD) / 256, 256>>>(carry, hinit);
    k_scan_apply<<<CBD / 256, 256>>>(ab, hinit, hh, hl);
    k_hgemm<2><<<dim3(12, 128), 256, SMEM>>>(hh, hl, wOUhd, wOUld, x, y);

    // ---- final norm + logits (5 N-tiles cover 260 of 320) ----
    k_rms_b<<<BS, 256>>>(y, fin_nw, xh, xl);
    k_hgemm<3><<<dim3(5, 128), 256, SMEM>>>(xh, xl, wLGh, wLGl, nullptr, out);
}

// round 15
// speedup vs baseline: 3.2370x; 1.0397x over previous
#include <cuda_runtime.h>
#include <cuda_bf16.h>
#include <math.h>
#include <stdint.h>

// ---------------- problem constants ----------------
constexpr int BB = 4;
constexpr int SS = 4096;
constexpr int DD = 768;
constexpr int PP = 683;
constexpr int NBYTE = 260;
constexpr int HASHMASK = 65535;     // HASH_VOCAB = 65536
constexpr int BS  = BB * SS;        // 16384 rows
constexpr int BSD = BS * DD;
constexpr int BPD = BB * PP * DD;
constexpr int CC  = 32;             // scan chunks
constexpr int LL  = SS / CC;        // 128
constexpr int CBD = CC * BB * DD;
constexpr int GK  = 768;            // GEMM K
constexpr int NLOGPAD = 384;        // logits weight rows padded

// ---------------- scratch layout (floats) ----------------
constexpr size_t OFF_X    = 0;
constexpr size_t OFF_Y    = OFF_X   + BSD;
constexpr size_t OFF_AB   = OFF_Y   + BSD;          // float2 [BS, DD]
constexpr size_t OFF_XH   = OFF_AB  + 2 * (size_t)BSD;
constexpr size_t OFF_XL   = OFF_XH  + BSD / 2;
constexpr size_t OFF_HH   = OFF_XL  + BSD / 2;
constexpr size_t OFF_HL   = OFF_HH  + BSD / 2;
constexpr size_t OFF_PAT  = OFF_HL  + BSD / 2;
constexpr size_t OFF_CAR  = OFF_PAT + BPD;          // float2 CBD
constexpr size_t OFF_HIN  = OFF_CAR + 2 * (size_t)CBD;
constexpr size_t OFF_CUM  = OFF_HIN + CBD;          // int
constexpr size_t OFF_PID  = OFF_CUM + BB * PP;      // int
constexpr size_t WHG_E    = 1536 * 768 / 2;         // bf16 elems / 2 = floats
constexpr size_t WOUT_E   = 768 * 768 / 2;
constexpr size_t WLOG_E   = (size_t)NLOGPAD * 768 / 2;
constexpr size_t OFF_WHGHE = OFF_PID + BS;
constexpr size_t OFF_WHGLE = OFF_WHGHE + WHG_E;
constexpr size_t OFF_WOUHE = OFF_WHGLE + WHG_E;
constexpr size_t OFF_WOULE = OFF_WOUHE + WOUT_E;
constexpr size_t OFF_WHGHD = OFF_WOULE + WOUT_E;
constexpr size_t OFF_WHGLD = OFF_WHGHD + WHG_E;
constexpr size_t OFF_WOUHD = OFF_WHGLD + WHG_E;
constexpr size_t OFF_WOULD = OFF_WOUHD + WOUT_E;
constexpr size_t OFF_WLGH  = OFF_WOULD + WOUT_E;
constexpr size_t OFF_WLGL  = OFF_WLGH + WLOG_E;
constexpr size_t SCRATCH_FLOATS = OFF_WLGL + WLOG_E + 64;
__device__ float g_scratch[SCRATCH_FLOATS];

// ---------------- PTX helpers (sm_100 baseline only) ----------------
__device__ __forceinline__ uint32_t s2u(const void* p) {
    uint32_t a;
    asm("{ .reg .u64 t; cvta.to.shared.u64 t, %1; cvt.u32.u64 %0, t; }" : "=r"(a) : "l"(p));
    return a;
}
__device__ __forceinline__ void cp16(uint32_t dst, const void* src) {
    asm volatile("cp.async.cg.shared.global [%0], [%1], 16;" :: "r"(dst), "l"(src));
}
__device__ __forceinline__ void cp_commit() { asm volatile("cp.async.commit_group;" ::: "memory"); }
template <int N>
__device__ __forceinline__ void cp_wait() { asm volatile("cp.async.wait_group %0;" :: "n"(N) : "memory"); }

__device__ __forceinline__ void ldsm_x4(uint32_t& r0, uint32_t& r1, uint32_t& r2, uint32_t& r3,
                                        uint32_t addr) {
    asm volatile("ldmatrix.sync.aligned.m8n8.x4.shared.b16 {%0,%1,%2,%3}, [%4];"
                 : "=r"(r0), "=r"(r1), "=r"(r2), "=r"(r3) : "r"(addr));
}
__device__ __forceinline__ void mma16816(float* c, const uint32_t* a, const uint32_t* b) {
    asm volatile(
        "mma.sync.aligned.m16n8k16.row.col.f32.bf16.bf16.f32 "
        "{%0,%1,%2,%3}, {%4,%5,%6,%7}, {%8,%9}, {%0,%1,%2,%3};"
        : "+f"(c[0]), "+f"(c[1]), "+f"(c[2]), "+f"(c[3])
        : "r"(a[0]), "r"(a[1]), "r"(a[2]), "r"(a[3]), "r"(b[0]), "r"(b[1]));
}

__device__ __forceinline__ uint32_t sw128(uint32_t o) { return o ^ ((o >> 3) & 0x70); }

__device__ __forceinline__ void split_bf16(float v, __nv_bfloat16& hi, __nv_bfloat16& lo) {
    hi = __float2bfloat16(v);
    lo = __float2bfloat16(v - __bfloat162float(hi));
}

// ---------------- batched minGRU coefficients (4 elements, 1 shared rcp) ----------------
__device__ __forceinline__ void mingru4(const float* hid4, const float* gt4,
                                        float* aout, float* bout) {
    float u[4], x[4], dd[4], e[4];
#pragma unroll
    for (int k = 0; k < 4; k++) {
        float g = fminf(fmaxf(gt4[k], -10.f), 10.f);
        u[k] = __expf(-g);
        x[k] = 1.f + u[k];
        float hm = fmaxf(fminf(hid4[k], 0.f), -10.f);
        e[k] = __expf(hm);
        dd[k] = (hid4[k] < 0.f) ? (1.f + e[k]) : 1.f;
    }
    float A0 = x[0] * dd[0], A1 = x[1] * dd[1];
    float A2 = x[2] * dd[2], A3 = x[3] * dd[3];
    float P01 = A0 * A1, P23 = A2 * A3;
    float W = __frcp_rn(P01 * P23);
    float W01 = W * P23, W23 = W * P01;
    float iA[4];
    iA[0] = W01 * A1; iA[1] = W01 * A0;
    iA[2] = W23 * A3; iA[3] = W23 * A2;
#pragma unroll
    for (int k = 0; k < 4; k++) {
        float ix = iA[k] * dd[k];          // sigmoid(g)
        aout[k] = u[k] * ix;               // sigmoid(-g)
        float gt_;
        if (hid4[k] >= 0.f) gt_ = hid4[k] + 0.5f;
        else                gt_ = e[k] * (iA[k] * x[k]);  // e/(1+e)
        bout[k] = ix * gt_;
    }
}

// ================= HMMA split-bf16 GEMM (128x96 tile, 2 CTAs/SM) =================
// BN=96 cuts A-operand staging traffic 1.5x vs BN=64 (L2->SMEM fill co-limiter).
// Per k-chunk: stage Ah,Al,Bh,Bl once; issue AhBh + AlBh + AhBl (pass-major).
// 256 threads, 8 warps (4x2), warp tile 32x48 (6 n8-tiles).
// Stage 56KB, double-buffered = 112KB/CTA -> 2 CTAs/SM (224KB).
// EPI: 1 = minGRU (a,b) from interleaved (hid,gate) cols -> ab float2 [BS,768]
//      2 = += Res, store fp32 [BS,768]
//      3 = logits, store fp32 [BS,260] col-guarded
template <int EPI>
__global__ void __launch_bounds__(256, 2)
k_hgemm(const __nv_bfloat16* __restrict__ Ah, const __nv_bfloat16* __restrict__ Al,
        const __nv_bfloat16* __restrict__ Bh, const __nv_bfloat16* __restrict__ Bl,
        const float* __restrict__ Res, float* __restrict__ Cout) {
    constexpr int KC = 64;               // bf16 per k-chunk (128 bytes)
    constexpr int NCH = GK / KC;         // 12
    constexpr int BN = 96;
    constexpr int MAT_A = 128 * 128;     // 16 KB
    constexpr int MAT_B = BN * 128;      // 12 KB
    constexpr int OFF_AH = 0;
    constexpr int OFF_AL = MAT_A;
    constexpr int OFF_BH = 2 * MAT_A;
    constexpr int OFF_BL = 2 * MAT_A + MAT_B;
    constexpr int STAGE  = 2 * MAT_A + 2 * MAT_B;   // 57344

    extern __shared__ char smem[];
    uint32_t sb = s2u(smem);

    int tid = threadIdx.x;
    int lane = tid & 31, wid = tid >> 5;
    int wm = wid >> 1, wn = wid & 1;     // warp tile: rows wm*32, cols wn*48
    int m0 = blockIdx.y * 128, n0 = blockIdx.x * BN;

    auto load_stage = [&](int kc) {
        uint32_t st = sb + (kc & 1) * STAGE;
        const __nv_bfloat16* ah = Ah + (size_t)m0 * GK + kc * KC;
        const __nv_bfloat16* al = Al + (size_t)m0 * GK + kc * KC;
        const __nv_bfloat16* bh = Bh + (size_t)n0 * GK + kc * KC;
        const __nv_bfloat16* bl = Bl + (size_t)n0 * GK + kc * KC;
#pragma unroll
        for (int i = 0; i < 4; i++) {          // A: 128 rows * 8 segs / 256 thr
            int idx = tid + i * 256;
            int r = idx >> 3, sg = idx & 7;
            uint32_t so = sw128(r * 128 + sg * 16);
            size_t go = (size_t)r * GK + sg * 8;
            cp16(st + OFF_AH + so, ah + go);
            cp16(st + OFF_AL + so, al + go);
        }
#pragma unroll
        for (int i = 0; i < 3; i++) {          // B: 96 rows * 8 segs / 256 thr
            int idx = tid + i * 256;
            int r = idx >> 3, sg = idx & 7;
            uint32_t so = sw128(r * 128 + sg * 16);
            size_t go = (size_t)r * GK + sg * 8;
            cp16(st + OFF_BH + so, bh + go);
            cp16(st + OFF_BL + so, bl + go);
        }
    };

    float acc[2][6][4];
#pragma unroll
    for (int i = 0; i < 2; i++)
#pragma unroll
        for (int j = 0; j < 6; j++)
#pragma unroll
            for (int q = 0; q < 4; q++) acc[i][j][q] = 0.f;

    int aRow = (lane & 15);
    int aSel = (lane >> 4);
    int bTile = (lane >> 4);            // which 8-row half within a 16-row pair
    int bSel = ((lane >> 3) & 1);       // k16-half
    int bRow = (lane & 7);

    load_stage(0); cp_commit();
    load_stage(1); cp_commit();

    for (int it = 0; it < NCH; it++) {
        cp_wait<1>();
        __syncthreads();

        uint32_t st = sb + (it & 1) * STAGE;
#pragma unroll
        for (int kk = 0; kk < 4; kk++) {
            uint32_t afh[2][4], afl[2][4], bfh[6][2], bfl[6][2];
#pragma unroll
            for (int i = 0; i < 2; i++) {
                int row = wm * 32 + i * 16 + aRow;
                int chunk = (kk * 2 + aSel) ^ (row & 7);
                uint32_t off = row * 128 + chunk * 16;
                ldsm_x4(afh[i][0], afh[i][1], afh[i][2], afh[i][3], st + OFF_AH + off);
                ldsm_x4(afl[i][0], afl[i][1], afl[i][2], afl[i][3], st + OFF_AL + off);
            }
#pragma unroll
            for (int jp = 0; jp < 3; jp++) {   // 3 pairs of n8-tiles = 48 cols
                int row = wn * 48 + jp * 16 + bTile * 8 + bRow;
                int chunk = (kk * 2 + bSel) ^ (row & 7);
                uint32_t off = row * 128 + chunk * 16;
                ldsm_x4(bfh[jp * 2][0], bfh[jp * 2][1], bfh[jp * 2 + 1][0], bfh[jp * 2 + 1][1],
                        st + OFF_BH + off);
                ldsm_x4(bfl[jp * 2][0], bfl[jp * 2][1], bfl[jp * 2 + 1][0], bfl[jp * 2 + 1][1],
                        st + OFF_BL + off);
            }
            // pass-major: consecutive MMAs hit different accumulators
#pragma unroll
            for (int i = 0; i < 2; i++)
#pragma unroll
                for (int j = 0; j < 6; j++) mma16816(acc[i][j], afh[i], bfh[j]);
#pragma unroll
            for (int i = 0; i < 2; i++)
#pragma unroll
                for (int j = 0; j < 6; j++) mma16816(acc[i][j], afl[i], bfh[j]);
#pragma unroll
            for (int i = 0; i < 2; i++)
#pragma unroll
                for (int j = 0; j < 6; j++) mma16816(acc[i][j], afh[i], bfl[j]);
        }
        __syncthreads();
        if (it + 2 < NCH) load_stage(it + 2);
        cp_commit();
    }

    // ---------------- epilogue ----------------
    int cRow = lane >> 2;            // 0..7
    int cCol = (lane & 3) * 2;       // even
    if (EPI == 1) {
        float2* ab = (float2*)Cout;
#pragma unroll
        for (int j = 0; j < 6; j++) {
            int col = n0 + wn * 48 + j * 8 + cCol;
            int d = col >> 1;
            float hid4[4], gt4[4];
            int rows[4];
#pragma unroll
            for (int i = 0; i < 2; i++) {
                int r0 = m0 + wm * 32 + i * 16 + cRow;
                rows[i * 2]     = r0;
                rows[i * 2 + 1] = r0 + 8;
                hid4[i * 2]     = acc[i][j][0];
                gt4[i * 2]      = acc[i][j][1];
                hid4[i * 2 + 1] = acc[i][j][2];
                gt4[i * 2 + 1]  = acc[i][j][3];
            }
            float av[4], bv[4];
            mingru4(hid4, gt4, av, bv);
#pragma unroll
            for (int k = 0; k < 4; k++)
                ab[(size_t)rows[k] * DD + d] = make_float2(av[k], bv[k]);
        }
    } else {
#pragma unroll
        for (int i = 0; i < 2; i++) {
#pragma unroll
            for (int j = 0; j < 6; j++) {
                int r0 = m0 + wm * 32 + i * 16 + cRow;
                int r1 = r0 + 8;
                int col = n0 + wn * 48 + j * 8 + cCol;
                float c0 = acc[i][j][0], c1 = acc[i][j][1];
                float c2 = acc[i][j][2], c3 = acc[i][j][3];
                if (EPI == 2) {
                    const float2* rr0 = (const float2*)(Res + (size_t)r0 * DD + col);
                    const float2* rr1 = (const float2*)(Res + (size_t)r1 * DD + col);
                    float2 v0 = rr0[0], v1 = rr1[0];
                    *(float2*)(Cout + (size_t)r0 * DD + col) = make_float2(c0 + v0.x, c1 + v0.y);
                    *(float2*)(Cout + (size_t)r1 * DD + col) = make_float2(c2 + v1.x, c3 + v1.y);
                } else {
                    if (col < NBYTE) {
                        Cout[(size_t)r0 * NBYTE + col] = c0;
                        Cout[(size_t)r1 * NBYTE + col] = c2;
                    }
                    if (col + 1 < NBYTE) {
                        Cout[(size_t)r0 * NBYTE + col + 1] = c1;
                        Cout[(size_t)r1 * NBYTE + col + 1] = c3;
                    }
                }
            }
        }
    }
}

// ---------------- weight prep: [K,N] fp32 -> transposed [Npad,K] bf16 hi/lo ----------------
__global__ void k_wprep(const float* __restrict__ W, __nv_bfloat16* __restrict__ Wh,
                        __nv_bfloat16* __restrict__ Wl, int N, int mode, int nvalid) {
    __shared__ float tile[32][33];
    int n0 = blockIdx.x * 32, k0 = blockIdx.y * 32;
    int tx = threadIdx.x, ty = threadIdx.y;
    int n = n0 + tx;
    float v = 0.f;
    if (n < nvalid) {
        int src = (mode == 1) ? ((n & 1) ? (N >> 1) + (n >> 1) : (n >> 1)) : n;
        v = W[(size_t)(k0 + ty) * N + src];
    }
    tile[ty][tx] = v;
    __syncthreads();
    int on = n0 + ty, ok = k0 + tx;
    float w = tile[tx][ty];
    __nv_bfloat16 hi, lo;
    split_bf16(w, hi, lo);
    Wh[(size_t)on * GK + ok] = hi;
    Wl[(size_t)on * GK + ok] = lo;
}

// ---------------- embed + rmsnorm fused ----------------
__global__ void k_embed_rms(const int* __restrict__ ids, const float* __restrict__ tok,
                            const float* __restrict__ hsh, const float* __restrict__ nw,
                            float* __restrict__ x, __nv_bfloat16* __restrict__ xh,
                            __nv_bfloat16* __restrict__ xl) {
    int bs = blockIdx.x;
    int s = bs & (SS - 1);
    int t0 = ids[bs];
    int acc = t0, p = 31;
#pragma unroll
    for (int j = 1; j < 4; j++) {
        if (s >= j) acc += ids[bs - j] * p;
        p *= 31;
    }
    int hid = acc & HASHMASK;
    const float* tr = tok + (size_t)t0 * DD;
    const float* hr = hsh + (size_t)hid * DD;
    float vals[3];
    float ss = 0.f;
#pragma unroll
    for (int i = 0; i < 3; i++) {
        int d = threadIdx.x + i * 256;
        float v = tr[d] + hr[d];
        vals[i] = v;
        ss += v * v;
    }
    __shared__ float red[8];
#pragma unroll
    for (int o = 16; o > 0; o >>= 1) ss += __shfl_xor_sync(~0u, ss, o);
    if ((threadIdx.x & 31) == 0) red[threadIdx.x >> 5] = ss;
    __syncthreads();
    if (threadIdx.x == 0) {
        float v = 0.f;
#pragma unroll
        for (int i = 0; i < 8; i++) v += red[i];
        red[0] = rsqrtf(v / DD + 1e-6f);
    }
    __syncthreads();
    float r = red[0];
    size_t rb = (size_t)bs * DD;
#pragma unroll
    for (int i = 0; i < 3; i++) {
        int d = threadIdx.x + i * 256;
        x[rb + d] = vals[i];
        float v = vals[i] * r * nw[d];
        __nv_bfloat16 hi, lo;
        split_bf16(v, hi, lo);
        xh[rb + d] = hi;
        xl[rb + d] = lo;
    }
}

// ---------------- gadd + rmsnorm fused ----------------
__global__ void k_gadd_rms(const float* __restrict__ y, const float* __restrict__ patch,
                           const int* __restrict__ pid, const float* __restrict__ nw,
                           float* __restrict__ x, __nv_bfloat16* __restrict__ xh,
                           __nv_bfloat16* __restrict__ xl) {
    int bs = blockIdx.x;
    int b = bs / SS;
    const float* pr = patch + (size_t)(b * PP + pid[bs]) * DD;
    const float* yr = y + (size_t)bs * DD;
    float vals[3];
    float ss = 0.f;
#pragma unroll
    for (int i = 0; i < 3; i++) {
        int d = threadIdx.x + i * 256;
        float v = yr[d] + pr[d];
        vals[i] = v;
        ss += v * v;
    }
    __shared__ float red[8];
#pragma unroll
    for (int o = 16; o > 0; o >>= 1) ss += __shfl_xor_sync(~0u, ss, o);
    if ((threadIdx.x & 31) == 0) red[threadIdx.x >> 5] = ss;
    __syncthreads();
    if (threadIdx.x == 0) {
        float v = 0.f;
#pragma unroll
        for (int i = 0; i < 8; i++) v += red[i];
        red[0] = rsqrtf(v / DD + 1e-6f);
    }
    __syncthreads();
    float r = red[0];
    size_t rb = (size_t)bs * DD;
#pragma unroll
    for (int i = 0; i < 3; i++) {
        int d = threadIdx.x + i * 256;
        x[rb + d] = vals[i];
        float v = vals[i] * r * nw[d];
        __nv_bfloat16 hi, lo;
        split_bf16(v, hi, lo);
        xh[rb + d] = hi;
        xl[rb + d] = lo;
    }
}

// ---------------- final rmsnorm (bf16 hi/lo only) ----------------
__global__ void k_rms_b(const float* __restrict__ y, const float* __restrict__ nw,
                        __nv_bfloat16* __restrict__ xh, __nv_bfloat16* __restrict__ xl) {
    int bs = blockIdx.x;
    const float* yr = y + (size_t)bs * DD;
    float vals[3];
    float ss = 0.f;
#pragma unroll
    for (int i = 0; i < 3; i++) {
        int d = threadIdx.x + i * 256;
        float v = yr[d];
        vals[i] = v;
        ss += v * v;
    }
    __shared__ float red[8];
#pragma unroll
    for (int o = 16; o > 0; o >>= 1) ss += __shfl_xor_sync(~0u, ss, o);
    if ((threadIdx.x & 31) == 0) red[threadIdx.x >> 5] = ss;
    __syncthreads();
    if (threadIdx.x == 0) {
        float v = 0.f;
#pragma unroll
        for (int i = 0; i < 8; i++) v += red[i];
        red[0] = rsqrtf(v / DD + 1e-6f);
    }
    __syncthreads();
    float r = red[0];
    size_t rb = (size_t)bs * DD;
#pragma unroll
    for (int i = 0; i < 3; i++) {
        int d = threadIdx.x + i * 256;
        float v = vals[i] * r * nw[d];
        __nv_bfloat16 hi, lo;
        split_bf16(v, hi, lo);
        xh[rb + d] = hi;
        xl[rb + d] = lo;
    }
}

// ---------------- minGRU scan over precomputed (a,b) ----------------
__global__ void k_scan_red(const float2* __restrict__ ab, float2* __restrict__ carry) {
    int idx = blockIdx.x * 256 + threadIdx.x;
    int d = idx % DD;
    int bc = idx / DD;
    int b = bc % BB;
    int c = bc / BB;
    const float2* base = ab + (size_t)(b * SS + c * LL) * DD + d;
    float A = 1.f, Bv = 0.f;
#pragma unroll 4
    for (int t = 0; t < LL; t++) {
        float2 v = *base;
        base += DD;
        A *= v.x;
        Bv = fmaf(v.x, Bv, v.y);
    }
    carry[idx] = make_float2(A, Bv);
}

__global__ void k_scan_carry(const float2* __restrict__ carry, float* __restrict__ hinit) {
    int ch = blockIdx.x * 256 + threadIdx.x;
    int d = ch % DD;
    int b = ch / DD;
    float h = 0.f;
#pragma unroll
    for (int c = 0; c < CC; c++) {
        int i = (c * BB + b) * DD + d;
        hinit[i] = h;
        float2 abv = carry[i];
        h = fmaf(abv.x, h, abv.y);
    }
}

__global__ void k_scan_apply(const float2* __restrict__ ab, const float* __restrict__ hinit,
                             __nv_bfloat16* __restrict__ hh, __nv_bfloat16* __restrict__ hl) {
    int idx = blockIdx.x * 256 + threadIdx.x;
    int d = idx % DD;
    int bc = idx / DD;
    int b = bc % BB;
    int c = bc / BB;
    size_t off = (size_t)(b * SS + c * LL) * DD + d;
    const float2* base = ab + off;
    float h = hinit[idx];
#pragma unroll 4
    for (int t = 0; t < LL; t++) {
        float2 v = *base;
        base += DD;
        h = fmaf(v.x, h, v.y);
        __nv_bfloat16 hi, lo;
        split_bf16(h, hi, lo);
        hh[off] = hi;
        hl[off] = lo;
        off += DD;
    }
}

// ---------------- patch bookkeeping ----------------
__global__ void k_cum(const int* __restrict__ lens, int* __restrict__ cum) {
    int b = blockIdx.x;
    if (threadIdx.x == 0) {
        int s = 0;
        for (int p = 0; p < PP; p++) {
            s += lens[b * PP + p];
            cum[b * PP + p] = s;
        }
    }
}

__global__ void k_pid(const int* __restrict__ cum, int* __restrict__ pid) {
    int i = blockIdx.x * 256 + threadIdx.x;
    if (i >= BS) return;
    int b = i / SS;
    int pos = i % SS;
    const int* c = cum + b * PP;
    int lo = 0, hi = PP;
    while (lo < hi) {
        int mid = (lo + hi) >> 1;
        if (c[mid] <= pos) lo = mid + 1;
        else hi = mid;
    }
    pid[i] = lo;
}

__global__ void k_segmax(const float* __restrict__ y, const int* __restrict__ cum,
                         float* __restrict__ patch) {
    int bp = blockIdx.x;
    int b = bp / PP, p = bp % PP;
    int start = p ? cum[b * PP + p - 1] : 0;
    int end = cum[b * PP + p];
    const float* yb = y + (size_t)b * SS * DD;
    float* orow = patch + (size_t)bp * DD;
    for (int d = threadIdx.x; d < DD; d += 256) {
        float m = -3.402823466e38f;
        for (int s = start; s < end; s++)
            m = fmaxf(m, yb[(size_t)s * DD + d]);
        orow[d] = m;
    }
}

// ---------------- launch ----------------
extern "C" void kernel_launch(void* const* d_in, const int* in_sizes, int n_in,
                              void* d_out, int out_size) {
    const int*   ids      = (const int*)d_in[0];
    const int*   lens     = (const int*)d_in[1];
    const float* tok      = (const float*)d_in[2];
    const float* hsh      = (const float*)d_in[3];
    const float* enc_nw   = (const float*)d_in[4];
    const float* enc_whg  = (const float*)d_in[5];
    const float* enc_wout = (const float*)d_in[6];
    const float* dec_nw   = (const float*)d_in[7];
    const float* dec_whg  = (const float*)d_in[8];
    const float* dec_wout = (const float*)d_in[9];
    const float* fin_nw   = (const float*)d_in[10];
    const float* oproj    = (const float*)d_in[11];
    float*       out      = (float*)d_out;

    float* base = nullptr;
    cudaGetSymbolAddress((void**)&base, g_scratch);
    float*         x     = base + OFF_X;
    float*         y     = base + OFF_Y;
    float2*        ab    = (float2*)(base + OFF_AB);
    __nv_bfloat16* xh    = (__nv_bfloat16*)(base + OFF_XH);
    __nv_bfloat16* xl    = (__nv_bfloat16*)(base + OFF_XL);
    __nv_bfloat16* hh    = (__nv_bfloat16*)(base + OFF_HH);
    __nv_bfloat16* hl    = (__nv_bfloat16*)(base + OFF_HL);
    float*         patch = base + OFF_PAT;
    float2*        carry = (float2*)(base + OFF_CAR);
    float*         hinit = base + OFF_HIN;
    int*           cum   = (int*)(base + OFF_CUM);
    int*           pid   = (int*)(base + OFF_PID);
    __nv_bfloat16* wHGhe = (__nv_bfloat16*)(base + OFF_WHGHE);
    __nv_bfloat16* wHGle = (__nv_bfloat16*)(base + OFF_WHGLE);
    __nv_bfloat16* wOUhe = (__nv_bfloat16*)(base + OFF_WOUHE);
    __nv_bfloat16* wOUle = (__nv_bfloat16*)(base + OFF_WOULE);
    __nv_bfloat16* wHGhd = (__nv_bfloat16*)(base + OFF_WHGHD);
    __nv_bfloat16* wHGld = (__nv_bfloat16*)(base + OFF_WHGLD);
    __nv_bfloat16* wOUhd = (__nv_bfloat16*)(base + OFF_WOUHD);
    __nv_bfloat16* wOUld = (__nv_bfloat16*)(base + OFF_WOULD);
    __nv_bfloat16* wLGh  = (__nv_bfloat16*)(base + OFF_WLGH);
    __nv_bfloat16* wLGl  = (__nv_bfloat16*)(base + OFF_WLGL);

    constexpr int SMEM = 2 * (2 * 128 * 128 + 2 * 96 * 128);  // 114688 bytes
    cudaFuncSetAttribute(k_hgemm<1>, cudaFuncAttributeMaxDynamicSharedMemorySize, SMEM);
    cudaFuncSetAttribute(k_hgemm<2>, cudaFuncAttributeMaxDynamicSharedMemorySize, SMEM);
    cudaFuncSetAttribute(k_hgemm<3>, cudaFuncAttributeMaxDynamicSharedMemorySize, SMEM);

    dim3 tb(32, 32);
    k_cum<<<BB, 32>>>(lens, cum);
    k_pid<<<(BS + 255) / 256, 256>>>(cum, pid);
    k_embed_rms<<<BS, 256>>>(ids, tok, hsh, enc_nw, x, xh, xl);
    k_wprep<<<dim3(1536 / 32, GK / 32), tb>>>(enc_whg, wHGhe, wHGle, 1536, 1, 1536);
    k_wprep<<<dim3(768 / 32, GK / 32), tb>>>(enc_wout, wOUhe, wOUle, 768, 0, 768);

    // ---- encoder block ----
    k_hgemm<1><<<dim3(16, 128), 256, SMEM>>>(xh, xl, wHGhe, wHGle, nullptr, (float*)ab);
    k_scan_red<<<CBD / 256, 256>>>(ab, carry);
    k_scan_carry<<<(BB * DD) / 256, 256>>>(carry, hinit);
    k_scan_apply<<<CBD / 256, 256>>>(ab, hinit, hh, hl);
    k_hgemm<2><<<dim3(8, 128), 256, SMEM>>>(hh, hl, wOUhe, wOUle, x, y);

    // remaining weight preps
    k_wprep<<<dim3(1536 / 32, GK / 32), tb>>>(dec_whg, wHGhd, wHGld, 1536, 1, 1536);
    k_wprep<<<dim3(768 / 32, GK / 32), tb>>>(dec_wout, wOUhd, wOUld, 768, 0, 768);
    k_wprep<<<dim3(NLOGPAD / 32, GK / 32), tb>>>(oproj, wLGh, wLGl, NBYTE, 0, NBYTE);

    // ---- patch pooling + decoder input ----
    k_segmax<<<BB * PP, 256>>>(y, cum, patch);
    k_gadd_rms<<<BS, 256>>>(y, patch, pid, dec_nw, x, xh, xl);

    // ---- decoder block ----
    k_hgemm<1><<<dim3(16, 128), 256, SMEM>>>(xh, xl, wHGhd, wHGld, nullptr, (float*)ab);
    k_scan_red<<<CBD / 256, 256>>>(ab, carry);
    k_scan_carry<<<(BB * DD) / 256, 256>>>(carry, hinit);
    k_scan_apply<<<CBD / 256, 256>>>(ab, hinit, hh, hl);
    k_hgemm<2><<<dim3(8, 128), 256, SMEM>>>(hh, hl, wOUhd, wOUld, x, y);

    // ---- final norm + logits (3 N-tiles cover 260 of 288) ----
    k_rms_b<<<BS, 256>>>(y, fin_nw, xh, xl);
    k_hgemm<3><<<dim3(3, 128), 256, SMEM>>>(xh, xl, wLGh, wLGl, nullptr, out);
}

// round 16
// speedup vs baseline: 4.1572x; 1.2843x over previous
#include <cuda_runtime.h>
#include <cuda_fp16.h>
#include <math.h>
#include <stdint.h>

// ---------------- problem constants ----------------
constexpr int BB = 4;
constexpr int SS = 4096;
constexpr int DD = 768;
constexpr int PP = 683;
constexpr int NBYTE = 260;
constexpr int HASHMASK = 65535;     // HASH_VOCAB = 65536
constexpr int BS  = BB * SS;        // 16384 rows
constexpr int BSD = BS * DD;
constexpr int BPD = BB * PP * DD;
constexpr int CC  = 32;             // scan chunks
constexpr int LL  = SS / CC;        // 128
constexpr int CBD = CC * BB * DD;
constexpr int GK  = 768;            // GEMM K
constexpr int NLOGPAD = 384;        // logits weight rows padded

// ---------------- scratch layout (floats) ----------------
constexpr size_t OFF_X    = 0;
constexpr size_t OFF_Y    = OFF_X   + BSD;
constexpr size_t OFF_AB   = OFF_Y   + BSD;          // float2 [BS, DD]
constexpr size_t OFF_XH   = OFF_AB  + 2 * (size_t)BSD;
constexpr size_t OFF_XL   = OFF_XH  + BSD / 2;
constexpr size_t OFF_HH   = OFF_XL  + BSD / 2;
constexpr size_t OFF_HL   = OFF_HH  + BSD / 2;
constexpr size_t OFF_PAT  = OFF_HL  + BSD / 2;
constexpr size_t OFF_CAR  = OFF_PAT + BPD;          // float2 CBD
constexpr size_t OFF_HIN  = OFF_CAR + 2 * (size_t)CBD;
constexpr size_t OFF_CUM  = OFF_HIN + CBD;          // int
constexpr size_t OFF_PID  = OFF_CUM + BB * PP;      // int
constexpr size_t WHG_E    = 1536 * 768 / 2;         // fp16 elems / 2 = floats
constexpr size_t WOUT_E   = 768 * 768 / 2;
constexpr size_t WLOG_E   = (size_t)NLOGPAD * 768 / 2;
constexpr size_t OFF_WHGE = OFF_PID + BS;
constexpr size_t OFF_WOUE = OFF_WHGE + WHG_E;
constexpr size_t OFF_WHGD = OFF_WOUE + WOUT_E;
constexpr size_t OFF_WOUD = OFF_WHGD + WHG_E;
constexpr size_t OFF_WLG  = OFF_WOUD + WOUT_E;
constexpr size_t SCRATCH_FLOATS = OFF_WLG + WLOG_E + 64;
__device__ float g_scratch[SCRATCH_FLOATS];

// ---------------- PTX helpers (sm_100 baseline only) ----------------
__device__ __forceinline__ uint32_t s2u(const void* p) {
    uint32_t a;
    asm("{ .reg .u64 t; cvta.to.shared.u64 t, %1; cvt.u32.u64 %0, t; }" : "=r"(a) : "l"(p));
    return a;
}
__device__ __forceinline__ void cp16(uint32_t dst, const void* src) {
    asm volatile("cp.async.cg.shared.global [%0], [%1], 16;" :: "r"(dst), "l"(src));
}
__device__ __forceinline__ void cp_commit() { asm volatile("cp.async.commit_group;" ::: "memory"); }
template <int N>
__device__ __forceinline__ void cp_wait() { asm volatile("cp.async.wait_group %0;" :: "n"(N) : "memory"); }

__device__ __forceinline__ void ldsm_x4(uint32_t& r0, uint32_t& r1, uint32_t& r2, uint32_t& r3,
                                        uint32_t addr) {
    asm volatile("ldmatrix.sync.aligned.m8n8.x4.shared.b16 {%0,%1,%2,%3}, [%4];"
                 : "=r"(r0), "=r"(r1), "=r"(r2), "=r"(r3) : "r"(addr));
}
__device__ __forceinline__ void mma16816(float* c, const uint32_t* a, const uint32_t* b) {
    asm volatile(
        "mma.sync.aligned.m16n8k16.row.col.f32.f16.f16.f32 "
        "{%0,%1,%2,%3}, {%4,%5,%6,%7}, {%8,%9}, {%0,%1,%2,%3};"
        : "+f"(c[0]), "+f"(c[1]), "+f"(c[2]), "+f"(c[3])
        : "r"(a[0]), "r"(a[1]), "r"(a[2]), "r"(a[3]), "r"(b[0]), "r"(b[1]));
}

__device__ __forceinline__ uint32_t sw128(uint32_t o) { return o ^ ((o >> 3) & 0x70); }

__device__ __forceinline__ void split_fp16(float v, __half& hi, __half& lo) {
    hi = __float2half_rn(v);
    lo = __float2half_rn(v - __half2float(hi));
}

// ---------------- batched minGRU coefficients (4 elements, 1 shared rcp) ----------------
__device__ __forceinline__ void mingru4(const float* hid4, const float* gt4,
                                        float* aout, float* bout) {
    float u[4], x[4], dd[4], e[4];
#pragma unroll
    for (int k = 0; k < 4; k++) {
        float g = fminf(fmaxf(gt4[k], -10.f), 10.f);
        u[k] = __expf(-g);
        x[k] = 1.f + u[k];
        float hm = fmaxf(fminf(hid4[k], 0.f), -10.f);
        e[k] = __expf(hm);
        dd[k] = (hid4[k] < 0.f) ? (1.f + e[k]) : 1.f;
    }
    float A0 = x[0] * dd[0], A1 = x[1] * dd[1];
    float A2 = x[2] * dd[2], A3 = x[3] * dd[3];
    float P01 = A0 * A1, P23 = A2 * A3;
    float W = __frcp_rn(P01 * P23);
    float W01 = W * P23, W23 = W * P01;
    float iA[4];
    iA[0] = W01 * A1; iA[1] = W01 * A0;
    iA[2] = W23 * A3; iA[3] = W23 * A2;
#pragma unroll
    for (int k = 0; k < 4; k++) {
        float ix = iA[k] * dd[k];          // sigmoid(g)
        aout[k] = u[k] * ix;               // sigmoid(-g)
        float gt_;
        if (hid4[k] >= 0.f) gt_ = hid4[k] + 0.5f;
        else                gt_ = e[k] * (iA[k] * x[k]);  // e/(1+e)
        bout[k] = ix * gt_;
    }
}

// ================= HMMA split-fp16 GEMM (128x128 tile, 2 CTAs/SM) =================
// fp16 2-pass: x = xh + xl (both fp16), weights single fp16.
// C = xh@W^T + xl@W^T; dropped term x*werr ~2^-12 rel (weights RTN half-ulp).
// 256 threads, 8 warps (4x2), warp tile 32x64 (8 n8-tiles).
// Stage 48KB (Ah|Al|Bw), double-buffered = 96KB/CTA -> 2 CTAs/SM.
// B frags loaded in 2 halves of 32 cols to bound live registers.
// EPI: 1 = minGRU (a,b) from interleaved (hid,gate) cols -> ab float2 [BS,768]
//      2 = += Res, store fp32 [BS,768]
//      3 = logits, store fp32 [BS,260] col-guarded
template <int EPI>
__global__ void __launch_bounds__(256, 2)
k_hgemm(const __half* __restrict__ Ah, const __half* __restrict__ Al,
        const __half* __restrict__ Bw,
        const float* __restrict__ Res, float* __restrict__ Cout) {
    constexpr int KC = 64;               // fp16 per k-chunk (128 bytes)
    constexpr int NCH = GK / KC;         // 12
    constexpr int MAT = 128 * 128;       // 16 KB per matrix tile
    constexpr int OFF_AHs = 0;
    constexpr int OFF_ALs = MAT;
    constexpr int OFF_BWs = 2 * MAT;
    constexpr int STAGE   = 3 * MAT;     // 49152

    extern __shared__ char smem[];
    uint32_t sb = s2u(smem);

    int tid = threadIdx.x;
    int lane = tid & 31, wid = tid >> 5;
    int wm = wid >> 1, wn = wid & 1;     // warp tile: rows wm*32, cols wn*64
    int m0 = blockIdx.y * 128, n0 = blockIdx.x * 128;

    auto load_stage = [&](int kc) {
        uint32_t st = sb + (kc & 1) * STAGE;
        const __half* ah = Ah + (size_t)m0 * GK + kc * KC;
        const __half* al = Al + (size_t)m0 * GK + kc * KC;
        const __half* bw = Bw + (size_t)n0 * GK + kc * KC;
#pragma unroll
        for (int i = 0; i < 4; i++) {          // 128 rows * 8 segs / 256 thr
            int idx = tid + i * 256;
            int r = idx >> 3, sg = idx & 7;
            uint32_t so = sw128(r * 128 + sg * 16);
            size_t go = (size_t)r * GK + sg * 8;
            cp16(st + OFF_AHs + so, ah + go);
            cp16(st + OFF_ALs + so, al + go);
            cp16(st + OFF_BWs + so, bw + go);
        }
    };

    float acc[2][8][4];
#pragma unroll
    for (int i = 0; i < 2; i++)
#pragma unroll
        for (int j = 0; j < 8; j++)
#pragma unroll
            for (int q = 0; q < 4; q++) acc[i][j][q] = 0.f;

    int aRow = (lane & 15);
    int aSel = (lane >> 4);
    int bTile = (lane >> 4);            // which 8-row half within a 16-row pair
    int bSel = ((lane >> 3) & 1);       // k16-half
    int bRow = (lane & 7);

    load_stage(0); cp_commit();
    load_stage(1); cp_commit();

    for (int it = 0; it < NCH; it++) {
        cp_wait<1>();
        __syncthreads();

        uint32_t st = sb + (it & 1) * STAGE;
#pragma unroll
        for (int kk = 0; kk < 4; kk++) {
            uint32_t afh[2][4], afl[2][4];
#pragma unroll
            for (int i = 0; i < 2; i++) {
                int row = wm * 32 + i * 16 + aRow;
                int chunk = (kk * 2 + aSel) ^ (row & 7);
                uint32_t off = row * 128 + chunk * 16;
                ldsm_x4(afh[i][0], afh[i][1], afh[i][2], afh[i][3], st + OFF_AHs + off);
                ldsm_x4(afl[i][0], afl[i][1], afl[i][2], afl[i][3], st + OFF_ALs + off);
            }
            // process B tile in 2 halves of 32 cols to bound live registers
#pragma unroll
            for (int jh = 0; jh < 2; jh++) {
                uint32_t bf[4][2];
#pragma unroll
                for (int jp = 0; jp < 2; jp++) {
                    int row = wn * 64 + jh * 32 + jp * 16 + bTile * 8 + bRow;
                    int chunk = (kk * 2 + bSel) ^ (row & 7);
                    uint32_t off = row * 128 + chunk * 16;
                    ldsm_x4(bf[jp * 2][0], bf[jp * 2][1], bf[jp * 2 + 1][0], bf[jp * 2 + 1][1],
                            st + OFF_BWs + off);
                }
                // pass-major: 8 independent accumulators between RAW reuse
#pragma unroll
                for (int i = 0; i < 2; i++)
#pragma unroll
                    for (int j = 0; j < 4; j++) mma16816(acc[i][jh * 4 + j], afh[i], bf[j]);
#pragma unroll
                for (int i = 0; i < 2; i++)
#pragma unroll
                    for (int j = 0; j < 4; j++) mma16816(acc[i][jh * 4 + j], afl[i], bf[j]);
            }
        }
        __syncthreads();
        if (it + 2 < NCH) load_stage(it + 2);
        cp_commit();
    }

    // ---------------- epilogue ----------------
    int cRow = lane >> 2;            // 0..7
    int cCol = (lane & 3) * 2;       // even
    if (EPI == 1) {
        float2* ab = (float2*)Cout;
#pragma unroll
        for (int j = 0; j < 8; j++) {
            int col = n0 + wn * 64 + j * 8 + cCol;
            int d = col >> 1;
            float hid4[4], gt4[4];
            int rows[4];
#pragma unroll
            for (int i = 0; i < 2; i++) {
                int r0 = m0 + wm * 32 + i * 16 + cRow;
                rows[i * 2]     = r0;
                rows[i * 2 + 1] = r0 + 8;
                hid4[i * 2]     = acc[i][j][0];
                gt4[i * 2]      = acc[i][j][1];
                hid4[i * 2 + 1] = acc[i][j][2];
                gt4[i * 2 + 1]  = acc[i][j][3];
            }
            float av[4], bv[4];
            mingru4(hid4, gt4, av, bv);
#pragma unroll
            for (int k = 0; k < 4; k++)
                ab[(size_t)rows[k] * DD + d] = make_float2(av[k], bv[k]);
        }
    } else {
#pragma unroll
        for (int i = 0; i < 2; i++) {
#pragma unroll
            for (int j = 0; j < 8; j++) {
                int r0 = m0 + wm * 32 + i * 16 + cRow;
                int r1 = r0 + 8;
                int col = n0 + wn * 64 + j * 8 + cCol;
                float c0 = acc[i][j][0], c1 = acc[i][j][1];
                float c2 = acc[i][j][2], c3 = acc[i][j][3];
                if (EPI == 2) {
                    const float2* rr0 = (const float2*)(Res + (size_t)r0 * DD + col);
                    const float2* rr1 = (const float2*)(Res + (size_t)r1 * DD + col);
                    float2 v0 = rr0[0], v1 = rr1[0];
                    *(float2*)(Cout + (size_t)r0 * DD + col) = make_float2(c0 + v0.x, c1 + v0.y);
                    *(float2*)(Cout + (size_t)r1 * DD + col) = make_float2(c2 + v1.x, c3 + v1.y);
                } else {
                    if (col < NBYTE) {
                        Cout[(size_t)r0 * NBYTE + col] = c0;
                        Cout[(size_t)r1 * NBYTE + col] = c2;
                    }
                    if (col + 1 < NBYTE) {
                        Cout[(size_t)r0 * NBYTE + col + 1] = c1;
                        Cout[(size_t)r1 * NBYTE + col + 1] = c3;
                    }
                }
            }
        }
    }
}

// ---------------- weight prep: [K,N] fp32 -> transposed [Npad,K] fp16 ----------------
__global__ void k_wprep(const float* __restrict__ W, __half* __restrict__ Wo,
                        int N, int mode, int nvalid) {
    __shared__ float tile[32][33];
    int n0 = blockIdx.x * 32, k0 = blockIdx.y * 32;
    int tx = threadIdx.x, ty = threadIdx.y;
    int n = n0 + tx;
    float v = 0.f;
    if (n < nvalid) {
        int src = (mode == 1) ? ((n & 1) ? (N >> 1) + (n >> 1) : (n >> 1)) : n;
        v = W[(size_t)(k0 + ty) * N + src];
    }
    tile[ty][tx] = v;
    __syncthreads();
    int on = n0 + ty, ok = k0 + tx;
    Wo[(size_t)on * GK + ok] = __float2half_rn(tile[tx][ty]);
}

// ---------------- embed + rmsnorm fused ----------------
__global__ void k_embed_rms(const int* __restrict__ ids, const float* __restrict__ tok,
                            const float* __restrict__ hsh, const float* __restrict__ nw,
                            float* __restrict__ x, __half* __restrict__ xh,
                            __half* __restrict__ xl) {
    int bs = blockIdx.x;
    int s = bs & (SS - 1);
    int t0 = ids[bs];
    int acc = t0, p = 31;
#pragma unroll
    for (int j = 1; j < 4; j++) {
        if (s >= j) acc += ids[bs - j] * p;
        p *= 31;
    }
    int hid = acc & HASHMASK;
    const float* tr = tok + (size_t)t0 * DD;
    const float* hr = hsh + (size_t)hid * DD;
    float vals[3];
    float ss = 0.f;
#pragma unroll
    for (int i = 0; i < 3; i++) {
        int d = threadIdx.x + i * 256;
        float v = tr[d] + hr[d];
        vals[i] = v;
        ss += v * v;
    }
    __shared__ float red[8];
#pragma unroll
    for (int o = 16; o > 0; o >>= 1) ss += __shfl_xor_sync(~0u, ss, o);
    if ((threadIdx.x & 31) == 0) red[threadIdx.x >> 5] = ss;
    __syncthreads();
    if (threadIdx.x == 0) {
        float v = 0.f;
#pragma unroll
        for (int i = 0; i < 8; i++) v += red[i];
        red[0] = rsqrtf(v / DD + 1e-6f);
    }
    __syncthreads();
    float r = red[0];
    size_t rb = (size_t)bs * DD;
#pragma unroll
    for (int i = 0; i < 3; i++) {
        int d = threadIdx.x + i * 256;
        x[rb + d] = vals[i];
        float v = vals[i] * r * nw[d];
        __half hi, lo;
        split_fp16(v, hi, lo);
        xh[rb + d] = hi;
        xl[rb + d] = lo;
    }
}

// ---------------- gadd + rmsnorm fused ----------------
__global__ void k_gadd_rms(const float* __restrict__ y, const float* __restrict__ patch,
                           const int* __restrict__ pid, const float* __restrict__ nw,
                           float* __restrict__ x, __half* __restrict__ xh,
                           __half* __restrict__ xl) {
    int bs = blockIdx.x;
    int b = bs / SS;
    const float* pr = patch + (size_t)(b * PP + pid[bs]) * DD;
    const float* yr = y + (size_t)bs * DD;
    float vals[3];
    float ss = 0.f;
#pragma unroll
    for (int i = 0; i < 3; i++) {
        int d = threadIdx.x + i * 256;
        float v = yr[d] + pr[d];
        vals[i] = v;
        ss += v * v;
    }
    __shared__ float red[8];
#pragma unroll
    for (int o = 16; o > 0; o >>= 1) ss += __shfl_xor_sync(~0u, ss, o);
    if ((threadIdx.x & 31) == 0) red[threadIdx.x >> 5] = ss;
    __syncthreads();
    if (threadIdx.x == 0) {
        float v = 0.f;
#pragma unroll
        for (int i = 0; i < 8; i++) v += red[i];
        red[0] = rsqrtf(v / DD + 1e-6f);
    }
    __syncthreads();
    float r = red[0];
    size_t rb = (size_t)bs * DD;
#pragma unroll
    for (int i = 0; i < 3; i++) {
        int d = threadIdx.x + i * 256;
        x[rb + d] = vals[i];
        float v = vals[i] * r * nw[d];
        __half hi, lo;
        split_fp16(v, hi, lo);
        xh[rb + d] = hi;
        xl[rb + d] = lo;
    }
}

// ---------------- final rmsnorm (fp16 hi/lo only) ----------------
__global__ void k_rms_b(const float* __restrict__ y, const float* __restrict__ nw,
                        __half* __restrict__ xh, __half* __restrict__ xl) {
    int bs = blockIdx.x;
    const float* yr = y + (size_t)bs * DD;
    float vals[3];
    float ss = 0.f;
#pragma unroll
    for (int i = 0; i < 3; i++) {
        int d = threadIdx.x + i * 256;
        float v = yr[d];
        vals[i] = v;
        ss += v * v;
    }
    __shared__ float red[8];
#pragma unroll
    for (int o = 16; o > 0; o >>= 1) ss += __shfl_xor_sync(~0u, ss, o);
    if ((threadIdx.x & 31) == 0) red[threadIdx.x >> 5] = ss;
    __syncthreads();
    if (threadIdx.x == 0) {
        float v = 0.f;
#pragma unroll
        for (int i = 0; i < 8; i++) v += red[i];
        red[0] = rsqrtf(v / DD + 1e-6f);
    }
    __syncthreads();
    float r = red[0];
    size_t rb = (size_t)bs * DD;
#pragma unroll
    for (int i = 0; i < 3; i++) {
        int d = threadIdx.x + i * 256;
        float v = vals[i] * r * nw[d];
        __half hi, lo;
        split_fp16(v, hi, lo);
        xh[rb + d] = hi;
        xl[rb + d] = lo;
    }
}

// ---------------- minGRU scan over precomputed (a,b) ----------------
__global__ void k_scan_red(const float2* __restrict__ ab, float2* __restrict__ carry) {
    int idx = blockIdx.x * 256 + threadIdx.x;
    int d = idx % DD;
    int bc = idx / DD;
    int b = bc % BB;
    int c = bc / BB;
    const float2* base = ab + (size_t)(b * SS + c * LL) * DD + d;
    float A = 1.f, Bv = 0.f;
#pragma unroll 4
    for (int t = 0; t < LL; t++) {
        float2 v = *base;
        base += DD;
        A *= v.x;
        Bv = fmaf(v.x, Bv, v.y);
    }
    carry[idx] = make_float2(A, Bv);
}

__global__ void k_scan_carry(const float2* __restrict__ carry, float* __restrict__ hinit) {
    int ch = blockIdx.x * 256 + threadIdx.x;
    int d = ch % DD;
    int b = ch / DD;
    float h = 0.f;
#pragma unroll
    for (int c = 0; c < CC; c++) {
        int i = (c * BB + b) * DD + d;
        hinit[i] = h;
        float2 abv = carry[i];
        h = fmaf(abv.x, h, abv.y);
    }
}

__global__ void k_scan_apply(const float2* __restrict__ ab, const float* __restrict__ hinit,
                             __half* __restrict__ hh, __half* __restrict__ hl) {
    int idx = blockIdx.x * 256 + threadIdx.x;
    int d = idx % DD;
    int bc = idx / DD;
    int b = bc % BB;
    int c = bc / BB;
    size_t off = (size_t)(b * SS + c * LL) * DD + d;
    const float2* base = ab + off;
    float h = hinit[idx];
#pragma unroll 4
    for (int t = 0; t < LL; t++) {
        float2 v = *base;
        base += DD;
        h = fmaf(v.x, h, v.y);
        __half hi, lo;
        split_fp16(h, hi, lo);
        hh[off] = hi;
        hl[off] = lo;
        off += DD;
    }
}

// ---------------- patch bookkeeping ----------------
__global__ void k_cum(const int* __restrict__ lens, int* __restrict__ cum) {
    int b = blockIdx.x;
    if (threadIdx.x == 0) {
        int s = 0;
        for (int p = 0; p < PP; p++) {
            s += lens[b * PP + p];
            cum[b * PP + p] = s;
        }
    }
}

__global__ void k_pid(const int* __restrict__ cum, int* __restrict__ pid) {
    int i = blockIdx.x * 256 + threadIdx.x;
    if (i >= BS) return;
    int b = i / SS;
    int pos = i % SS;
    const int* c = cum + b * PP;
    int lo = 0, hi = PP;
    while (lo < hi) {
        int mid = (lo + hi) >> 1;
        if (c[mid] <= pos) lo = mid + 1;
        else hi = mid;
    }
    pid[i] = lo;
}

__global__ void k_segmax(const float* __restrict__ y, const int* __restrict__ cum,
                         float* __restrict__ patch) {
    int bp = blockIdx.x;
    int b = bp / PP, p = bp % PP;
    int start = p ? cum[b * PP + p - 1] : 0;
    int end = cum[b * PP + p];
    const float* yb = y + (size_t)b * SS * DD;
    float* orow = patch + (size_t)bp * DD;
    for (int d = threadIdx.x; d < DD; d += 256) {
        float m = -3.402823466e38f;
        for (int s = start; s < end; s++)
            m = fmaxf(m, yb[(size_t)s * DD + d]);
        orow[d] = m;
    }
}

// ---------------- launch ----------------
extern "C" void kernel_launch(void* const* d_in, const int* in_sizes, int n_in,
                              void* d_out, int out_size) {
    const int*   ids      = (const int*)d_in[0];
    const int*   lens     = (const int*)d_in[1];
    const float* tok      = (const float*)d_in[2];
    const float* hsh      = (const float*)d_in[3];
    const float* enc_nw   = (const float*)d_in[4];
    const float* enc_whg  = (const float*)d_in[5];
    const float* enc_wout = (const float*)d_in[6];
    const float* dec_nw   = (const float*)d_in[7];
    const float* dec_whg  = (const float*)d_in[8];
    const float* dec_wout = (const float*)d_in[9];
    const float* fin_nw   = (const float*)d_in[10];
    const float* oproj    = (const float*)d_in[11];
    float*       out      = (float*)d_out;

    float* base = nullptr;
    cudaGetSymbolAddress((void**)&base, g_scratch);
    float*   x     = base + OFF_X;
    float*   y     = base + OFF_Y;
    float2*  ab    = (float2*)(base + OFF_AB);
    __half*  xh    = (__half*)(base + OFF_XH);
    __half*  xl    = (__half*)(base + OFF_XL);
    __half*  hh    = (__half*)(base + OFF_HH);
    __half*  hl    = (__half*)(base + OFF_HL);
    float*   patch = base + OFF_PAT;
    float2*  carry = (float2*)(base + OFF_CAR);
    float*   hinit = base + OFF_HIN;
    int*     cum   = (int*)(base + OFF_CUM);
    int*     pid   = (int*)(base + OFF_PID);
    __half*  wHGe  = (__half*)(base + OFF_WHGE);
    __half*  wOUe  = (__half*)(base + OFF_WOUE);
    __half*  wHGd  = (__half*)(base + OFF_WHGD);
    __half*  wOUd  = (__half*)(base + OFF_WOUD);
    __half*  wLG   = (__half*)(base + OFF_WLG);

    constexpr int SMEM = 2 * 3 * 128 * 128;  // 98304 bytes
    cudaFuncSetAttribute(k_hgemm<1>, cudaFuncAttributeMaxDynamicSharedMemorySize, SMEM);
    cudaFuncSetAttribute(k_hgemm<2>, cudaFuncAttributeMaxDynamicSharedMemorySize, SMEM);
    cudaFuncSetAttribute(k_hgemm<3>, cudaFuncAttributeMaxDynamicSharedMemorySize, SMEM);

    dim3 tb(32, 32);
    k_cum<<<BB, 32>>>(lens, cum);
    k_pid<<<(BS + 255) / 256, 256>>>(cum, pid);
    k_embed_rms<<<BS, 256>>>(ids, tok, hsh, enc_nw, x, xh, xl);
    k_wprep<<<dim3(1536 / 32, GK / 32), tb>>>(enc_whg, wHGe, 1536, 1, 1536);
    k_wprep<<<dim3(768 / 32, GK / 32), tb>>>(enc_wout, wOUe, 768, 0, 768);

    // ---- encoder block ----
    k_hgemm<1><<<dim3(12, 128), 256, SMEM>>>(xh, xl, wHGe, nullptr, (float*)ab);
    k_scan_red<<<CBD / 256, 256>>>(ab, carry);
    k_scan_carry<<<(BB * DD) / 256, 256>>>(carry, hinit);
    k_scan_apply<<<CBD / 256, 256>>>(ab, hinit, hh, hl);
    k_hgemm<2><<<dim3(6, 128), 256, SMEM>>>(hh, hl, wOUe, x, y);

    // remaining weight preps
    k_wprep<<<dim3(1536 / 32, GK / 32), tb>>>(dec_whg, wHGd, 1536, 1, 1536);
    k_wprep<<<dim3(768 / 32, GK / 32), tb>>>(dec_wout, wOUd, 768, 0, 768);
    k_wprep<<<dim3(NLOGPAD / 32, GK / 32), tb>>>(oproj, wLG, NBYTE, 0, NBYTE);

    // ---- patch pooling + decoder input ----
    k_segmax<<<BB * PP, 256>>>(y, cum, patch);
    k_gadd_rms<<<BS, 256>>>(y, patch, pid, dec_nw, x, xh, xl);

    // ---- decoder block ----
    k_hgemm<1><<<dim3(12, 128), 256, SMEM>>>(xh, xl, wHGd, nullptr, (float*)ab);
    k_scan_red<<<CBD / 256, 256>>>(ab, carry);
    k_scan_carry<<<(BB * DD) / 256, 256>>>(carry, hinit);
    k_scan_apply<<<CBD / 256, 256>>>(ab, hinit, hh, hl);
    k_hgemm<2><<<dim3(6, 128), 256, SMEM>>>(hh, hl, wOUd, x, y);

    // ---- final norm + logits (3 N-tiles cover 260 of 384) ----
    k_rms_b<<<BS, 256>>>(y, fin_nw, xh, xl);
    k_hgemm<3><<<dim3(3, 128), 256, SMEM>>>(xh, xl, wLG, nullptr, out);
}

// round 17
// speedup vs baseline: 4.5547x; 1.0956x over previous
#include <cuda_runtime.h>
#include <cuda_fp16.h>
#include <math.h>
#include <stdint.h>

// ---------------- problem constants ----------------
constexpr int BB = 4;
constexpr int SS = 4096;
constexpr int DD = 768;
constexpr int PP = 683;
constexpr int NBYTE = 260;
constexpr int HASHMASK = 65535;     // HASH_VOCAB = 65536
constexpr int BS  = BB * SS;        // 16384 rows
constexpr int BSD = BS * DD;
constexpr int BPD = BB * PP * DD;
constexpr int CC  = 32;             // scan chunks
constexpr int LL  = SS / CC;        // 128
constexpr int CBD = CC * BB * DD;
constexpr int GK  = 768;            // GEMM K
constexpr int NLOGPAD = 384;        // logits weight rows padded

// ---------------- scratch layout (floats) ----------------
constexpr size_t OFF_X    = 0;
constexpr size_t OFF_Y    = OFF_X   + BSD;
constexpr size_t OFF_AB   = OFF_Y   + BSD;          // float2 [BS, DD]
constexpr size_t OFF_XH   = OFF_AB  + 2 * (size_t)BSD;
constexpr size_t OFF_XL   = OFF_XH  + BSD / 2;
constexpr size_t OFF_HH   = OFF_XL  + BSD / 2;
constexpr size_t OFF_HL   = OFF_HH  + BSD / 2;      // unused now, kept for layout
constexpr size_t OFF_PAT  = OFF_HL  + BSD / 2;
constexpr size_t OFF_CAR  = OFF_PAT + BPD;          // float2 CBD
constexpr size_t OFF_HIN  = OFF_CAR + 2 * (size_t)CBD;
constexpr size_t OFF_CUM  = OFF_HIN + CBD;          // int
constexpr size_t OFF_PID  = OFF_CUM + BB * PP;      // int
constexpr size_t WHG_E    = 1536 * 768 / 2;         // fp16 elems / 2 = floats
constexpr size_t WOUT_E   = 768 * 768 / 2;
constexpr size_t WLOG_E   = (size_t)NLOGPAD * 768 / 2;
constexpr size_t OFF_WHGE = OFF_PID + BS;
constexpr size_t OFF_WOUE = OFF_WHGE + WHG_E;
constexpr size_t OFF_WHGD = OFF_WOUE + WOUT_E;
constexpr size_t OFF_WOUD = OFF_WHGD + WHG_E;
constexpr size_t OFF_WLG  = OFF_WOUD + WOUT_E;
constexpr size_t SCRATCH_FLOATS = OFF_WLG + WLOG_E + 64;
__device__ float g_scratch[SCRATCH_FLOATS];

// ---------------- PTX helpers (sm_100 baseline only) ----------------
__device__ __forceinline__ uint32_t s2u(const void* p) {
    uint32_t a;
    asm("{ .reg .u64 t; cvta.to.shared.u64 t, %1; cvt.u32.u64 %0, t; }" : "=r"(a) : "l"(p));
    return a;
}
__device__ __forceinline__ void cp16(uint32_t dst, const void* src) {
    asm volatile("cp.async.cg.shared.global [%0], [%1], 16;" :: "r"(dst), "l"(src));
}
__device__ __forceinline__ void cp_commit() { asm volatile("cp.async.commit_group;" ::: "memory"); }
template <int N>
__device__ __forceinline__ void cp_wait() { asm volatile("cp.async.wait_group %0;" :: "n"(N) : "memory"); }

__device__ __forceinline__ void ldsm_x4(uint32_t& r0, uint32_t& r1, uint32_t& r2, uint32_t& r3,
                                        uint32_t addr) {
    asm volatile("ldmatrix.sync.aligned.m8n8.x4.shared.b16 {%0,%1,%2,%3}, [%4];"
                 : "=r"(r0), "=r"(r1), "=r"(r2), "=r"(r3) : "r"(addr));
}
__device__ __forceinline__ void mma16816(float* c, const uint32_t* a, const uint32_t* b) {
    asm volatile(
        "mma.sync.aligned.m16n8k16.row.col.f32.f16.f16.f32 "
        "{%0,%1,%2,%3}, {%4,%5,%6,%7}, {%8,%9}, {%0,%1,%2,%3};"
        : "+f"(c[0]), "+f"(c[1]), "+f"(c[2]), "+f"(c[3])
        : "r"(a[0]), "r"(a[1]), "r"(a[2]), "r"(a[3]), "r"(b[0]), "r"(b[1]));
}

__device__ __forceinline__ uint32_t sw128(uint32_t o) { return o ^ ((o >> 3) & 0x70); }

__device__ __forceinline__ void split_fp16(float v, __half& hi, __half& lo) {
    hi = __float2half_rn(v);
    lo = __float2half_rn(v - __half2float(hi));
}

// ---------------- batched minGRU coefficients (4 elements, 1 shared rcp) ----------------
__device__ __forceinline__ void mingru4(const float* hid4, const float* gt4,
                                        float* aout, float* bout) {
    float u[4], x[4], dd[4], e[4];
#pragma unroll
    for (int k = 0; k < 4; k++) {
        float g = fminf(fmaxf(gt4[k], -10.f), 10.f);
        u[k] = __expf(-g);
        x[k] = 1.f + u[k];
        float hm = fmaxf(fminf(hid4[k], 0.f), -10.f);
        e[k] = __expf(hm);
        dd[k] = (hid4[k] < 0.f) ? (1.f + e[k]) : 1.f;
    }
    float A0 = x[0] * dd[0], A1 = x[1] * dd[1];
    float A2 = x[2] * dd[2], A3 = x[3] * dd[3];
    float P01 = A0 * A1, P23 = A2 * A3;
    float W = __frcp_rn(P01 * P23);
    float W01 = W * P23, W23 = W * P01;
    float iA[4];
    iA[0] = W01 * A1; iA[1] = W01 * A0;
    iA[2] = W23 * A3; iA[3] = W23 * A2;
#pragma unroll
    for (int k = 0; k < 4; k++) {
        float ix = iA[k] * dd[k];          // sigmoid(g)
        aout[k] = u[k] * ix;               // sigmoid(-g)
        float gt_;
        if (hid4[k] >= 0.f) gt_ = hid4[k] + 0.5f;
        else                gt_ = e[k] * (iA[k] * x[k]);  // e/(1+e)
        bout[k] = ix * gt_;
    }
}

// ================= HMMA split-fp16 GEMM (128x128 tile, 2 CTAs/SM) =================
// TWOP=true : x = xh + xl (both fp16), weights fp16; C = xh@W^T + xl@W^T.
// TWOP=false: single fp16 pass (used for GEMM2 where the fp32 residual dominates).
// 256 threads, 8 warps (4x2), warp tile 32x64 (8 n8-tiles).
// EPI: 1 = minGRU (a,b) from interleaved (hid,gate) cols -> ab float2 [BS,768]
//      2 = += Res, store fp32 [BS,768]
//      3 = logits, store fp32 [BS,260] col-guarded
template <int EPI, bool TWOP>
__global__ void __launch_bounds__(256, 2)
k_hgemm(const __half* __restrict__ Ah, const __half* __restrict__ Al,
        const __half* __restrict__ Bw,
        const float* __restrict__ Res, float* __restrict__ Cout) {
    constexpr int KC = 64;               // fp16 per k-chunk (128 bytes)
    constexpr int NCH = GK / KC;         // 12
    constexpr int MAT = 128 * 128;       // 16 KB per matrix tile
    constexpr int NMAT = TWOP ? 3 : 2;
    constexpr int OFF_AHs = 0;
    constexpr int OFF_BWs = (TWOP ? 2 : 1) * MAT;
    constexpr int OFF_ALs = MAT;         // only valid when TWOP
    constexpr int STAGE   = NMAT * MAT;

    extern __shared__ char smem[];
    uint32_t sb = s2u(smem);

    int tid = threadIdx.x;
    int lane = tid & 31, wid = tid >> 5;
    int wm = wid >> 1, wn = wid & 1;     // warp tile: rows wm*32, cols wn*64
    int m0 = blockIdx.y * 128, n0 = blockIdx.x * 128;

    auto load_stage = [&](int kc) {
        uint32_t st = sb + (kc & 1) * STAGE;
        const __half* ah = Ah + (size_t)m0 * GK + kc * KC;
        const __half* bw = Bw + (size_t)n0 * GK + kc * KC;
        const __half* al = TWOP ? (Al + (size_t)m0 * GK + kc * KC) : nullptr;
#pragma unroll
        for (int i = 0; i < 4; i++) {          // 128 rows * 8 segs / 256 thr
            int idx = tid + i * 256;
            int r = idx >> 3, sg = idx & 7;
            uint32_t so = sw128(r * 128 + sg * 16);
            size_t go = (size_t)r * GK + sg * 8;
            cp16(st + OFF_AHs + so, ah + go);
            if (TWOP) cp16(st + OFF_ALs + so, al + go);
            cp16(st + OFF_BWs + so, bw + go);
        }
    };

    float acc[2][8][4];
#pragma unroll
    for (int i = 0; i < 2; i++)
#pragma unroll
        for (int j = 0; j < 8; j++)
#pragma unroll
            for (int q = 0; q < 4; q++) acc[i][j][q] = 0.f;

    int aRow = (lane & 15);
    int aSel = (lane >> 4);
    int bTile = (lane >> 4);            // which 8-row half within a 16-row pair
    int bSel = ((lane >> 3) & 1);       // k16-half
    int bRow = (lane & 7);

    load_stage(0); cp_commit();
    load_stage(1); cp_commit();

    for (int it = 0; it < NCH; it++) {
        cp_wait<1>();
        __syncthreads();

        uint32_t st = sb + (it & 1) * STAGE;
#pragma unroll
        for (int kk = 0; kk < 4; kk++) {
            uint32_t afh[2][4], afl[2][4];
#pragma unroll
            for (int i = 0; i < 2; i++) {
                int row = wm * 32 + i * 16 + aRow;
                int chunk = (kk * 2 + aSel) ^ (row & 7);
                uint32_t off = row * 128 + chunk * 16;
                ldsm_x4(afh[i][0], afh[i][1], afh[i][2], afh[i][3], st + OFF_AHs + off);
                if (TWOP)
                    ldsm_x4(afl[i][0], afl[i][1], afl[i][2], afl[i][3], st + OFF_ALs + off);
            }
            // process B tile in 2 halves of 32 cols to bound live registers
#pragma unroll
            for (int jh = 0; jh < 2; jh++) {
                uint32_t bf[4][2];
#pragma unroll
                for (int jp = 0; jp < 2; jp++) {
                    int row = wn * 64 + jh * 32 + jp * 16 + bTile * 8 + bRow;
                    int chunk = (kk * 2 + bSel) ^ (row & 7);
                    uint32_t off = row * 128 + chunk * 16;
                    ldsm_x4(bf[jp * 2][0], bf[jp * 2][1], bf[jp * 2 + 1][0], bf[jp * 2 + 1][1],
                            st + OFF_BWs + off);
                }
#pragma unroll
                for (int i = 0; i < 2; i++)
#pragma unroll
                    for (int j = 0; j < 4; j++) mma16816(acc[i][jh * 4 + j], afh[i], bf[j]);
                if (TWOP) {
#pragma unroll
                    for (int i = 0; i < 2; i++)
#pragma unroll
                        for (int j = 0; j < 4; j++) mma16816(acc[i][jh * 4 + j], afl[i], bf[j]);
                }
            }
        }
        __syncthreads();
        if (it + 2 < NCH) load_stage(it + 2);
        cp_commit();
    }

    // ---------------- epilogue ----------------
    int cRow = lane >> 2;            // 0..7
    int cCol = (lane & 3) * 2;       // even
    if (EPI == 1) {
        float2* ab = (float2*)Cout;
#pragma unroll
        for (int j = 0; j < 8; j++) {
            int col = n0 + wn * 64 + j * 8 + cCol;
            int d = col >> 1;
            float hid4[4], gt4[4];
            int rows[4];
#pragma unroll
            for (int i = 0; i < 2; i++) {
                int r0 = m0 + wm * 32 + i * 16 + cRow;
                rows[i * 2]     = r0;
                rows[i * 2 + 1] = r0 + 8;
                hid4[i * 2]     = acc[i][j][0];
                gt4[i * 2]      = acc[i][j][1];
                hid4[i * 2 + 1] = acc[i][j][2];
                gt4[i * 2 + 1]  = acc[i][j][3];
            }
            float av[4], bv[4];
            mingru4(hid4, gt4, av, bv);
#pragma unroll
            for (int k = 0; k < 4; k++)
                ab[(size_t)rows[k] * DD + d] = make_float2(av[k], bv[k]);
        }
    } else {
#pragma unroll
        for (int i = 0; i < 2; i++) {
#pragma unroll
            for (int j = 0; j < 8; j++) {
                int r0 = m0 + wm * 32 + i * 16 + cRow;
                int r1 = r0 + 8;
                int col = n0 + wn * 64 + j * 8 + cCol;
                float c0 = acc[i][j][0], c1 = acc[i][j][1];
                float c2 = acc[i][j][2], c3 = acc[i][j][3];
                if (EPI == 2) {
                    const float2* rr0 = (const float2*)(Res + (size_t)r0 * DD + col);
                    const float2* rr1 = (const float2*)(Res + (size_t)r1 * DD + col);
                    float2 v0 = rr0[0], v1 = rr1[0];
                    *(float2*)(Cout + (size_t)r0 * DD + col) = make_float2(c0 + v0.x, c1 + v0.y);
                    *(float2*)(Cout + (size_t)r1 * DD + col) = make_float2(c2 + v1.x, c3 + v1.y);
                } else {
                    if (col < NBYTE) {
                        Cout[(size_t)r0 * NBYTE + col] = c0;
                        Cout[(size_t)r1 * NBYTE + col] = c2;
                    }
                    if (col + 1 < NBYTE) {
                        Cout[(size_t)r0 * NBYTE + col + 1] = c1;
                        Cout[(size_t)r1 * NBYTE + col + 1] = c3;
                    }
                }
            }
        }
    }
}

// ---------------- weight prep: [K,N] fp32 -> transposed [Npad,K] fp16 ----------------
__global__ void k_wprep(const float* __restrict__ W, __half* __restrict__ Wo,
                        int N, int mode, int nvalid) {
    __shared__ float tile[32][33];
    int n0 = blockIdx.x * 32, k0 = blockIdx.y * 32;
    int tx = threadIdx.x, ty = threadIdx.y;
    int n = n0 + tx;
    float v = 0.f;
    if (n < nvalid) {
        int src = (mode == 1) ? ((n & 1) ? (N >> 1) + (n >> 1) : (n >> 1)) : n;
        v = W[(size_t)(k0 + ty) * N + src];
    }
    tile[ty][tx] = v;
    __syncthreads();
    int on = n0 + ty, ok = k0 + tx;
    Wo[(size_t)on * GK + ok] = __float2half_rn(tile[tx][ty]);
}

// ---------------- embed + rmsnorm fused ----------------
__global__ void k_embed_rms(const int* __restrict__ ids, const float* __restrict__ tok,
                            const float* __restrict__ hsh, const float* __restrict__ nw,
                            float* __restrict__ x, __half* __restrict__ xh,
                            __half* __restrict__ xl) {
    int bs = blockIdx.x;
    int s = bs & (SS - 1);
    int t0 = ids[bs];
    int acc = t0, p = 31;
#pragma unroll
    for (int j = 1; j < 4; j++) {
        if (s >= j) acc += ids[bs - j] * p;
        p *= 31;
    }
    int hid = acc & HASHMASK;
    const float* tr = tok + (size_t)t0 * DD;
    const float* hr = hsh + (size_t)hid * DD;
    float vals[3];
    float ss = 0.f;
#pragma unroll
    for (int i = 0; i < 3; i++) {
        int d = threadIdx.x + i * 256;
        float v = tr[d] + hr[d];
        vals[i] = v;
        ss += v * v;
    }
    __shared__ float red[8];
#pragma unroll
    for (int o = 16; o > 0; o >>= 1) ss += __shfl_xor_sync(~0u, ss, o);
    if ((threadIdx.x & 31) == 0) red[threadIdx.x >> 5] = ss;
    __syncthreads();
    if (threadIdx.x == 0) {
        float v = 0.f;
#pragma unroll
        for (int i = 0; i < 8; i++) v += red[i];
        red[0] = rsqrtf(v / DD + 1e-6f);
    }
    __syncthreads();
    float r = red[0];
    size_t rb = (size_t)bs * DD;
#pragma unroll
    for (int i = 0; i < 3; i++) {
        int d = threadIdx.x + i * 256;
        x[rb + d] = vals[i];
        float v = vals[i] * r * nw[d];
        __half hi, lo;
        split_fp16(v, hi, lo);
        xh[rb + d] = hi;
        xl[rb + d] = lo;
    }
}

// ---------------- gadd + rmsnorm fused ----------------
__global__ void k_gadd_rms(const float* __restrict__ y, const float* __restrict__ patch,
                           const int* __restrict__ pid, const float* __restrict__ nw,
                           float* __restrict__ x, __half* __restrict__ xh,
                           __half* __restrict__ xl) {
    int bs = blockIdx.x;
    int b = bs / SS;
    const float* pr = patch + (size_t)(b * PP + pid[bs]) * DD;
    const float* yr = y + (size_t)bs * DD;
    float vals[3];
    float ss = 0.f;
#pragma unroll
    for (int i = 0; i < 3; i++) {
        int d = threadIdx.x + i * 256;
        float v = yr[d] + pr[d];
        vals[i] = v;
        ss += v * v;
    }
    __shared__ float red[8];
#pragma unroll
    for (int o = 16; o > 0; o >>= 1) ss += __shfl_xor_sync(~0u, ss, o);
    if ((threadIdx.x & 31) == 0) red[threadIdx.x >> 5] = ss;
    __syncthreads();
    if (threadIdx.x == 0) {
        float v = 0.f;
#pragma unroll
        for (int i = 0; i < 8; i++) v += red[i];
        red[0] = rsqrtf(v / DD + 1e-6f);
    }
    __syncthreads();
    float r = red[0];
    size_t rb = (size_t)bs * DD;
#pragma unroll
    for (int i = 0; i < 3; i++) {
        int d = threadIdx.x + i * 256;
        x[rb + d] = vals[i];
        float v = vals[i] * r * nw[d];
        __half hi, lo;
        split_fp16(v, hi, lo);
        xh[rb + d] = hi;
        xl[rb + d] = lo;
    }
}

// ---------------- final rmsnorm (fp16 hi/lo only) ----------------
__global__ void k_rms_b(const float* __restrict__ y, const float* __restrict__ nw,
                        __half* __restrict__ xh, __half* __restrict__ xl) {
    int bs = blockIdx.x;
    const float* yr = y + (size_t)bs * DD;
    float vals[3];
    float ss = 0.f;
#pragma unroll
    for (int i = 0; i < 3; i++) {
        int d = threadIdx.x + i * 256;
        float v = yr[d];
        vals[i] = v;
        ss += v * v;
    }
    __shared__ float red[8];
#pragma unroll
    for (int o = 16; o > 0; o >>= 1) ss += __shfl_xor_sync(~0u, ss, o);
    if ((threadIdx.x & 31) == 0) red[threadIdx.x >> 5] = ss;
    __syncthreads();
    if (threadIdx.x == 0) {
        float v = 0.f;
#pragma unroll
        for (int i = 0; i < 8; i++) v += red[i];
        red[0] = rsqrtf(v / DD + 1e-6f);
    }
    __syncthreads();
    float r = red[0];
    size_t rb = (size_t)bs * DD;
#pragma unroll
    for (int i = 0; i < 3; i++) {
        int d = threadIdx.x + i * 256;
        float v = vals[i] * r * nw[d];
        __half hi, lo;
        split_fp16(v, hi, lo);
        xh[rb + d] = hi;
        xl[rb + d] = lo;
    }
}

// ---------------- minGRU scan over precomputed (a,b) ----------------
__global__ void k_scan_red(const float2* __restrict__ ab, float2* __restrict__ carry) {
    int idx = blockIdx.x * 256 + threadIdx.x;
    int d = idx % DD;
    int bc = idx / DD;
    int b = bc % BB;
    int c = bc / BB;
    const float2* base = ab + (size_t)(b * SS + c * LL) * DD + d;
    float A = 1.f, Bv = 0.f;
#pragma unroll 4
    for (int t = 0; t < LL; t++) {
        float2 v = *base;
        base += DD;
        A *= v.x;
        Bv = fmaf(v.x, Bv, v.y);
    }
    carry[idx] = make_float2(A, Bv);
}

__global__ void k_scan_carry(const float2* __restrict__ carry, float* __restrict__ hinit) {
    int ch = blockIdx.x * 256 + threadIdx.x;
    int d = ch % DD;
    int b = ch / DD;
    float h = 0.f;
#pragma unroll
    for (int c = 0; c < CC; c++) {
        int i = (c * BB + b) * DD + d;
        hinit[i] = h;
        float2 abv = carry[i];
        h = fmaf(abv.x, h, abv.y);
    }
}

// writes hh only (single fp16 is enough for GEMM2's residual-dominated output)
__global__ void k_scan_apply(const float2* __restrict__ ab, const float* __restrict__ hinit,
                             __half* __restrict__ hh) {
    int idx = blockIdx.x * 256 + threadIdx.x;
    int d = idx % DD;
    int bc = idx / DD;
    int b = bc % BB;
    int c = bc / BB;
    size_t off = (size_t)(b * SS + c * LL) * DD + d;
    const float2* base = ab + off;
    float h = hinit[idx];
#pragma unroll 4
    for (int t = 0; t < LL; t++) {
        float2 v = *base;
        base += DD;
        h = fmaf(v.x, h, v.y);
        hh[off] = __float2half_rn(h);
        off += DD;
    }
}

// ---------------- patch bookkeeping ----------------
__global__ void k_cum(const int* __restrict__ lens, int* __restrict__ cum) {
    int b = blockIdx.x;
    if (threadIdx.x == 0) {
        int s = 0;
        for (int p = 0; p < PP; p++) {
            s += lens[b * PP + p];
            cum[b * PP + p] = s;
        }
    }
}

__global__ void k_pid(const int* __restrict__ cum, int* __restrict__ pid) {
    int i = blockIdx.x * 256 + threadIdx.x;
    if (i >= BS) return;
    int b = i / SS;
    int pos = i % SS;
    const int* c = cum + b * PP;
    int lo = 0, hi = PP;
    while (lo < hi) {
        int mid = (lo + hi) >> 1;
        if (c[mid] <= pos) lo = mid + 1;
        else hi = mid;
    }
    pid[i] = lo;
}

__global__ void k_segmax(const float* __restrict__ y, const int* __restrict__ cum,
                         float* __restrict__ patch) {
    int bp = blockIdx.x;
    int b = bp / PP, p = bp % PP;
    int start = p ? cum[b * PP + p - 1] : 0;
    int end = cum[b * PP + p];
    const float* yb = y + (size_t)b * SS * DD;
    float* orow = patch + (size_t)bp * DD;
    for (int d = threadIdx.x; d < DD; d += 256) {
        float m = -3.402823466e38f;
        for (int s = start; s < end; s++)
            m = fmaxf(m, yb[(size_t)s * DD + d]);
        orow[d] = m;
    }
}

// ---------------- launch ----------------
extern "C" void kernel_launch(void* const* d_in, const int* in_sizes, int n_in,
                              void* d_out, int out_size) {
    const int*   ids      = (const int*)d_in[0];
    const int*   lens     = (const int*)d_in[1];
    const float* tok      = (const float*)d_in[2];
    const float* hsh      = (const float*)d_in[3];
    const float* enc_nw   = (const float*)d_in[4];
    const float* enc_whg  = (const float*)d_in[5];
    const float* enc_wout = (const float*)d_in[6];
    const float* dec_nw   = (const float*)d_in[7];
    const float* dec_whg  = (const float*)d_in[8];
    const float* dec_wout = (const float*)d_in[9];
    const float* fin_nw   = (const float*)d_in[10];
    const float* oproj    = (const float*)d_in[11];
    float*       out      = (float*)d_out;

    float* base = nullptr;
    cudaGetSymbolAddress((void**)&base, g_scratch);
    float*   x     = base + OFF_X;
    float*   y     = base + OFF_Y;
    float2*  ab    = (float2*)(base + OFF_AB);
    __half*  xh    = (__half*)(base + OFF_XH);
    __half*  xl    = (__half*)(base + OFF_XL);
    __half*  hh    = (__half*)(base + OFF_HH);
    float*   patch = base + OFF_PAT;
    float2*  carry = (float2*)(base + OFF_CAR);
    float*   hinit = base + OFF_HIN;
    int*     cum   = (int*)(base + OFF_CUM);
    int*     pid   = (int*)(base + OFF_PID);
    __half*  wHGe  = (__half*)(base + OFF_WHGE);
    __half*  wOUe  = (__half*)(base + OFF_WOUE);
    __half*  wHGd  = (__half*)(base + OFF_WHGD);
    __half*  wOUd  = (__half*)(base + OFF_WOUD);
    __half*  wLG   = (__half*)(base + OFF_WLG);

    constexpr int SMEM2P = 2 * 3 * 128 * 128;  // 98304 bytes (2-pass: Ah|Al|Bw)
    constexpr int SMEM1P = 2 * 2 * 128 * 128;  // 65536 bytes (1-pass: Ah|Bw)
    cudaFuncSetAttribute((const void*)k_hgemm<1, true>,  cudaFuncAttributeMaxDynamicSharedMemorySize, SMEM2P);
    cudaFuncSetAttribute((const void*)k_hgemm<2, false>, cudaFuncAttributeMaxDynamicSharedMemorySize, SMEM1P);
    cudaFuncSetAttribute((const void*)k_hgemm<3, true>,  cudaFuncAttributeMaxDynamicSharedMemorySize, SMEM2P);

    dim3 tb(32, 32);
    k_cum<<<BB, 32>>>(lens, cum);
    k_pid<<<(BS + 255) / 256, 256>>>(cum, pid);
    k_embed_rms<<<BS, 256>>>(ids, tok, hsh, enc_nw, x, xh, xl);
    k_wprep<<<dim3(1536 / 32, GK / 32), tb>>>(enc_whg, wHGe, 1536, 1, 1536);
    k_wprep<<<dim3(768 / 32, GK / 32), tb>>>(enc_wout, wOUe, 768, 0, 768);

    // ---- encoder block ----
    k_hgemm<1, true><<<dim3(12, 128), 256, SMEM2P>>>(xh, xl, wHGe, nullptr, (float*)ab);
    k_scan_red<<<CBD / 256, 256>>>(ab, carry);
    k_scan_carry<<<(BB * DD) / 256, 256>>>(carry, hinit);
    k_scan_apply<<<CBD / 256, 256>>>(ab, hinit, hh);
    k_hgemm<2, false><<<dim3(6, 128), 256, SMEM1P>>>(hh, nullptr, wOUe, x, y);

    // remaining weight preps
    k_wprep<<<dim3(1536 / 32, GK / 32), tb>>>(dec_whg, wHGd, 1536, 1, 1536);
    k_wprep<<<dim3(768 / 32, GK / 32), tb>>>(dec_wout, wOUd, 768, 0, 768);
    k_wprep<<<dim3(NLOGPAD / 32, GK / 32), tb>>>(oproj, wLG, NBYTE, 0, NBYTE);

    // ---- patch pooling + decoder input ----
    k_segmax<<<BB * PP, 256>>>(y, cum, patch);
    k_gadd_rms<<<BS, 256>>>(y, patch, pid, dec_nw, x, xh, xl);

    // ---- decoder block ----
    k_hgemm<1, true><<<dim3(12, 128), 256, SMEM2P>>>(xh, xl, wHGd, nullptr, (float*)ab);
    k_scan_red<<<CBD / 256, 256>>>(ab, carry);
    k_scan_carry<<<(BB * DD) / 256, 256>>>(carry, hinit);
    k_scan_apply<<<CBD / 256, 256>>>(ab, hinit, hh);
    k_hgemm<2, false><<<dim3(6, 128), 256, SMEM1P>>>(hh, nullptr, wOUd, x, y);

    // ---- final norm + logits (3 N-tiles cover 260 of 384) ----
    k_rms_b<<<BS, 256>>>(y, fin_nw, xh, xl);
    k_hgemm<3, true><<<dim3(3, 128), 256, SMEM2P>>>(xh, xl, wLG, nullptr, out);
}